// round 3
// baseline (speedup 1.0000x reference)
#include <cuda_runtime.h>
#include <math.h>

#define N0   3000
#define KK1  1500
#define KK2  750
#define HID  128
#define INC  32
#define OUTC 3
#define EMAX 48000

#define CDIV(a,b) (((a)+(b)-1)/(b))

// ---------------- scratch (static device globals; no allocation allowed) ----------------
// float scratch offsets (in floats)
static const size_t O_AUG0 = 0;
static const size_t O_A1   = O_AUG0 + (size_t)N0*N0;
static const size_t O_AUG1 = O_A1   + (size_t)KK1*KK1;
static const size_t O_A2   = O_AUG1 + (size_t)KK1*KK1;
static const size_t O_XW0  = O_A2   + (size_t)KK2*KK2;
static const size_t O_H0   = O_XW0  + (size_t)N0*HID;
static const size_t O_U0   = O_H0   + (size_t)N0*HID;
static const size_t O_XW   = O_U0   + (size_t)N0*HID;
static const size_t O_V    = O_XW   + (size_t)KK1*HID;
static const size_t O_Z    = O_V    + (size_t)KK1*HID;
static const size_t O_H1   = O_Z    + (size_t)KK1*HID;
static const size_t O_H1G  = O_H1   + (size_t)KK1*HID;   // reused later as u1b
static const size_t O_U1   = O_H1G  + (size_t)KK1*HID;
static const size_t O_H2   = O_U1   + (size_t)KK1*HID;
static const size_t O_H2G  = O_H2   + (size_t)KK2*HID;
static const size_t O_XW3  = O_H2G  + (size_t)KK2*HID;
static const size_t O_DIS0 = O_XW3  + (size_t)N0*4;
static const size_t O_DIS1 = O_DIS0 + N0;
static const size_t O_DIS2 = O_DIS1 + KK1;
static const size_t O_SC   = O_DIS2 + 768;
static const size_t O_VL1  = O_SC   + N0;
static const size_t O_VL2  = O_VL1  + 1536;
static const size_t O_PN   = O_VL2  + 768;
static const size_t FTOT   = O_PN   + 32;

__device__ float g_f[FTOT];

// int scratch offsets (in ints)
static const size_t IO_CNTS = 0;        // 3000
static const size_t IO_CNTD = 3000;     // 3000
static const size_t IO_CURS = 6000;     // 3000
static const size_t IO_CURD = 9000;     // 3000
static const size_t IO_OFFS = 12000;    // 3008
static const size_t IO_OFFD = 15008;    // 3008
static const size_t IO_COLS = 18016;    // EMAX
static const size_t IO_COLD = IO_COLS + EMAX;
static const size_t IO_P1   = IO_COLD + EMAX;   // 1536
static const size_t IO_P2   = IO_P1 + 1536;     // 768
static const size_t ITOT    = IO_P2 + 768;

__device__ int g_i[ITOT];

// ---------------- kernels ----------------

__global__ void k_count(const int* ei, int E, int* cnt_s, int* cnt_d) {
    int e = blockIdx.x * blockDim.x + threadIdx.x;
    if (e < E) {
        atomicAdd(&cnt_s[ei[e]], 1);
        atomicAdd(&cnt_d[ei[E + e]], 1);
    }
}

// one-block exclusive scan of up to 3072 elements (n <= 3072)
__global__ void k_scan(const int* cnt, int n, int* off) {
    __shared__ int sh[3072];
    __shared__ int ps[1024];
    int tid = threadIdx.x;
    for (int i = tid; i < 3072; i += 1024) sh[i] = (i < n) ? cnt[i] : 0;
    __syncthreads();
    int a = sh[3*tid], b = sh[3*tid+1], c = sh[3*tid+2];
    int s = a + b + c;
    ps[tid] = s;
    __syncthreads();
    for (int d = 1; d < 1024; d <<= 1) {
        int v = 0;
        if (tid >= d) v = ps[tid - d];
        __syncthreads();
        if (tid >= d) ps[tid] += v;
        __syncthreads();
    }
    int excl = ps[tid] - s;
    if (3*tid   < n) off[3*tid]   = excl;
    if (3*tid+1 < n) off[3*tid+1] = excl + a;
    if (3*tid+2 < n) off[3*tid+2] = excl + a + b;
    if (tid == 1023) off[n] = ps[1023];
}

__global__ void k_fill(const int* ei, int E, const int* off_s, const int* off_d,
                       int* cur_s, int* cur_d, int* col_s, int* col_d) {
    int e = blockIdx.x * blockDim.x + threadIdx.x;
    if (e < E) {
        int s = ei[e], t = ei[E + e];
        int p = atomicAdd(&cur_s[s], 1); col_s[off_s[s] + p] = t;
        int q = atomicAdd(&cur_d[t], 1); col_d[off_d[t] + q] = s;
    }
}

__global__ void k_dis0(const int* cnt_d, float* dis) {
    int i = blockIdx.x * blockDim.x + threadIdx.x;
    if (i < N0) dis[i] = rsqrtf((float)cnt_d[i] + 2.0f);
}

// tiled SGEMM: C[M,N] = A[M,K] @ B[K,N] (row-major). aug=1: A,B diag->1 on load, C diag->0.
__global__ __launch_bounds__(256) void k_sgemm(const float* __restrict__ A,
                                               const float* __restrict__ B,
                                               float* __restrict__ C,
                                               int M, int N, int K, int aug) {
    __shared__ float As[16][65];
    __shared__ float Bs[16][64];
    int bm = blockIdx.y * 64, bn = blockIdx.x * 64;
    int tid = threadIdx.x;
    int tx = tid & 15, ty = tid >> 4;
    float acc[4][4] = {};
    for (int k0 = 0; k0 < K; k0 += 16) {
        #pragma unroll
        for (int l = tid; l < 64*16; l += 256) {
            int m = l >> 4, kk = l & 15;
            int gm = bm + m, gk = k0 + kk;
            float v = 0.0f;
            if (gm < M && gk < K) v = A[(size_t)gm * K + gk];
            if (aug && gm == gk && gm < M && gk < K) v = 1.0f;
            As[kk][m] = v;
        }
        #pragma unroll
        for (int l = tid; l < 16*64; l += 256) {
            int kk = l >> 6, nn = l & 63;
            int gk = k0 + kk, gn = bn + nn;
            float v = 0.0f;
            if (gk < K && gn < N) v = B[(size_t)gk * N + gn];
            if (aug && gk == gn && gk < K && gn < N) v = 1.0f;
            Bs[kk][nn] = v;
        }
        __syncthreads();
        #pragma unroll
        for (int kk = 0; kk < 16; kk++) {
            float a0 = As[kk][ty*4+0], a1 = As[kk][ty*4+1];
            float a2 = As[kk][ty*4+2], a3 = As[kk][ty*4+3];
            float b0 = Bs[kk][tx*4+0], b1 = Bs[kk][tx*4+1];
            float b2 = Bs[kk][tx*4+2], b3 = Bs[kk][tx*4+3];
            acc[0][0] += a0*b0; acc[0][1] += a0*b1; acc[0][2] += a0*b2; acc[0][3] += a0*b3;
            acc[1][0] += a1*b0; acc[1][1] += a1*b1; acc[1][2] += a1*b2; acc[1][3] += a1*b3;
            acc[2][0] += a2*b0; acc[2][1] += a2*b1; acc[2][2] += a2*b2; acc[2][3] += a2*b3;
            acc[3][0] += a3*b0; acc[3][1] += a3*b1; acc[3][2] += a3*b2; acc[3][3] += a3*b3;
        }
        __syncthreads();
    }
    #pragma unroll
    for (int r = 0; r < 4; r++) {
        #pragma unroll
        for (int c = 0; c < 4; c++) {
            int gm = bm + ty*4 + r, gn = bn + tx*4 + c;
            if (gm < M && gn < N) {
                float v = acc[r][c];
                if (aug && gm == gn) v = 0.0f;
                C[(size_t)gm * N + gn] = v;
            }
        }
    }
}

// sparse GCN aggregate for A0 (HID cols): out = tanh(dis_i*(sum dis_s XW_s + 2 dis_i XW_i) + b)
__global__ void k_gcn0(const float* __restrict__ XW, const float* __restrict__ b,
                       const float* __restrict__ dis, const int* __restrict__ off,
                       const int* __restrict__ col, float* __restrict__ out) {
    __shared__ int   snb[128];
    __shared__ float sds[128];
    int i = blockIdx.x, c = threadIdx.x;
    float di = dis[i];
    float acc = 2.0f * di * XW[(size_t)i*HID + c];
    int s0 = off[i], s1 = off[i+1];
    for (int base = s0; base < s1; base += 128) {
        int e = base + c;
        if (e < s1) { int s = col[e]; snb[c] = s; sds[c] = dis[s]; }
        __syncthreads();
        int lim = min(128, s1 - base);
        for (int t = 0; t < lim; t++)
            acc += sds[t] * XW[(size_t)snb[t]*HID + c];
        __syncthreads();
    }
    out[(size_t)i*HID + c] = tanhf(di * acc + b[c]);
}

__global__ void k_pnorm(const float* p, float* out) {
    __shared__ float sh[128];
    int c = threadIdx.x;
    sh[c] = p[c] * p[c];
    __syncthreads();
    for (int st = 64; st > 0; st >>= 1) { if (c < st) sh[c] += sh[c+st]; __syncthreads(); }
    if (c == 0) out[0] = rsqrtf(sh[0]);
}

__global__ void k_score(const float* __restrict__ h, const float* __restrict__ p,
                        const float* __restrict__ invn, float* __restrict__ s) {
    __shared__ float sh[128];
    int i = blockIdx.x, c = threadIdx.x;
    sh[c] = h[(size_t)i*HID + c] * p[c];
    __syncthreads();
    for (int st = 64; st > 0; st >>= 1) { if (c < st) sh[c] += sh[c+st]; __syncthreads(); }
    if (c == 0) s[i] = tanhf(sh[0] * invn[0]);
}

// exact top-K selection via rank counting (set semantics; order-invariant downstream)
__global__ void k_topk(const float* __restrict__ s, int n, int K,
                       int* __restrict__ perm, float* __restrict__ vals) {
    __shared__ float sh[256];
    int i = blockIdx.x * blockDim.x + threadIdx.x;
    float si = (i < n) ? s[i] : -1e30f;
    int rank = 0;
    for (int j0 = 0; j0 < n; j0 += 256) {
        int j = j0 + threadIdx.x;
        sh[threadIdx.x] = (j < n) ? s[j] : -1e30f;
        __syncthreads();
        int lim = min(256, n - j0);
        for (int t = 0; t < lim; t++) {
            float sj = sh[t];
            int jj = j0 + t;
            rank += (sj > si) || (sj == si && jj < i);
        }
        __syncthreads();
    }
    if (i < n && rank < K) { perm[rank] = i; vals[rank] = si; }
}

// sparse-sparse A@A via 2-path enumeration through middle node k (off-diag B entries)
__global__ void k_aug_pairs(const int* __restrict__ off_s, const int* __restrict__ col_s,
                            const int* __restrict__ off_d, const int* __restrict__ col_d,
                            float* __restrict__ Aug) {
    int k = blockIdx.x;
    int os = off_s[k], ns = off_s[k+1] - os;
    int od = off_d[k], nd = off_d[k+1] - od;
    int tot = ns * nd;
    for (int t = threadIdx.x; t < tot; t += 128) {
        int i = col_s[os + t / nd];   // edge k->i
        int j = col_d[od + t % nd];   // edge j->k
        if (i != k && j != k) atomicAdd(&Aug[(size_t)i*N0 + j], 1.0f);
    }
}

__global__ void k_aug_edges(const int* ei, int E, float* Aug) {
    int e = blockIdx.x * blockDim.x + threadIdx.x;
    if (e < E) {
        int s = ei[e], t = ei[E + e];
        if (s != t) atomicAdd(&Aug[(size_t)t*N0 + s], 2.0f);
    }
}

__global__ void k_zero_diag(float* Aug, int n) {
    int i = blockIdx.x * blockDim.x + threadIdx.x;
    if (i < n) Aug[(size_t)i*n + i] = 0.0f;
}

__global__ void k_gather_A(const float* __restrict__ Aug, int n,
                           const int* __restrict__ perm, float* __restrict__ Asub, int k) {
    int idx = blockIdx.x * blockDim.x + threadIdx.x;
    if (idx < k*k) {
        int a = idx / k, b = idx % k;
        Asub[idx] = Aug[(size_t)perm[a]*n + perm[b]];
    }
}

__global__ void k_gather_gate(const float* __restrict__ h, const int* __restrict__ perm,
                              const float* __restrict__ vals, float* __restrict__ out, int k) {
    int idx = blockIdx.x * blockDim.x + threadIdx.x;
    if (idx < k*HID) {
        int r = idx >> 7, c = idx & 127;
        out[idx] = h[(size_t)perm[r]*HID + c] * vals[r];
    }
}

__global__ void k_rowsum_dis(const float* __restrict__ A, int n, float* __restrict__ dis) {
    __shared__ float sh[256];
    int i = blockIdx.x;
    float s = 0.0f;
    for (int j = threadIdx.x; j < n; j += 256) s += A[(size_t)i*n + j];
    sh[threadIdx.x] = s;
    __syncthreads();
    for (int st = 128; st > 0; st >>= 1) { if (threadIdx.x < st) sh[threadIdx.x] += sh[threadIdx.x+st]; __syncthreads(); }
    if (threadIdx.x == 0) dis[i] = rsqrtf(sh[0] + 2.0f);
}

__global__ void k_scale_v(const float* __restrict__ XW, const float* __restrict__ dis,
                          float* __restrict__ v, int n) {
    int idx = blockIdx.x * blockDim.x + threadIdx.x;
    if (idx < n*HID) v[idx] = dis[idx >> 7] * XW[idx];
}

__global__ void k_gcn_epi(const float* __restrict__ Z, const float* __restrict__ XW,
                          const float* __restrict__ b, const float* __restrict__ dis,
                          float* __restrict__ out, int n) {
    int idx = blockIdx.x * blockDim.x + threadIdx.x;
    if (idx < n*HID) {
        int i = idx >> 7, c = idx & 127;
        float di = dis[i];
        out[idx] = tanhf(di * Z[idx] + 2.0f * di * di * XW[idx] + b[c]);
    }
}

__global__ void k_copy(const float* src, float* dst, int n) {
    int idx = blockIdx.x * blockDim.x + threadIdx.x;
    if (idx < n) dst[idx] = src[idx];
}

__global__ void k_scatter_add(float* __restrict__ u, const float* __restrict__ h,
                              const int* __restrict__ perm, int k) {
    int idx = blockIdx.x * blockDim.x + threadIdx.x;
    if (idx < k*HID) {
        int r = idx >> 7, c = idx & 127;
        u[(size_t)perm[r]*HID + c] += h[idx];
    }
}

// final sparse GCN (OUTC=3), no activation, add noise 0.1*z, write to d_out
__global__ void k_gcn_final(const float* __restrict__ XW3, const float* __restrict__ b,
                            const float* __restrict__ dis, const int* __restrict__ off,
                            const int* __restrict__ col, const float* __restrict__ z,
                            float* __restrict__ out) {
    int i = blockIdx.x * blockDim.x + threadIdx.x;
    if (i >= N0) return;
    float di = dis[i];
    float a0 = 2.0f * di * XW3[i*3+0];
    float a1 = 2.0f * di * XW3[i*3+1];
    float a2 = 2.0f * di * XW3[i*3+2];
    int s0 = off[i], s1 = off[i+1];
    for (int e = s0; e < s1; e++) {
        int s = col[e];
        float ds = dis[s];
        a0 += ds * XW3[s*3+0];
        a1 += ds * XW3[s*3+1];
        a2 += ds * XW3[s*3+2];
    }
    out[i*3+0] = di*a0 + b[0] + 0.1f*z[i*3+0];
    out[i*3+1] = di*a1 + b[1] + 0.1f*z[i*3+1];
    out[i*3+2] = di*a2 + b[2] + 0.1f*z[i*3+2];
}

// ---------------- launch ----------------
extern "C" void kernel_launch(void* const* d_in, const int* in_sizes, int n_in,
                              void* d_out, int out_size) {
    const float* x   = (const float*)d_in[0];
    const float* z   = (const float*)d_in[1];
    const float* W0  = (const float*)d_in[2];
    const float* b0  = (const float*)d_in[3];
    const float* W1  = (const float*)d_in[4];
    const float* b1  = (const float*)d_in[5];
    const float* W2  = (const float*)d_in[6];
    const float* b2  = (const float*)d_in[7];
    const float* p1  = (const float*)d_in[8];
    const float* p2  = (const float*)d_in[9];
    const float* Wu0 = (const float*)d_in[10];
    const float* bu0 = (const float*)d_in[11];
    const float* Wu1 = (const float*)d_in[12];
    const float* bu1 = (const float*)d_in[13];
    const int*   ei  = (const int*)d_in[14];
    int E = in_sizes[14] / 2;
    if (E > EMAX) E = EMAX;

    float* F; cudaGetSymbolAddress((void**)&F, g_f);
    int*   I; cudaGetSymbolAddress((void**)&I, g_i);
    float* out = (float*)d_out;

    float *Aug0 = F+O_AUG0, *A1 = F+O_A1, *Aug1 = F+O_AUG1, *A2 = F+O_A2;
    float *XW0 = F+O_XW0, *h0 = F+O_H0, *u0 = F+O_U0;
    float *XW = F+O_XW, *V = F+O_V, *Zb = F+O_Z;
    float *h1 = F+O_H1, *h1g = F+O_H1G, *u1 = F+O_U1;
    float *h2 = F+O_H2, *h2g = F+O_H2G, *XW3 = F+O_XW3;
    float *dis0 = F+O_DIS0, *dis1 = F+O_DIS1, *dis2 = F+O_DIS2;
    float *score = F+O_SC, *vals1 = F+O_VL1, *vals2 = F+O_VL2, *pn = F+O_PN;
    int *perm1 = I+IO_P1, *perm2 = I+IO_P2;
    float* u1b = h1g; // reuse after gated input consumed

    // zero scratch that accumulates
    cudaMemsetAsync(Aug0, 0, (size_t)N0*N0*sizeof(float));
    cudaMemsetAsync(I, 0, 12000*sizeof(int));            // cnt_s, cnt_d, cur_s, cur_d
    cudaMemsetAsync(d_out, 0, (size_t)out_size*sizeof(float));

    // CSR build
    k_count<<<CDIV(E,256),256>>>(ei, E, I+IO_CNTS, I+IO_CNTD);
    k_scan<<<1,1024>>>(I+IO_CNTS, N0, I+IO_OFFS);
    k_scan<<<1,1024>>>(I+IO_CNTD, N0, I+IO_OFFD);
    k_fill<<<CDIV(E,256),256>>>(ei, E, I+IO_OFFS, I+IO_OFFD, I+IO_CURS, I+IO_CURD, I+IO_COLS, I+IO_COLD);
    k_dis0<<<CDIV(N0,256),256>>>(I+IO_CNTD, dis0);

    // down0: h0 = tanh(gcn(A0, x))
    k_sgemm<<<dim3(CDIV(HID,64), CDIV(N0,64)),256>>>(x, W0, XW0, N0, HID, INC, 0);
    k_gcn0<<<N0,128>>>(XW0, b0, dis0, I+IO_OFFD, I+IO_COLD, h0);

    // pool1 scores + selection
    k_pnorm<<<1,128>>>(p1, pn);
    k_score<<<N0,128>>>(h0, p1, pn, score);
    k_topk<<<CDIV(N0,256),256>>>(score, N0, KK1, perm1, vals1);

    // augment(A0) sparse-sparse into dense Aug0
    k_aug_pairs<<<N0,128>>>(I+IO_OFFS, I+IO_COLS, I+IO_OFFD, I+IO_COLD, Aug0);
    k_aug_edges<<<CDIV(E,256),256>>>(ei, E, Aug0);
    k_zero_diag<<<CDIV(N0,256),256>>>(Aug0, N0);

    // A1, gated h1 input
    k_gather_A<<<CDIV(KK1*KK1,256),256>>>(Aug0, N0, perm1, A1, KK1);
    k_gather_gate<<<CDIV(KK1*HID,256),256>>>(h0, perm1, vals1, h1g, KK1);

    // down1: h1 = tanh(gcn(A1, h1g))
    k_rowsum_dis<<<KK1,256>>>(A1, KK1, dis1);
    k_sgemm<<<dim3(CDIV(HID,64), CDIV(KK1,64)),256>>>(h1g, W1, XW, KK1, HID, HID, 0);
    k_scale_v<<<CDIV(KK1*HID,256),256>>>(XW, dis1, V, KK1);
    k_sgemm<<<dim3(CDIV(HID,64), CDIV(KK1,64)),256>>>(A1, V, Zb, KK1, HID, KK1, 0);
    k_gcn_epi<<<CDIV(KK1*HID,256),256>>>(Zb, XW, b1, dis1, h1, KK1);

    // pool2
    k_pnorm<<<1,128>>>(p2, pn);
    k_score<<<KK1,128>>>(h1, p2, pn, score);
    k_topk<<<CDIV(KK1,256),256>>>(score, KK1, KK2, perm2, vals2);

    // augment(A1) dense (B1@B1 with diag substitution, diag-zeroed output)
    k_sgemm<<<dim3(CDIV(KK1,64), CDIV(KK1,64)),256>>>(A1, A1, Aug1, KK1, KK1, KK1, 1);

    k_gather_A<<<CDIV(KK2*KK2,256),256>>>(Aug1, KK1, perm2, A2, KK2);
    k_gather_gate<<<CDIV(KK2*HID,256),256>>>(h1, perm2, vals2, h2g, KK2);

    // down2: h2 = tanh(gcn(A2, h2g))
    k_rowsum_dis<<<KK2,256>>>(A2, KK2, dis2);
    k_sgemm<<<dim3(CDIV(HID,64), CDIV(KK2,64)),256>>>(h2g, W2, XW, KK2, HID, HID, 0);
    k_scale_v<<<CDIV(KK2*HID,256),256>>>(XW, dis2, V, KK2);
    k_sgemm<<<dim3(CDIV(HID,64), CDIV(KK2,64)),256>>>(A2, V, Zb, KK2, HID, KK2, 0);
    k_gcn_epi<<<CDIV(KK2*HID,256),256>>>(Zb, XW, b2, dis2, h2, KK2);

    // up0: u1 = h1 + scatter(h2 @ perm2); u1b = tanh(gcn(A1, u1))
    k_copy<<<CDIV(KK1*HID,256),256>>>(h1, u1, KK1*HID);
    k_scatter_add<<<CDIV(KK2*HID,256),256>>>(u1, h2, perm2, KK2);
    k_sgemm<<<dim3(CDIV(HID,64), CDIV(KK1,64)),256>>>(u1, Wu0, XW, KK1, HID, HID, 0);
    k_scale_v<<<CDIV(KK1*HID,256),256>>>(XW, dis1, V, KK1);
    k_sgemm<<<dim3(CDIV(HID,64), CDIV(KK1,64)),256>>>(A1, V, Zb, KK1, HID, KK1, 0);
    k_gcn_epi<<<CDIV(KK1*HID,256),256>>>(Zb, XW, bu0, dis1, u1b, KK1);

    // up1: u0 = h0 + scatter(u1b @ perm1); drift = gcn(A0, u0) (no act) + 0.1*z
    k_copy<<<CDIV(N0*HID,256),256>>>(h0, u0, N0*HID);
    k_scatter_add<<<CDIV(KK1*HID,256),256>>>(u0, u1b, perm1, KK1);
    k_sgemm<<<dim3(1, CDIV(N0,64)),256>>>(u0, Wu1, XW3, N0, OUTC, HID, 0);
    k_gcn_final<<<CDIV(N0,128),128>>>(XW3, bu1, dis0, I+IO_OFFD, I+IO_COLD, z, out);
}

// round 4
// speedup vs baseline: 1.1995x; 1.1995x over previous
#include <cuda_runtime.h>
#include <math.h>

#define N0   3000
#define KK1  1500
#define KK2  750
#define HID  128
#define INC  32
#define OUTC 3
#define EMAX 48000
#define BCLD 768   // padded ld for Bc

#define CDIV(a,b) (((a)+(b)-1)/(b))

// ---------------- scratch ----------------
static const size_t O_A1   = 0;
static const size_t O_BR   = O_A1  + (size_t)KK1*KK1;          // 750x1500
static const size_t O_BC   = O_BR  + (size_t)KK2*KK1;          // 1500x768
static const size_t O_A2   = O_BC  + (size_t)KK1*BCLD;         // 750x750
static const size_t O_XW0  = O_A2  + (size_t)KK2*KK2;
static const size_t O_H0   = O_XW0 + (size_t)N0*HID;
static const size_t O_U0   = O_H0  + (size_t)N0*HID;
static const size_t O_XW   = O_U0  + (size_t)N0*HID;
static const size_t O_H1   = O_XW  + (size_t)KK1*HID;
static const size_t O_H1G  = O_H1  + (size_t)KK1*HID;   // reused as u1b
static const size_t O_U1   = O_H1G + (size_t)KK1*HID;
static const size_t O_H2   = O_U1  + (size_t)KK1*HID;
static const size_t O_H2G  = O_H2  + (size_t)KK2*HID;
static const size_t O_XW3  = O_H2G + (size_t)KK2*HID;
static const size_t O_DIS0 = O_XW3 + (size_t)N0*4;
static const size_t O_DIS1 = O_DIS0 + N0;
static const size_t O_DIS2 = O_DIS1 + KK1;
static const size_t O_SC   = O_DIS2 + 768;
static const size_t O_VL1  = O_SC   + N0;
static const size_t O_VL2  = O_VL1  + 1536;
static const size_t O_PN   = O_VL2  + 768;
static const size_t FTOT   = O_PN   + 32;

__device__ float g_f[FTOT];

static const size_t IO_CNTS = 0;        // 3000
static const size_t IO_CNTD = 3000;
static const size_t IO_CURS = 6000;
static const size_t IO_CURD = 9000;
static const size_t IO_OFFS = 12000;    // 3008
static const size_t IO_OFFD = 15008;
static const size_t IO_COLS = 18016;    // EMAX
static const size_t IO_COLD = IO_COLS + EMAX;
static const size_t IO_P1   = IO_COLD + EMAX;   // 1536
static const size_t IO_P2   = IO_P1 + 1536;     // 768
static const size_t IO_INV1 = IO_P2 + 768;      // 3072
static const size_t ITOT    = IO_INV1 + 3072;

__device__ int g_i[ITOT];

// ---------------- CSR build ----------------
__global__ void k_count(const int* ei, int E, int* cnt_s, int* cnt_d) {
    int e = blockIdx.x * blockDim.x + threadIdx.x;
    if (e < E) {
        atomicAdd(&cnt_s[ei[e]], 1);
        atomicAdd(&cnt_d[ei[E + e]], 1);
    }
}

__global__ void k_scan(const int* cnt, int n, int* off) {
    __shared__ int sh[3072];
    __shared__ int ps[1024];
    int tid = threadIdx.x;
    for (int i = tid; i < 3072; i += 1024) sh[i] = (i < n) ? cnt[i] : 0;
    __syncthreads();
    int a = sh[3*tid], b = sh[3*tid+1], c = sh[3*tid+2];
    int s = a + b + c;
    ps[tid] = s;
    __syncthreads();
    for (int d = 1; d < 1024; d <<= 1) {
        int v = 0;
        if (tid >= d) v = ps[tid - d];
        __syncthreads();
        if (tid >= d) ps[tid] += v;
        __syncthreads();
    }
    int excl = ps[tid] - s;
    if (3*tid   < n) off[3*tid]   = excl;
    if (3*tid+1 < n) off[3*tid+1] = excl + a;
    if (3*tid+2 < n) off[3*tid+2] = excl + a + b;
    if (tid == 1023) off[n] = ps[1023];
}

__global__ void k_fill(const int* ei, int E, const int* off_s, const int* off_d,
                       int* cur_s, int* cur_d, int* col_s, int* col_d) {
    int e = blockIdx.x * blockDim.x + threadIdx.x;
    if (e < E) {
        int s = ei[e], t = ei[E + e];
        int p = atomicAdd(&cur_s[s], 1); col_s[off_s[s] + p] = t;
        int q = atomicAdd(&cur_d[t], 1); col_d[off_d[t] + q] = s;
    }
}

__global__ void k_dis0(const int* cnt_d, float* dis) {
    int i = blockIdx.x * blockDim.x + threadIdx.x;
    if (i < N0) dis[i] = rsqrtf((float)cnt_d[i] + 2.0f);
}

// ---------------- unified SGEMM 64x64, BK=32, 4x4/thread ----------------
// C[M,N](ld=N) = A[M,lda] @ B[K,ldb] ; optional B-row scale bscale[k];
// optional fused GCN epilogue: C = tanh(dis[m]*acc + 2*dis[m]^2*XW[m*N+n] + bias[n])
__global__ __launch_bounds__(256) void k_gemm64(
    const float* __restrict__ A, int lda,
    const float* __restrict__ B, int ldb,
    float* __restrict__ C,
    int M, int N, int K,
    const float* __restrict__ bscale,
    const float* __restrict__ dis,
    const float* __restrict__ XW,
    const float* __restrict__ bias)
{
    __shared__ float As[32][68];
    __shared__ float Bs[32][64];
    int bm = blockIdx.y * 64, bn = blockIdx.x * 64;
    int tid = threadIdx.x, tx = tid & 15, ty = tid >> 4;
    float acc[4][4] = {};
    for (int k0 = 0; k0 < K; k0 += 32) {
        #pragma unroll
        for (int l = 0; l < 8; l++) {
            int idx = tid + l * 256;
            int m = idx >> 5, kk = idx & 31;
            int gm = bm + m, gk = k0 + kk;
            As[kk][m] = (gm < M && gk < K) ? A[(size_t)gm * lda + gk] : 0.0f;
        }
        #pragma unroll
        for (int l = 0; l < 8; l++) {
            int idx = tid + l * 256;
            int kk = idx >> 6, nn = idx & 63;
            int gk = k0 + kk, gn = bn + nn;
            float v = 0.0f;
            if (gk < K && gn < N) {
                v = B[(size_t)gk * ldb + gn];
                if (bscale) v *= bscale[gk];
            }
            Bs[kk][nn] = v;
        }
        __syncthreads();
        #pragma unroll
        for (int kk = 0; kk < 32; kk++) {
            float a0 = As[kk][ty*4+0], a1 = As[kk][ty*4+1];
            float a2 = As[kk][ty*4+2], a3 = As[kk][ty*4+3];
            float b0 = Bs[kk][tx*4+0], b1 = Bs[kk][tx*4+1];
            float b2 = Bs[kk][tx*4+2], b3 = Bs[kk][tx*4+3];
            acc[0][0] += a0*b0; acc[0][1] += a0*b1; acc[0][2] += a0*b2; acc[0][3] += a0*b3;
            acc[1][0] += a1*b0; acc[1][1] += a1*b1; acc[1][2] += a1*b2; acc[1][3] += a1*b3;
            acc[2][0] += a2*b0; acc[2][1] += a2*b1; acc[2][2] += a2*b2; acc[2][3] += a2*b3;
            acc[3][0] += a3*b0; acc[3][1] += a3*b1; acc[3][2] += a3*b2; acc[3][3] += a3*b3;
        }
        __syncthreads();
    }
    #pragma unroll
    for (int r = 0; r < 4; r++) {
        int gm = bm + ty*4 + r;
        if (gm >= M) continue;
        float d = 0.0f;
        if (dis) d = dis[gm];
        #pragma unroll
        for (int c = 0; c < 4; c++) {
            int gn = bn + tx*4 + c;
            if (gn < N) {
                float v = acc[r][c];
                if (dis) v = tanhf(d * v + 2.0f * d * d * XW[(size_t)gm * N + gn] + bias[gn]);
                C[(size_t)gm * N + gn] = v;
            }
        }
    }
}

// ---------------- sparse GCN on A0 ----------------
__global__ void k_gcn0(const float* __restrict__ XW, const float* __restrict__ b,
                       const float* __restrict__ dis, const int* __restrict__ off,
                       const int* __restrict__ col, float* __restrict__ out) {
    __shared__ int   snb[128];
    __shared__ float sds[128];
    int i = blockIdx.x, c = threadIdx.x;
    float di = dis[i];
    float acc = 2.0f * di * XW[(size_t)i*HID + c];
    int s0 = off[i], s1 = off[i+1];
    for (int base = s0; base < s1; base += 128) {
        int e = base + c;
        if (e < s1) { int s = col[e]; snb[c] = s; sds[c] = dis[s]; }
        __syncthreads();
        int lim = min(128, s1 - base);
        for (int t = 0; t < lim; t++)
            acc += sds[t] * XW[(size_t)snb[t]*HID + c];
        __syncthreads();
    }
    out[(size_t)i*HID + c] = tanhf(di * acc + b[c]);
}

// ---------------- pooling ----------------
__global__ void k_pnorm(const float* p, float* out) {
    __shared__ float sh[128];
    int c = threadIdx.x;
    sh[c] = p[c] * p[c];
    __syncthreads();
    for (int st = 64; st > 0; st >>= 1) { if (c < st) sh[c] += sh[c+st]; __syncthreads(); }
    if (c == 0) out[0] = rsqrtf(sh[0]);
}

__global__ void k_score(const float* __restrict__ h, const float* __restrict__ p,
                        const float* __restrict__ invn, float* __restrict__ s) {
    __shared__ float sh[128];
    int i = blockIdx.x, c = threadIdx.x;
    sh[c] = h[(size_t)i*HID + c] * p[c];
    __syncthreads();
    for (int st = 64; st > 0; st >>= 1) { if (c < st) sh[c] += sh[c+st]; __syncthreads(); }
    if (c == 0) s[i] = tanhf(sh[0] * invn[0]);
}

__global__ void k_topk(const float* __restrict__ s, int n, int K,
                       int* __restrict__ perm, float* __restrict__ vals) {
    __shared__ float sh[256];
    int i = blockIdx.x * blockDim.x + threadIdx.x;
    float si = (i < n) ? s[i] : -1e30f;
    int rank = 0;
    for (int j0 = 0; j0 < n; j0 += 256) {
        int j = j0 + threadIdx.x;
        sh[threadIdx.x] = (j < n) ? s[j] : -1e30f;
        __syncthreads();
        int lim = min(256, n - j0);
        for (int t = 0; t < lim; t++) {
            float sj = sh[t];
            int jj = j0 + t;
            rank += (sj > si) || (sj == si && jj < i);
        }
        __syncthreads();
    }
    if (i < n && rank < K) { perm[rank] = i; vals[rank] = si; }
}

__global__ void k_inv_init(int* inv, int n) {
    int i = blockIdx.x * blockDim.x + threadIdx.x;
    if (i < n) inv[i] = -1;
}
__global__ void k_inv_set(const int* perm, int* inv, int k) {
    int i = blockIdx.x * blockDim.x + threadIdx.x;
    if (i < k) inv[perm[i]] = i;
}

// ---------------- sparse augment(A0) directly into A1 (perm1 submatrix) ----------------
__global__ void k_aug_pairs_direct(const int* __restrict__ off_s, const int* __restrict__ col_s,
                                   const int* __restrict__ off_d, const int* __restrict__ col_d,
                                   const int* __restrict__ inv, float* __restrict__ A1) {
    int k = blockIdx.x;
    int os = off_s[k], ns = off_s[k+1] - os;
    int od = off_d[k], nd = off_d[k+1] - od;
    int tot = ns * nd;
    for (int t = threadIdx.x; t < tot; t += 128) {
        int i = col_s[os + t / nd];   // edge k->i   (A[i,k])
        int j = col_d[od + t % nd];   // edge j->k   (A[k,j])
        if (i != k && j != k && i != j) {
            int r = inv[i], c = inv[j];
            if (r >= 0 && c >= 0) atomicAdd(&A1[(size_t)r*KK1 + c], 1.0f);
        }
    }
}

__global__ void k_aug_edges_direct(const int* ei, int E, const int* __restrict__ inv,
                                   float* __restrict__ A1) {
    int e = blockIdx.x * blockDim.x + threadIdx.x;
    if (e < E) {
        int s = ei[e], t = ei[E + e];
        if (s != t) {
            int r = inv[t], c = inv[s];
            if (r >= 0 && c >= 0) atomicAdd(&A1[(size_t)r*KK1 + c], 2.0f);
        }
    }
}

// ---------------- gathers for A2 = B1[perm2,:] @ B1[:,perm2] ----------------
__global__ void k_gather_rows(const float* __restrict__ A1, const int* __restrict__ perm,
                              float* __restrict__ Br) {
    int idx = blockIdx.x * blockDim.x + threadIdx.x;   // KK2*KK1
    if (idx < KK2*KK1) {
        int a = idx / KK1, k = idx % KK1;
        int pa = perm[a];
        Br[idx] = A1[(size_t)pa*KK1 + k] + (k == pa ? 1.0f : 0.0f);
    }
}
__global__ void k_gather_cols(const float* __restrict__ A1, const int* __restrict__ perm,
                              float* __restrict__ Bc) {
    int idx = blockIdx.x * blockDim.x + threadIdx.x;   // KK1*BCLD
    if (idx < KK1*BCLD) {
        int k = idx / BCLD, b = idx % BCLD;
        float v = 0.0f;
        if (b < KK2) {
            int pb = perm[b];
            v = A1[(size_t)k*KK1 + pb] + (k == pb ? 1.0f : 0.0f);
        }
        Bc[idx] = v;
    }
}
__global__ void k_zero_diag(float* A, int n) {
    int i = blockIdx.x * blockDim.x + threadIdx.x;
    if (i < n) A[(size_t)i*n + i] = 0.0f;
}

__global__ void k_gather_gate(const float* __restrict__ h, const int* __restrict__ perm,
                              const float* __restrict__ vals, float* __restrict__ out, int k) {
    int idx = blockIdx.x * blockDim.x + threadIdx.x;
    if (idx < k*HID) {
        int r = idx >> 7, c = idx & 127;
        out[idx] = h[(size_t)perm[r]*HID + c] * vals[r];
    }
}

__global__ void k_rowsum_dis(const float* __restrict__ A, int n, float* __restrict__ dis) {
    __shared__ float sh[256];
    int i = blockIdx.x;
    float s = 0.0f;
    for (int j = threadIdx.x; j < n; j += 256) s += A[(size_t)i*n + j];
    sh[threadIdx.x] = s;
    __syncthreads();
    for (int st = 128; st > 0; st >>= 1) { if (threadIdx.x < st) sh[threadIdx.x] += sh[threadIdx.x+st]; __syncthreads(); }
    if (threadIdx.x == 0) dis[i] = rsqrtf(sh[0] + 2.0f);
}

__global__ void k_copy(const float* src, float* dst, int n) {
    int idx = blockIdx.x * blockDim.x + threadIdx.x;
    if (idx < n) dst[idx] = src[idx];
}

__global__ void k_scatter_add(float* __restrict__ u, const float* __restrict__ h,
                              const int* __restrict__ perm, int k) {
    int idx = blockIdx.x * blockDim.x + threadIdx.x;
    if (idx < k*HID) {
        int r = idx >> 7, c = idx & 127;
        u[(size_t)perm[r]*HID + c] += h[idx];
    }
}

__global__ void k_gcn_final(const float* __restrict__ XW3, const float* __restrict__ b,
                            const float* __restrict__ dis, const int* __restrict__ off,
                            const int* __restrict__ col, const float* __restrict__ z,
                            float* __restrict__ out) {
    int i = blockIdx.x * blockDim.x + threadIdx.x;
    if (i >= N0) return;
    float di = dis[i];
    float a0 = 2.0f * di * XW3[i*3+0];
    float a1 = 2.0f * di * XW3[i*3+1];
    float a2 = 2.0f * di * XW3[i*3+2];
    int s0 = off[i], s1 = off[i+1];
    for (int e = s0; e < s1; e++) {
        int s = col[e];
        float ds = dis[s];
        a0 += ds * XW3[s*3+0];
        a1 += ds * XW3[s*3+1];
        a2 += ds * XW3[s*3+2];
    }
    out[i*3+0] = di*a0 + b[0] + 0.1f*z[i*3+0];
    out[i*3+1] = di*a1 + b[1] + 0.1f*z[i*3+1];
    out[i*3+2] = di*a2 + b[2] + 0.1f*z[i*3+2];
}

// ---------------- launch ----------------
extern "C" void kernel_launch(void* const* d_in, const int* in_sizes, int n_in,
                              void* d_out, int out_size) {
    const float* x   = (const float*)d_in[0];
    const float* z   = (const float*)d_in[1];
    const float* W0  = (const float*)d_in[2];
    const float* b0  = (const float*)d_in[3];
    const float* W1  = (const float*)d_in[4];
    const float* b1  = (const float*)d_in[5];
    const float* W2  = (const float*)d_in[6];
    const float* b2  = (const float*)d_in[7];
    const float* p1  = (const float*)d_in[8];
    const float* p2  = (const float*)d_in[9];
    const float* Wu0 = (const float*)d_in[10];
    const float* bu0 = (const float*)d_in[11];
    const float* Wu1 = (const float*)d_in[12];
    const float* bu1 = (const float*)d_in[13];
    const int*   ei  = (const int*)d_in[14];
    int E = in_sizes[14] / 2;
    if (E > EMAX) E = EMAX;

    float* F; cudaGetSymbolAddress((void**)&F, g_f);
    int*   I; cudaGetSymbolAddress((void**)&I, g_i);
    float* out = (float*)d_out;

    float *A1 = F+O_A1, *Br = F+O_BR, *Bc = F+O_BC, *A2 = F+O_A2;
    float *XW0 = F+O_XW0, *h0 = F+O_H0, *u0 = F+O_U0, *XW = F+O_XW;
    float *h1 = F+O_H1, *h1g = F+O_H1G, *u1 = F+O_U1;
    float *h2 = F+O_H2, *h2g = F+O_H2G, *XW3 = F+O_XW3;
    float *dis0 = F+O_DIS0, *dis1 = F+O_DIS1, *dis2 = F+O_DIS2;
    float *score = F+O_SC, *vals1 = F+O_VL1, *vals2 = F+O_VL2, *pn = F+O_PN;
    int *perm1 = I+IO_P1, *perm2 = I+IO_P2, *inv1 = I+IO_INV1;
    float* u1b = h1g;

    cudaMemsetAsync(A1, 0, (size_t)KK1*KK1*sizeof(float));
    cudaMemsetAsync(I, 0, 12000*sizeof(int));
    cudaMemsetAsync(d_out, 0, (size_t)out_size*sizeof(float));

    // CSR
    k_count<<<CDIV(E,256),256>>>(ei, E, I+IO_CNTS, I+IO_CNTD);
    k_scan<<<1,1024>>>(I+IO_CNTS, N0, I+IO_OFFS);
    k_scan<<<1,1024>>>(I+IO_CNTD, N0, I+IO_OFFD);
    k_fill<<<CDIV(E,256),256>>>(ei, E, I+IO_OFFS, I+IO_OFFD, I+IO_CURS, I+IO_CURD, I+IO_COLS, I+IO_COLD);
    k_dis0<<<CDIV(N0,256),256>>>(I+IO_CNTD, dis0);

    // down0
    k_gemm64<<<dim3(2, CDIV(N0,64)),256>>>(x, INC, W0, HID, XW0, N0, HID, INC, 0, 0, 0, 0);
    k_gcn0<<<N0,128>>>(XW0, b0, dis0, I+IO_OFFD, I+IO_COLD, h0);

    // pool1
    k_pnorm<<<1,128>>>(p1, pn);
    k_score<<<N0,128>>>(h0, p1, pn, score);
    k_topk<<<CDIV(N0,256),256>>>(score, N0, KK1, perm1, vals1);
    k_inv_init<<<CDIV(N0,256),256>>>(inv1, N0);
    k_inv_set<<<CDIV(KK1,256),256>>>(perm1, inv1, KK1);

    // augment(A0) -> A1 directly (sparse-sparse, exact integer adds)
    k_aug_pairs_direct<<<N0,128>>>(I+IO_OFFS, I+IO_COLS, I+IO_OFFD, I+IO_COLD, inv1, A1);
    k_aug_edges_direct<<<CDIV(E,256),256>>>(ei, E, inv1, A1);

    // down1: h1 = tanh(gcn(A1, gate(h0)))
    k_gather_gate<<<CDIV(KK1*HID,256),256>>>(h0, perm1, vals1, h1g, KK1);
    k_rowsum_dis<<<KK1,256>>>(A1, KK1, dis1);
    k_gemm64<<<dim3(2, CDIV(KK1,64)),256>>>(h1g, HID, W1, HID, XW, KK1, HID, HID, 0, 0, 0, 0);
    k_gemm64<<<dim3(2, CDIV(KK1,64)),256>>>(A1, KK1, XW, HID, h1, KK1, HID, KK1, dis1, dis1, XW, b1);

    // pool2
    k_pnorm<<<1,128>>>(p2, pn);
    k_score<<<KK1,128>>>(h1, p2, pn, score);
    k_topk<<<CDIV(KK1,256),256>>>(score, KK1, KK2, perm2, vals2);

    // A2 = (A1+I)[perm2,:] @ (A1+I)[:,perm2], diag zeroed  (750x750x1500 only)
    k_gather_rows<<<CDIV(KK2*KK1,256),256>>>(A1, perm2, Br);
    k_gather_cols<<<CDIV(KK1*BCLD,256),256>>>(A1, perm2, Bc);
    k_gemm64<<<dim3(CDIV(KK2,64), CDIV(KK2,64)),256>>>(Br, KK1, Bc, BCLD, A2, KK2, KK2, KK1, 0, 0, 0, 0);
    k_zero_diag<<<CDIV(KK2,256),256>>>(A2, KK2);

    // down2
    k_gather_gate<<<CDIV(KK2*HID,256),256>>>(h1, perm2, vals2, h2g, KK2);
    k_rowsum_dis<<<KK2,256>>>(A2, KK2, dis2);
    k_gemm64<<<dim3(2, CDIV(KK2,64)),256>>>(h2g, HID, W2, HID, XW, KK2, HID, HID, 0, 0, 0, 0);
    k_gemm64<<<dim3(2, CDIV(KK2,64)),256>>>(A2, KK2, XW, HID, h2, KK2, HID, KK2, dis2, dis2, XW, b2);

    // up0: u1 = h1 + scatter(h2); u1b = tanh(gcn(A1, u1))
    k_copy<<<CDIV(KK1*HID,256),256>>>(h1, u1, KK1*HID);
    k_scatter_add<<<CDIV(KK2*HID,256),256>>>(u1, h2, perm2, KK2);
    k_gemm64<<<dim3(2, CDIV(KK1,64)),256>>>(u1, HID, Wu0, HID, XW, KK1, HID, HID, 0, 0, 0, 0);
    k_gemm64<<<dim3(2, CDIV(KK1,64)),256>>>(A1, KK1, XW, HID, u1b, KK1, HID, KK1, dis1, dis1, XW, bu0);

    // up1: u0 = h0 + scatter(u1b); drift = gcn(A0, u0) + 0.1 z
    k_copy<<<CDIV(N0*HID,256),256>>>(h0, u0, N0*HID);
    k_scatter_add<<<CDIV(KK1*HID,256),256>>>(u0, u1b, perm1, KK1);
    k_gemm64<<<dim3(1, CDIV(N0,64)),256>>>(u0, HID, Wu1, OUTC, XW3, N0, OUTC, HID, 0, 0, 0, 0);
    k_gcn_final<<<CDIV(N0,128),128>>>(XW3, bu1, dis0, I+IO_OFFD, I+IO_COLD, z, out);
}

// round 9
// speedup vs baseline: 1.8240x; 1.5206x over previous
#include <cuda_runtime.h>
#include <math.h>

#define N0   3000
#define KK1  1500
#define KK2  750
#define HID  128
#define INC  32
#define OUTC 3
#define EMAX 48000
#define BCLD 768

#define CDIV(a,b) (((a)+(b)-1)/(b))

// ---------------- float scratch ----------------
static const size_t O_A1   = 0;                                  // KK1*KK1
static const size_t O_RS1  = O_A1  + (size_t)KK1*KK1;            // KK1
static const size_t O_RS2  = O_RS1 + KK1;                        // 768
static const size_t O_BC   = O_RS2 + 768;                        // KK1*BCLD
static const size_t O_A2   = O_BC  + (size_t)KK1*BCLD;           // KK2*KK2
static const size_t O_PART = O_A2  + (size_t)KK2*KK2;            // 4*KK1*HID = 768k
static const size_t O_XW0  = O_PART+ (size_t)4*KK1*HID;
static const size_t O_H0   = O_XW0 + (size_t)N0*HID;
static const size_t O_XW   = O_H0  + (size_t)N0*HID;
static const size_t O_H1   = O_XW  + (size_t)KK1*HID;
static const size_t O_U1B  = O_H1  + (size_t)KK1*HID;
static const size_t O_H2   = O_U1B + (size_t)KK1*HID;
static const size_t O_XW3  = O_H2  + (size_t)KK2*HID;
static const size_t O_DIS0 = O_XW3 + (size_t)N0*4;
static const size_t O_DIS1 = O_DIS0 + N0;
static const size_t O_DIS2 = O_DIS1 + KK1;
static const size_t O_SC   = O_DIS2 + 768;
static const size_t O_VL1  = O_SC   + N0;
static const size_t O_VL2  = O_VL1  + 1536;
static const size_t FTOT   = O_VL2  + 768;

__device__ float g_f[FTOT];

// ---------------- int scratch ----------------
static const size_t IO_CNTS = 0;
static const size_t IO_CNTD = 3000;
static const size_t IO_CURS = 6000;
static const size_t IO_CURD = 9000;
static const size_t IO_OFFS = 12000;
static const size_t IO_OFFD = 15008;
static const size_t IO_COLS = 18016;
static const size_t IO_COLD = IO_COLS + EMAX;
static const size_t IO_P1   = IO_COLD + EMAX;
static const size_t IO_P2   = IO_P1 + 1536;
static const size_t IO_INV1 = IO_P2 + 768;     // 3072
static const size_t IO_INV2 = IO_INV1 + 3072;  // 1536
static const size_t ITOT    = IO_INV2 + 1536;

__device__ int g_i[ITOT];

// ---------------- CSR build ----------------
__global__ void k_count(const int* ei, int E, int* cnt_s, int* cnt_d) {
    int e = blockIdx.x * blockDim.x + threadIdx.x;
    if (e < E) {
        atomicAdd(&cnt_s[ei[e]], 1);
        atomicAdd(&cnt_d[ei[E + e]], 1);
    }
}

__global__ void k_scan(const int* cnt, int n, int* off) {
    __shared__ int sh[3072];
    __shared__ int ps[1024];
    int tid = threadIdx.x;
    for (int i = tid; i < 3072; i += 1024) sh[i] = (i < n) ? cnt[i] : 0;
    __syncthreads();
    int a = sh[3*tid], b = sh[3*tid+1], c = sh[3*tid+2];
    int s = a + b + c;
    ps[tid] = s;
    __syncthreads();
    for (int d = 1; d < 1024; d <<= 1) {
        int v = 0;
        if (tid >= d) v = ps[tid - d];
        __syncthreads();
        if (tid >= d) ps[tid] += v;
        __syncthreads();
    }
    int excl = ps[tid] - s;
    if (3*tid   < n) off[3*tid]   = excl;
    if (3*tid+1 < n) off[3*tid+1] = excl + a;
    if (3*tid+2 < n) off[3*tid+2] = excl + a + b;
    if (tid == 1023) off[n] = ps[1023];
}

__global__ void k_fill(const int* ei, int E, const int* off_s, const int* off_d,
                       int* cur_s, int* cur_d, int* col_s, int* col_d) {
    int e = blockIdx.x * blockDim.x + threadIdx.x;
    if (e < E) {
        int s = ei[e], t = ei[E + e];
        int p = atomicAdd(&cur_s[s], 1); col_s[off_s[s] + p] = t;
        int q = atomicAdd(&cur_d[t], 1); col_d[off_d[t] + q] = s;
    }
}

__global__ void k_dis0(const int* cnt_d, float* dis) {
    int i = blockIdx.x * blockDim.x + threadIdx.x;
    if (i < N0) dis[i] = rsqrtf((float)cnt_d[i] + 2.0f);
}

// ---------------- templated SGEMM 64x64, BK=32, 4x4/thread ----------------
// AM: 0 plain A[gm]; 1 gather-gate A[aperm[gm]]*avals[gm]; 2 perm-row+diag A[aperm[gm]]+(gk==aperm[gm]);
//     3 add-scatter A[gm] + (ainv[gm]>=0 ? adelta[ainv[gm]] : 0)
// EPI: 0 plain store; 3 zero-diag store + rowsum atomic (A2 product)
// BSCALE: multiply B row k by bscale[k]
template<int AM, int EPI, bool BSCALE>
__global__ __launch_bounds__(256) void k_gemm64(
    const float* __restrict__ A, int lda,
    const float* __restrict__ B, int ldb,
    float* __restrict__ C,
    int M, int N, int K, int Kc,
    const float* __restrict__ bscale,
    const int* __restrict__ aperm, const float* __restrict__ avals,
    const float* __restrict__ adelta, const int* __restrict__ ainv,
    float* __restrict__ rowsum)
{
    __shared__ float As[32][68];
    __shared__ float Bs[32][64];
    int bm = blockIdx.y * 64, bn = blockIdx.x * 64;
    int kstart = blockIdx.z * Kc;
    int kend = min(K, kstart + Kc);
    if (gridDim.z > 1) C += (size_t)blockIdx.z * M * N;
    int tid = threadIdx.x, tx = tid & 15, ty = tid >> 4;
    float acc[4][4] = {};
    for (int k0 = kstart; k0 < kend; k0 += 32) {
        #pragma unroll
        for (int l = 0; l < 8; l++) {
            int idx = tid + l * 256;
            int m = idx >> 5, kk = idx & 31;
            int gm = bm + m, gk = k0 + kk;
            float v = 0.0f;
            if (gm < M && gk < kend) {
                if (AM == 0) v = A[(size_t)gm * lda + gk];
                else if (AM == 1) v = A[(size_t)aperm[gm] * lda + gk] * avals[gm];
                else if (AM == 2) {
                    int p = aperm[gm];
                    v = A[(size_t)p * lda + gk] + (gk == p ? 1.0f : 0.0f);
                } else {
                    v = A[(size_t)gm * lda + gk];
                    int r = ainv[gm];
                    if (r >= 0) v += adelta[(size_t)r * lda + gk];
                }
            }
            As[kk][m] = v;
        }
        #pragma unroll
        for (int l = 0; l < 8; l++) {
            int idx = tid + l * 256;
            int kk = idx >> 6, nn = idx & 63;
            int gk = k0 + kk, gn = bn + nn;
            float v = 0.0f;
            if (gk < kend && gn < N) {
                v = B[(size_t)gk * ldb + gn];
                if (BSCALE) v *= bscale[gk];
            }
            Bs[kk][nn] = v;
        }
        __syncthreads();
        #pragma unroll
        for (int kk = 0; kk < 32; kk++) {
            float a0 = As[kk][ty*4+0], a1 = As[kk][ty*4+1];
            float a2 = As[kk][ty*4+2], a3 = As[kk][ty*4+3];
            float b0 = Bs[kk][tx*4+0], b1 = Bs[kk][tx*4+1];
            float b2 = Bs[kk][tx*4+2], b3 = Bs[kk][tx*4+3];
            acc[0][0] += a0*b0; acc[0][1] += a0*b1; acc[0][2] += a0*b2; acc[0][3] += a0*b3;
            acc[1][0] += a1*b0; acc[1][1] += a1*b1; acc[1][2] += a1*b2; acc[1][3] += a1*b3;
            acc[2][0] += a2*b0; acc[2][1] += a2*b1; acc[2][2] += a2*b2; acc[2][3] += a2*b3;
            acc[3][0] += a3*b0; acc[3][1] += a3*b1; acc[3][2] += a3*b2; acc[3][3] += a3*b3;
        }
        __syncthreads();
    }
    #pragma unroll
    for (int r = 0; r < 4; r++) {
        int gm = bm + ty*4 + r;
        if (gm >= M) continue;
        float rpart = 0.0f;
        #pragma unroll
        for (int c = 0; c < 4; c++) {
            int gn = bn + tx*4 + c;
            if (gn < N) {
                float v = acc[r][c];
                if (EPI == 3) {
                    if (gm == gn) v = 0.0f;
                    rpart += v;
                }
                C[(size_t)gm * N + gn] = v;
            }
        }
        if (EPI == 3) {
            // reduce rpart across the 16 tx lanes (half-warp groups)
            #pragma unroll
            for (int off = 8; off > 0; off >>= 1)
                rpart += __shfl_down_sync(0xffffffffu, rpart, off, 16);
            if (tx == 0) atomicAdd(&rowsum[gm], rpart);
        }
    }
}

// ---------------- sparse GCN on A0 ----------------
__global__ void k_gcn0(const float* __restrict__ XW, const float* __restrict__ b,
                       const float* __restrict__ dis, const int* __restrict__ off,
                       const int* __restrict__ col, float* __restrict__ out) {
    __shared__ int   snb[128];
    __shared__ float sds[128];
    int i = blockIdx.x, c = threadIdx.x;
    float di = dis[i];
    float acc = 2.0f * di * XW[(size_t)i*HID + c];
    int s0 = off[i], s1 = off[i+1];
    for (int base = s0; base < s1; base += 128) {
        int e = base + c;
        if (e < s1) { int s = col[e]; snb[c] = s; sds[c] = dis[s]; }
        __syncthreads();
        int lim = min(128, s1 - base);
        for (int t = 0; t < lim; t++)
            acc += sds[t] * XW[(size_t)snb[t]*HID + c];
        __syncthreads();
    }
    out[(size_t)i*HID + c] = tanhf(di * acc + b[c]);
}

// ---------------- pooling (pnorm fused, inv init fused) ----------------
__global__ void k_score(const float* __restrict__ h, const float* __restrict__ p,
                        float* __restrict__ s, int* __restrict__ inv) {
    __shared__ float sh[128];
    __shared__ float sp[128];
    int i = blockIdx.x, c = threadIdx.x;
    float pc = p[c];
    sp[c] = pc * pc;
    sh[c] = h[(size_t)i*HID + c] * pc;
    __syncthreads();
    for (int st = 64; st > 0; st >>= 1) {
        if (c < st) { sh[c] += sh[c+st]; sp[c] += sp[c+st]; }
        __syncthreads();
    }
    if (c == 0) { s[i] = tanhf(sh[0] * rsqrtf(sp[0])); inv[i] = -1; }
}

__global__ void k_topk(const float* __restrict__ s, int n, int K,
                       int* __restrict__ perm, float* __restrict__ vals,
                       int* __restrict__ inv) {
    __shared__ float sh[256];
    int i = blockIdx.x * blockDim.x + threadIdx.x;
    float si = (i < n) ? s[i] : -1e30f;
    int rank = 0;
    for (int j0 = 0; j0 < n; j0 += 256) {
        int j = j0 + threadIdx.x;
        sh[threadIdx.x] = (j < n) ? s[j] : -1e30f;
        __syncthreads();
        const float4* sh4 = (const float4*)sh;
        #pragma unroll 4
        for (int t = 0; t < 64; t++) {
            float4 v = sh4[t];
            int jj = j0 + 4*t;
            rank += (v.x > si) || (v.x == si && jj   < i);
            rank += (v.y > si) || (v.y == si && jj+1 < i);
            rank += (v.z > si) || (v.z == si && jj+2 < i);
            rank += (v.w > si) || (v.w == si && jj+3 < i);
        }
        __syncthreads();
    }
    if (i < n && rank < K) { perm[rank] = i; vals[rank] = si; inv[i] = rank; }
}

// ---------------- sparse augment(A0) into A1 submatrix + rowsum ----------------
__global__ void k_aug_pairs(const int* __restrict__ off_s, const int* __restrict__ col_s,
                            const int* __restrict__ off_d, const int* __restrict__ col_d,
                            const int* __restrict__ inv, float* __restrict__ A1,
                            float* __restrict__ rs) {
    int k = blockIdx.x;
    int os = off_s[k], ns = off_s[k+1] - os;
    int od = off_d[k], nd = off_d[k+1] - od;
    int tot = ns * nd;
    for (int t = threadIdx.x; t < tot; t += 128) {
        int i = col_s[os + t / nd];   // edge k->i : A[i,k]
        int j = col_d[od + t % nd];   // edge j->k : A[k,j]
        if (i != k && j != k && i != j) {
            int r = inv[i], c = inv[j];
            if (r >= 0 && c >= 0) {
                atomicAdd(&A1[(size_t)r*KK1 + c], 1.0f);
                atomicAdd(&rs[r], 1.0f);
            }
        }
    }
}

__global__ void k_aug_edges(const int* ei, int E, const int* __restrict__ inv,
                            float* __restrict__ A1, float* __restrict__ rs) {
    int e = blockIdx.x * blockDim.x + threadIdx.x;
    if (e < E) {
        int s = ei[e], t = ei[E + e];
        if (s != t) {
            int r = inv[t], c = inv[s];
            if (r >= 0 && c >= 0) {
                atomicAdd(&A1[(size_t)r*KK1 + c], 2.0f);
                atomicAdd(&rs[r], 2.0f);
            }
        }
    }
}

__global__ void k_rs2dis(const float* rs, float* dis, int n) {
    int i = blockIdx.x * blockDim.x + threadIdx.x;
    if (i < n) dis[i] = rsqrtf(rs[i] + 2.0f);
}

// Bc[k][b] = A1[k][perm2[b]] + (k==perm2[b])
__global__ void k_gather_cols(const float* __restrict__ A1, const int* __restrict__ perm,
                              float* __restrict__ Bc) {
    int idx = blockIdx.x * blockDim.x + threadIdx.x;
    if (idx < KK1*BCLD) {
        int k = idx / BCLD, b = idx % BCLD;
        float v = 0.0f;
        if (b < KK2) {
            int pb = perm[b];
            v = A1[(size_t)k*KK1 + pb] + (k == pb ? 1.0f : 0.0f);
        }
        Bc[idx] = v;
    }
}

// out = tanh(dis[i]*(sum_z part[z]) + 2*dis^2*XW + bias)
__global__ void k_agg_epi(const float* __restrict__ part, int S,
                          const float* __restrict__ XW, const float* __restrict__ bias,
                          const float* __restrict__ dis, float* __restrict__ out, int n) {
    int idx = blockIdx.x * blockDim.x + threadIdx.x;
    if (idx < n*HID) {
        size_t stride = (size_t)n * HID;
        float a = part[idx];
        for (int zz = 1; zz < S; zz++) a += part[idx + zz*stride];
        int i = idx >> 7, c = idx & 127;
        float d = dis[i];
        out[idx] = tanhf(d * a + 2.0f * d * d * XW[idx] + bias[c]);
    }
}

// final sparse GCN (OUTC=3) + noise
__global__ void k_gcn_final(const float* __restrict__ XW3, const float* __restrict__ b,
                            const float* __restrict__ dis, const int* __restrict__ off,
                            const int* __restrict__ col, const float* __restrict__ z,
                            float* __restrict__ out) {
    int i = blockIdx.x * blockDim.x + threadIdx.x;
    if (i >= N0) return;
    float di = dis[i];
    float a0 = 2.0f * di * XW3[i*3+0];
    float a1 = 2.0f * di * XW3[i*3+1];
    float a2 = 2.0f * di * XW3[i*3+2];
    int s0 = off[i], s1 = off[i+1];
    for (int e = s0; e < s1; e++) {
        int s = col[e];
        float ds = dis[s];
        a0 += ds * XW3[s*3+0];
        a1 += ds * XW3[s*3+1];
        a2 += ds * XW3[s*3+2];
    }
    out[i*3+0] = di*a0 + b[0] + 0.1f*z[i*3+0];
    out[i*3+1] = di*a1 + b[1] + 0.1f*z[i*3+1];
    out[i*3+2] = di*a2 + b[2] + 0.1f*z[i*3+2];
}

// ---------------- launch ----------------
extern "C" void kernel_launch(void* const* d_in, const int* in_sizes, int n_in,
                              void* d_out, int out_size) {
    const float* x   = (const float*)d_in[0];
    const float* z   = (const float*)d_in[1];
    const float* W0  = (const float*)d_in[2];
    const float* b0  = (const float*)d_in[3];
    const float* W1  = (const float*)d_in[4];
    const float* b1  = (const float*)d_in[5];
    const float* W2  = (const float*)d_in[6];
    const float* b2  = (const float*)d_in[7];
    const float* p1  = (const float*)d_in[8];
    const float* p2  = (const float*)d_in[9];
    const float* Wu0 = (const float*)d_in[10];
    const float* bu0 = (const float*)d_in[11];
    const float* Wu1 = (const float*)d_in[12];
    const float* bu1 = (const float*)d_in[13];
    const int*   ei  = (const int*)d_in[14];
    int E = in_sizes[14] / 2;
    if (E > EMAX) E = EMAX;

    float* F; cudaGetSymbolAddress((void**)&F, g_f);
    int*   I; cudaGetSymbolAddress((void**)&I, g_i);
    float* out = (float*)d_out;

    float *A1 = F+O_A1, *rs1 = F+O_RS1, *rs2 = F+O_RS2;
    float *Bc = F+O_BC, *A2 = F+O_A2, *part = F+O_PART;
    float *XW0 = F+O_XW0, *h0 = F+O_H0, *XW = F+O_XW;
    float *h1 = F+O_H1, *u1b = F+O_U1B, *h2 = F+O_H2, *XW3 = F+O_XW3;
    float *dis0 = F+O_DIS0, *dis1 = F+O_DIS1, *dis2 = F+O_DIS2;
    float *score = F+O_SC, *vals1 = F+O_VL1, *vals2 = F+O_VL2;
    int *perm1 = I+IO_P1, *perm2 = I+IO_P2, *inv1 = I+IO_INV1, *inv2 = I+IO_INV2;

    // zero: A1 + rs1 + rs2 (contiguous), int counters, d_out (label part must be 0)
    cudaMemsetAsync(A1, 0, ((size_t)KK1*KK1 + KK1 + 768)*sizeof(float));
    cudaMemsetAsync(I, 0, 12000*sizeof(int));
    cudaMemsetAsync(d_out, 0, (size_t)out_size*sizeof(float));

    // CSR
    k_count<<<CDIV(E,256),256>>>(ei, E, I+IO_CNTS, I+IO_CNTD);
    k_scan<<<1,1024>>>(I+IO_CNTS, N0, I+IO_OFFS);
    k_scan<<<1,1024>>>(I+IO_CNTD, N0, I+IO_OFFD);
    k_fill<<<CDIV(E,256),256>>>(ei, E, I+IO_OFFS, I+IO_OFFD, I+IO_CURS, I+IO_CURD, I+IO_COLS, I+IO_COLD);
    k_dis0<<<CDIV(N0,256),256>>>(I+IO_CNTD, dis0);

    // down0: XW0 = x@W0 ; h0 = tanh(gcn0)
    k_gemm64<0,0,false><<<dim3(2, CDIV(N0,64), 1),256>>>(x, INC, W0, HID, XW0, N0, HID, INC, INC,
        0, 0, 0, 0, 0, 0);
    k_gcn0<<<N0,128>>>(XW0, b0, dis0, I+IO_OFFD, I+IO_COLD, h0);

    // pool1
    k_score<<<N0,128>>>(h0, p1, score, inv1);
    k_topk<<<CDIV(N0,256),256>>>(score, N0, KK1, perm1, vals1, inv1);

    // augment(A0) -> A1 + rowsum; dis1
    k_aug_pairs<<<N0,128>>>(I+IO_OFFS, I+IO_COLS, I+IO_OFFD, I+IO_COLD, inv1, A1, rs1);
    k_aug_edges<<<CDIV(E,256),256>>>(ei, E, inv1, A1, rs1);
    k_rs2dis<<<CDIV(KK1,256),256>>>(rs1, dis1, KK1);

    // down1: XW = gate(h0)@W1 ; split-K agg ; epi -> h1
    k_gemm64<1,0,false><<<dim3(2, CDIV(KK1,64), 1),256>>>(h0, HID, W1, HID, XW, KK1, HID, HID, HID,
        0, perm1, vals1, 0, 0, 0);
    k_gemm64<0,0,true><<<dim3(2, CDIV(KK1,64), 4),256>>>(A1, KK1, XW, HID, part, KK1, HID, KK1, 375,
        dis1, 0, 0, 0, 0, 0);
    k_agg_epi<<<CDIV(KK1*HID,256),256>>>(part, 4, XW, b1, dis1, h1, KK1);

    // pool2
    k_score<<<KK1,128>>>(h1, p2, score, inv2);
    k_topk<<<CDIV(KK1,256),256>>>(score, KK1, KK2, perm2, vals2, inv2);

    // A2 = (A1+I)[perm2,:] @ (A1+I)[:,perm2], diag zeroed, rowsum -> rs2 (zeroed upfront)
    k_gather_cols<<<CDIV(KK1*BCLD,256),256>>>(A1, perm2, Bc);
    k_gemm64<2,3,false><<<dim3(CDIV(KK2,64), CDIV(KK2,64), 1),256>>>(A1, KK1, Bc, BCLD, A2,
        KK2, KK2, KK1, KK1, 0, perm2, 0, 0, 0, rs2);
    k_rs2dis<<<CDIV(KK2,256),256>>>(rs2, dis2, KK2);

    // down2: XW = gate(h1)@W2 ; split-K agg ; epi -> h2
    k_gemm64<1,0,false><<<dim3(2, CDIV(KK2,64), 1),256>>>(h1, HID, W2, HID, XW, KK2, HID, HID, HID,
        0, perm2, vals2, 0, 0, 0);
    k_gemm64<0,0,true><<<dim3(2, CDIV(KK2,64), 8),256>>>(A2, KK2, XW, HID, part, KK2, HID, KK2, 94,
        dis2, 0, 0, 0, 0, 0);
    k_agg_epi<<<CDIV(KK2*HID,256),256>>>(part, 8, XW, b2, dis2, h2, KK2);

    // up0: XW = (h1 + scatter(h2,inv2))@Wu0 ; split-K agg ; epi -> u1b
    k_gemm64<3,0,false><<<dim3(2, CDIV(KK1,64), 1),256>>>(h1, HID, Wu0, HID, XW, KK1, HID, HID, HID,
        0, 0, 0, h2, inv2, 0);
    k_gemm64<0,0,true><<<dim3(2, CDIV(KK1,64), 4),256>>>(A1, KK1, XW, HID, part, KK1, HID, KK1, 375,
        dis1, 0, 0, 0, 0, 0);
    k_agg_epi<<<CDIV(KK1*HID,256),256>>>(part, 4, XW, bu0, dis1, u1b, KK1);

    // up1: XW3 = (h0 + scatter(u1b,inv1))@Wu1 ; final sparse GCN + noise
    k_gemm64<3,0,false><<<dim3(1, CDIV(N0,64), 1),256>>>(h0, HID, Wu1, OUTC, XW3, N0, OUTC, HID, HID,
        0, 0, 0, u1b, inv1, 0);
    k_gcn_final<<<CDIV(N0,128),128>>>(XW3, bu1, dis0, I+IO_OFFD, I+IO_COLD, z, out);
}

// round 10
// speedup vs baseline: 2.0761x; 1.1382x over previous
#include <cuda_runtime.h>
#include <math.h>

#define N0   3000
#define KK1  1500
#define KK2  750
#define A2LD 752
#define HID  128
#define INC  32
#define OUTC 3
#define EMAX 48000
#define BCLD 768

#define CDIV(a,b) (((a)+(b)-1)/(b))

// ---------------- float scratch ----------------
static const size_t O_A1   = 0;                                  // KK1*KK1
static const size_t O_RS1  = O_A1  + (size_t)KK1*KK1;            // KK1
static const size_t O_RS2  = O_RS1 + KK1;                        // 768
static const size_t O_BC   = O_RS2 + 768;                        // KK1*BCLD
static const size_t O_A2   = O_BC  + (size_t)KK1*BCLD;           // KK2*A2LD
static const size_t O_PART = O_A2  + (size_t)KK2*A2LD;           // 2,304,000
static const size_t O_XW0  = O_PART+ (size_t)2304000;
static const size_t O_H0   = O_XW0 + (size_t)N0*HID;
static const size_t O_XW   = O_H0  + (size_t)N0*HID;
static const size_t O_H1   = O_XW  + (size_t)KK1*HID;
static const size_t O_U1B  = O_H1  + (size_t)KK1*HID;
static const size_t O_H2   = O_U1B + (size_t)KK1*HID;
static const size_t O_XW3  = O_H2  + (size_t)KK2*HID;
static const size_t O_SC   = O_XW3 + (size_t)N0*4;
static const size_t O_VL1  = O_SC  + N0;
static const size_t O_VL2  = O_VL1 + 1536;
static const size_t FTOT   = O_VL2 + 768;

__device__ float g_f[FTOT];

// ---------------- int scratch ----------------
static const size_t IO_CNTS = 0;
static const size_t IO_CNTD = 3000;
static const size_t IO_CURS = 6000;
static const size_t IO_CURD = 9000;
static const size_t IO_OFFS = 12000;
static const size_t IO_OFFD = 15008;
static const size_t IO_COLS = 18016;
static const size_t IO_COLD = IO_COLS + EMAX;
static const size_t IO_P1   = IO_COLD + EMAX;
static const size_t IO_P2   = IO_P1 + 1536;
static const size_t IO_INV1 = IO_P2 + 768;     // 3072
static const size_t IO_INV2 = IO_INV1 + 3072;  // 1536
static const size_t ITOT    = IO_INV2 + 1536;

__device__ int g_i[ITOT];

// ---------------- CSR build ----------------
__global__ void k_count(const int* ei, int E, int* cnt_s, int* cnt_d) {
    int e = blockIdx.x * blockDim.x + threadIdx.x;
    if (e < E) {
        atomicAdd(&cnt_s[ei[e]], 1);
        atomicAdd(&cnt_d[ei[E + e]], 1);
    }
}

__global__ void k_scan(const int* cnt, int n, int* off) {
    __shared__ int sh[3072];
    __shared__ int ps[1024];
    int tid = threadIdx.x;
    for (int i = tid; i < 3072; i += 1024) sh[i] = (i < n) ? cnt[i] : 0;
    __syncthreads();
    int a = sh[3*tid], b = sh[3*tid+1], c = sh[3*tid+2];
    int s = a + b + c;
    ps[tid] = s;
    __syncthreads();
    for (int d = 1; d < 1024; d <<= 1) {
        int v = 0;
        if (tid >= d) v = ps[tid - d];
        __syncthreads();
        if (tid >= d) ps[tid] += v;
        __syncthreads();
    }
    int excl = ps[tid] - s;
    if (3*tid   < n) off[3*tid]   = excl;
    if (3*tid+1 < n) off[3*tid+1] = excl + a;
    if (3*tid+2 < n) off[3*tid+2] = excl + a + b;
    if (tid == 1023) off[n] = ps[1023];
}

__global__ void k_fill(const int* ei, int E, const int* off_s, const int* off_d,
                       int* cur_s, int* cur_d, int* col_s, int* col_d) {
    int e = blockIdx.x * blockDim.x + threadIdx.x;
    if (e < E) {
        int s = ei[e], t = ei[E + e];
        int p = atomicAdd(&cur_s[s], 1); col_s[off_s[s] + p] = t;
        int q = atomicAdd(&cur_d[t], 1); col_d[off_d[t] + q] = s;
    }
}

// ---------------- SGEMM 128x128 tile, BK=16, 8x8 microtile ----------------
// AM: 0 plain A[gm]; 1 gather-gate A[aperm[gm]]*avals[gm];
//     2 perm-row+diag A[aperm[gm]] + (gk==aperm[gm]);
//     3 add-scatter A[gm] + (ainv[gm]>=0 ? adelta[ainv[gm]] : 0)
// BS: 0 none; 1 B row k scaled by rsqrtf(rs[k]+2)
// Requires: lda%4==0, ldb%4==0, Kc%16==0 (for z>1).
template<int AM, int BS>
__global__ __launch_bounds__(256) void k_gemm128(
    const float* __restrict__ A, int lda,
    const float* __restrict__ B, int ldb,
    float* __restrict__ C, int ldc,
    int M, int N, int K, int Kc,
    const float* __restrict__ rs,
    const int* __restrict__ aperm, const float* __restrict__ avals,
    const float* __restrict__ adelta, const int* __restrict__ ainv)
{
    __shared__ float As[16][132];
    __shared__ float Bs[16][128];
    int bm = blockIdx.y * 128, bn = blockIdx.x * 128;
    int kstart = blockIdx.z * Kc;
    int kend = min(K, kstart + Kc);
    if (gridDim.z > 1) C += (size_t)blockIdx.z * M * ldc;
    int tid = threadIdx.x, tx = tid & 15, ty = tid >> 4;
    float acc[8][8] = {};
    for (int k0 = kstart; k0 < kend; k0 += 16) {
        // ---- load A tile (128 rows x 16 k) as float4 along k ----
        #pragma unroll
        for (int l = 0; l < 2; l++) {
            int idx = tid + l * 256;            // [0,512)
            int m = idx >> 2, k4 = idx & 3;
            int gm = bm + m, gk = k0 + k4 * 4;  // gk % 4 == 0 (kstart mult of 16)
            float4 v = make_float4(0.f, 0.f, 0.f, 0.f);
            if (gm < M) {
                const float* src;
                float scale = 1.0f;
                int p = -1;
                if (AM == 1)      { p = aperm[gm]; scale = avals[gm]; src = A + (size_t)p * lda; }
                else if (AM == 2) { p = aperm[gm];                     src = A + (size_t)p * lda; }
                else               src = A + (size_t)gm * lda;
                if (gk + 3 < kend) v = *(const float4*)(src + gk);
                else {
                    float* vv = &v.x;
                    #pragma unroll
                    for (int q = 0; q < 4; q++) if (gk + q < kend) vv[q] = src[gk + q];
                }
                if (AM == 1) { v.x *= scale; v.y *= scale; v.z *= scale; v.w *= scale; }
                if (AM == 2) {
                    if (p >= gk && p < gk + 4 && p < kend) (&v.x)[p - gk] += 1.0f;
                }
                if (AM == 3) {
                    int r = ainv[gm];
                    if (r >= 0) {
                        const float* ds = adelta + (size_t)r * lda;
                        if (gk + 3 < kend) {
                            float4 d4 = *(const float4*)(ds + gk);
                            v.x += d4.x; v.y += d4.y; v.z += d4.z; v.w += d4.w;
                        } else {
                            float* vv = &v.x;
                            #pragma unroll
                            for (int q = 0; q < 4; q++) if (gk + q < kend) vv[q] += ds[gk + q];
                        }
                    }
                }
            }
            As[k4*4+0][m] = v.x; As[k4*4+1][m] = v.y;
            As[k4*4+2][m] = v.z; As[k4*4+3][m] = v.w;
        }
        // ---- load B tile (16 k x 128 n) as float4 along n ----
        #pragma unroll
        for (int l = 0; l < 2; l++) {
            int idx = tid + l * 256;
            int kk = idx >> 5, n4 = idx & 31;
            int gk = k0 + kk, gn = bn + n4 * 4;
            float4 v = make_float4(0.f, 0.f, 0.f, 0.f);
            if (gk < kend && gn < N) {
                if (gn + 3 < N) v = *(const float4*)(B + (size_t)gk * ldb + gn);
                else {
                    float* vv = &v.x;
                    #pragma unroll
                    for (int q = 0; q < 4; q++) if (gn + q < N) vv[q] = B[(size_t)gk * ldb + gn + q];
                }
                if (BS == 1) {
                    float sc = rsqrtf(rs[gk] + 2.0f);
                    v.x *= sc; v.y *= sc; v.z *= sc; v.w *= sc;
                }
            }
            *(float4*)&Bs[kk][n4*4] = v;
        }
        __syncthreads();
        #pragma unroll
        for (int kk = 0; kk < 16; kk++) {
            float a[8], b[8];
            *(float4*)&a[0] = *(const float4*)&As[kk][ty*8];
            *(float4*)&a[4] = *(const float4*)&As[kk][ty*8+4];
            *(float4*)&b[0] = *(const float4*)&Bs[kk][tx*8];
            *(float4*)&b[4] = *(const float4*)&Bs[kk][tx*8+4];
            #pragma unroll
            for (int r = 0; r < 8; r++)
                #pragma unroll
                for (int c = 0; c < 8; c++)
                    acc[r][c] += a[r] * b[c];
        }
        __syncthreads();
    }
    #pragma unroll
    for (int r = 0; r < 8; r++) {
        int gm = bm + ty*8 + r;
        if (gm >= M) continue;
        #pragma unroll
        for (int c = 0; c < 8; c++) {
            int gn = bn + tx*8 + c;
            if (gn < N) C[(size_t)gm * ldc + gn] = acc[r][c];
        }
    }
}

// ---------------- sparse GCN on A0 (dis from degree counts) ----------------
__global__ void k_gcn0(const float* __restrict__ XW, const float* __restrict__ b,
                       const int* __restrict__ cnt, const int* __restrict__ off,
                       const int* __restrict__ col, float* __restrict__ out) {
    __shared__ int   snb[128];
    __shared__ float sds[128];
    int i = blockIdx.x, c = threadIdx.x;
    float di = rsqrtf((float)cnt[i] + 2.0f);
    float acc = 2.0f * di * XW[(size_t)i*HID + c];
    int s0 = off[i], s1 = off[i+1];
    for (int base = s0; base < s1; base += 128) {
        int e = base + c;
        if (e < s1) { int s = col[e]; snb[c] = s; sds[c] = rsqrtf((float)cnt[s] + 2.0f); }
        __syncthreads();
        int lim = min(128, s1 - base);
        for (int t = 0; t < lim; t++)
            acc += sds[t] * XW[(size_t)snb[t]*HID + c];
        __syncthreads();
    }
    out[(size_t)i*HID + c] = tanhf(di * acc + b[c]);
}

// ---------------- pooling ----------------
__global__ void k_score(const float* __restrict__ h, const float* __restrict__ p,
                        float* __restrict__ s, int* __restrict__ inv) {
    __shared__ float sh[128];
    __shared__ float sp[128];
    int i = blockIdx.x, c = threadIdx.x;
    float pc = p[c];
    sp[c] = pc * pc;
    sh[c] = h[(size_t)i*HID + c] * pc;
    __syncthreads();
    for (int st = 64; st > 0; st >>= 1) {
        if (c < st) { sh[c] += sh[c+st]; sp[c] += sp[c+st]; }
        __syncthreads();
    }
    if (c == 0) { s[i] = tanhf(sh[0] * rsqrtf(sp[0])); inv[i] = -1; }
}

__global__ void k_topk(const float* __restrict__ s, int n, int K,
                       int* __restrict__ perm, float* __restrict__ vals,
                       int* __restrict__ inv) {
    __shared__ float sh[256];
    int i = blockIdx.x * blockDim.x + threadIdx.x;
    float si = (i < n) ? s[i] : -1e30f;
    int rank = 0;
    for (int j0 = 0; j0 < n; j0 += 256) {
        int j = j0 + threadIdx.x;
        sh[threadIdx.x] = (j < n) ? s[j] : -1e30f;
        __syncthreads();
        const float4* sh4 = (const float4*)sh;
        #pragma unroll 4
        for (int t = 0; t < 64; t++) {
            float4 v = sh4[t];
            int jj = j0 + 4*t;
            rank += (v.x > si) || (v.x == si && jj   < i);
            rank += (v.y > si) || (v.y == si && jj+1 < i);
            rank += (v.z > si) || (v.z == si && jj+2 < i);
            rank += (v.w > si) || (v.w == si && jj+3 < i);
        }
        __syncthreads();
    }
    if (i < n && rank < K) { perm[rank] = i; vals[rank] = si; inv[i] = rank; }
}

// ---------------- sparse augment(A0) into A1 submatrix + rowsum ----------------
__global__ void k_aug_pairs(const int* __restrict__ off_s, const int* __restrict__ col_s,
                            const int* __restrict__ off_d, const int* __restrict__ col_d,
                            const int* __restrict__ inv, float* __restrict__ A1,
                            float* __restrict__ rs) {
    int k = blockIdx.x;
    int os = off_s[k], ns = off_s[k+1] - os;
    int od = off_d[k], nd = off_d[k+1] - od;
    int tot = ns * nd;
    for (int t = threadIdx.x; t < tot; t += 128) {
        int i = col_s[os + t / nd];   // edge k->i : A[i,k]
        int j = col_d[od + t % nd];   // edge j->k : A[k,j]
        if (i != k && j != k && i != j) {
            int r = inv[i], c = inv[j];
            if (r >= 0 && c >= 0) {
                atomicAdd(&A1[(size_t)r*KK1 + c], 1.0f);
                atomicAdd(&rs[r], 1.0f);
            }
        }
    }
}

__global__ void k_aug_edges(const int* ei, int E, const int* __restrict__ inv,
                            float* __restrict__ A1, float* __restrict__ rs) {
    int e = blockIdx.x * blockDim.x + threadIdx.x;
    if (e < E) {
        int s = ei[e], t = ei[E + e];
        if (s != t) {
            int r = inv[t], c = inv[s];
            if (r >= 0 && c >= 0) {
                atomicAdd(&A1[(size_t)r*KK1 + c], 2.0f);
                atomicAdd(&rs[r], 2.0f);
            }
        }
    }
}

// Bc[k][b] = A1[k][perm2[b]] + (k==perm2[b])
__global__ void k_gather_cols(const float* __restrict__ A1, const int* __restrict__ perm,
                              float* __restrict__ Bc) {
    int idx = blockIdx.x * blockDim.x + threadIdx.x;
    if (idx < KK1*BCLD) {
        int k = idx / BCLD, b = idx % BCLD;
        float v = 0.0f;
        if (b < KK2) {
            int pb = perm[b];
            v = A1[(size_t)k*KK1 + pb] + (k == pb ? 1.0f : 0.0f);
        }
        Bc[idx] = v;
    }
}

// sum 4 partials of the A2 product, zero diag, rowsum -> rs2, store A2 (ld=A2LD)
__global__ void k_a2_finish(const float* __restrict__ part, float* __restrict__ A2,
                            float* __restrict__ rs2) {
    __shared__ float sh[256];
    int i = blockIdx.x;
    float rsum = 0.0f;
    for (int j = threadIdx.x; j < KK2; j += 256) {
        float s = 0.0f;
        #pragma unroll
        for (int zz = 0; zz < 4; zz++)
            s += part[(size_t)zz*KK2*A2LD + (size_t)i*A2LD + j];
        if (j == i) s = 0.0f;
        A2[(size_t)i*A2LD + j] = s;
        rsum += s;
    }
    sh[threadIdx.x] = rsum;
    __syncthreads();
    for (int st = 128; st > 0; st >>= 1) {
        if (threadIdx.x < st) sh[threadIdx.x] += sh[threadIdx.x + st];
        __syncthreads();
    }
    if (threadIdx.x == 0) rs2[i] = sh[0];
}

// out = tanh(d*(sum_z part[z]) + 2*d^2*XW + bias), d = rsqrt(rs+2)
__global__ void k_agg_epi(const float* __restrict__ part, int S,
                          const float* __restrict__ XW, const float* __restrict__ bias,
                          const float* __restrict__ rs, float* __restrict__ out, int n) {
    int idx = blockIdx.x * blockDim.x + threadIdx.x;
    if (idx < n*HID) {
        size_t stride = (size_t)n * HID;
        float a = part[idx];
        #pragma unroll 4
        for (int zz = 1; zz < S; zz++) a += part[idx + zz*stride];
        int i = idx >> 7, c = idx & 127;
        float d = rsqrtf(rs[i] + 2.0f);
        out[idx] = tanhf(d * a + 2.0f * d * d * XW[idx] + bias[c]);
    }
}

// XW3 = (h0 + scatter(u1b, inv1)) @ Wu1  (N=3), warp per row
__global__ void k_xw3(const float* __restrict__ h0, const float* __restrict__ u1b,
                      const int* __restrict__ inv1, const float* __restrict__ W,
                      float* __restrict__ XW3) {
    int w = (blockIdx.x * blockDim.x + threadIdx.x) >> 5;
    int lane = threadIdx.x & 31;
    if (w >= N0) return;
    int r = inv1[w];
    float a0 = 0.f, a1 = 0.f, a2 = 0.f;
    #pragma unroll
    for (int q = 0; q < 4; q++) {
        int k = lane + q * 32;
        float v = h0[(size_t)w*HID + k];
        if (r >= 0) v += u1b[(size_t)r*HID + k];
        a0 += v * W[k*3+0];
        a1 += v * W[k*3+1];
        a2 += v * W[k*3+2];
    }
    #pragma unroll
    for (int off = 16; off > 0; off >>= 1) {
        a0 += __shfl_down_sync(0xffffffffu, a0, off);
        a1 += __shfl_down_sync(0xffffffffu, a1, off);
        a2 += __shfl_down_sync(0xffffffffu, a2, off);
    }
    if (lane == 0) { XW3[w*3+0] = a0; XW3[w*3+1] = a1; XW3[w*3+2] = a2; }
}

// final sparse GCN (OUTC=3) + noise
__global__ void k_gcn_final(const float* __restrict__ XW3, const float* __restrict__ b,
                            const int* __restrict__ cnt, const int* __restrict__ off,
                            const int* __restrict__ col, const float* __restrict__ z,
                            float* __restrict__ out) {
    int i = blockIdx.x * blockDim.x + threadIdx.x;
    if (i >= N0) return;
    float di = rsqrtf((float)cnt[i] + 2.0f);
    float a0 = 2.0f * di * XW3[i*3+0];
    float a1 = 2.0f * di * XW3[i*3+1];
    float a2 = 2.0f * di * XW3[i*3+2];
    int s0 = off[i], s1 = off[i+1];
    for (int e = s0; e < s1; e++) {
        int s = col[e];
        float ds = rsqrtf((float)cnt[s] + 2.0f);
        a0 += ds * XW3[s*3+0];
        a1 += ds * XW3[s*3+1];
        a2 += ds * XW3[s*3+2];
    }
    out[i*3+0] = di*a0 + b[0] + 0.1f*z[i*3+0];
    out[i*3+1] = di*a1 + b[1] + 0.1f*z[i*3+1];
    out[i*3+2] = di*a2 + b[2] + 0.1f*z[i*3+2];
}

// ---------------- launch ----------------
extern "C" void kernel_launch(void* const* d_in, const int* in_sizes, int n_in,
                              void* d_out, int out_size) {
    const float* x   = (const float*)d_in[0];
    const float* z   = (const float*)d_in[1];
    const float* W0  = (const float*)d_in[2];
    const float* b0  = (const float*)d_in[3];
    const float* W1  = (const float*)d_in[4];
    const float* b1  = (const float*)d_in[5];
    const float* W2  = (const float*)d_in[6];
    const float* b2  = (const float*)d_in[7];
    const float* p1  = (const float*)d_in[8];
    const float* p2  = (const float*)d_in[9];
    const float* Wu0 = (const float*)d_in[10];
    const float* bu0 = (const float*)d_in[11];
    const float* Wu1 = (const float*)d_in[12];
    const float* bu1 = (const float*)d_in[13];
    const int*   ei  = (const int*)d_in[14];
    int E = in_sizes[14] / 2;
    if (E > EMAX) E = EMAX;

    float* F; cudaGetSymbolAddress((void**)&F, g_f);
    int*   I; cudaGetSymbolAddress((void**)&I, g_i);
    float* out = (float*)d_out;

    float *A1 = F+O_A1, *rs1 = F+O_RS1, *rs2 = F+O_RS2;
    float *Bc = F+O_BC, *A2 = F+O_A2, *part = F+O_PART;
    float *XW0 = F+O_XW0, *h0 = F+O_H0, *XW = F+O_XW;
    float *h1 = F+O_H1, *u1b = F+O_U1B, *h2 = F+O_H2, *XW3 = F+O_XW3;
    float *score = F+O_SC, *vals1 = F+O_VL1, *vals2 = F+O_VL2;
    int *perm1 = I+IO_P1, *perm2 = I+IO_P2, *inv1 = I+IO_INV1, *inv2 = I+IO_INV2;

    cudaMemsetAsync(A1, 0, ((size_t)KK1*KK1 + KK1 + 768)*sizeof(float));
    cudaMemsetAsync(I, 0, 12000*sizeof(int));
    cudaMemsetAsync(d_out, 0, (size_t)out_size*sizeof(float));

    // CSR
    k_count<<<CDIV(E,256),256>>>(ei, E, I+IO_CNTS, I+IO_CNTD);
    k_scan<<<1,1024>>>(I+IO_CNTS, N0, I+IO_OFFS);
    k_scan<<<1,1024>>>(I+IO_CNTD, N0, I+IO_OFFD);
    k_fill<<<CDIV(E,256),256>>>(ei, E, I+IO_OFFS, I+IO_OFFD, I+IO_CURS, I+IO_CURD, I+IO_COLS, I+IO_COLD);

    // down0: XW0 = x@W0 ; h0 = tanh(gcn0)
    k_gemm128<0,0><<<dim3(1, CDIV(N0,128), 1),256>>>(x, INC, W0, HID, XW0, HID,
        N0, HID, INC, INC, 0, 0, 0, 0, 0);
    k_gcn0<<<N0,128>>>(XW0, b0, I+IO_CNTD, I+IO_OFFD, I+IO_COLD, h0);

    // pool1
    k_score<<<N0,128>>>(h0, p1, score, inv1);
    k_topk<<<CDIV(N0,256),256>>>(score, N0, KK1, perm1, vals1, inv1);

    // augment(A0) -> A1 + rowsum
    k_aug_pairs<<<N0,128>>>(I+IO_OFFS, I+IO_COLS, I+IO_OFFD, I+IO_COLD, inv1, A1, rs1);
    k_aug_edges<<<CDIV(E,256),256>>>(ei, E, inv1, A1, rs1);

    // down1: XW = gate(h0)@W1 ; split-K agg ; epi -> h1
    k_gemm128<1,0><<<dim3(1, CDIV(KK1,128), 1),256>>>(h0, HID, W1, HID, XW, HID,
        KK1, HID, HID, HID, 0, perm1, vals1, 0, 0);
    k_gemm128<0,1><<<dim3(1, CDIV(KK1,128), 12),256>>>(A1, KK1, XW, HID, part, HID,
        KK1, HID, KK1, 128, rs1, 0, 0, 0, 0);
    k_agg_epi<<<CDIV(KK1*HID,256),256>>>(part, 12, XW, b1, rs1, h1, KK1);

    // pool2
    k_score<<<KK1,128>>>(h1, p2, score, inv2);
    k_topk<<<CDIV(KK1,256),256>>>(score, KK1, KK2, perm2, vals2, inv2);

    // A2 = (A1+I)[perm2,:] @ (A1+I)[:,perm2] : split-K partials then finish
    k_gather_cols<<<CDIV(KK1*BCLD,256),256>>>(A1, perm2, Bc);
    k_gemm128<2,0><<<dim3(CDIV(KK2,128), CDIV(KK2,128), 4),256>>>(A1, KK1, Bc, BCLD, part, A2LD,
        KK2, KK2, KK1, 384, 0, perm2, 0, 0, 0);
    k_a2_finish<<<KK2,256>>>(part, A2, rs2);

    // down2: XW = gate(h1)@W2 ; split-K agg ; epi -> h2
    k_gemm128<1,0><<<dim3(1, CDIV(KK2,128), 1),256>>>(h1, HID, W2, HID, XW, HID,
        KK2, HID, HID, HID, 0, perm2, vals2, 0, 0);
    k_gemm128<0,1><<<dim3(1, CDIV(KK2,128), 24),256>>>(A2, A2LD, XW, HID, part, HID,
        KK2, HID, KK2, 32, rs2, 0, 0, 0, 0);
    k_agg_epi<<<CDIV(KK2*HID,256),256>>>(part, 24, XW, b2, rs2, h2, KK2);

    // up0: XW = (h1 + scatter(h2,inv2))@Wu0 ; split-K agg ; epi -> u1b
    k_gemm128<3,0><<<dim3(1, CDIV(KK1,128), 1),256>>>(h1, HID, Wu0, HID, XW, HID,
        KK1, HID, HID, HID, 0, 0, 0, h2, inv2);
    k_gemm128<0,1><<<dim3(1, CDIV(KK1,128), 12),256>>>(A1, KK1, XW, HID, part, HID,
        KK1, HID, KK1, 128, rs1, 0, 0, 0, 0);
    k_agg_epi<<<CDIV(KK1*HID,256),256>>>(part, 12, XW, bu0, rs1, u1b, KK1);

    // up1: XW3 = (h0 + scatter(u1b,inv1))@Wu1 ; final sparse GCN + noise
    k_xw3<<<CDIV(N0*32,256),256>>>(h0, u1b, inv1, Wu1, XW3);
    k_gcn_final<<<CDIV(N0,128),128>>>(XW3, bu1, I+IO_CNTD, I+IO_OFFD, I+IO_COLD, z, out);
}

// round 12
// speedup vs baseline: 2.8408x; 1.3683x over previous
#include <cuda_runtime.h>
#include <cuda_bf16.h>
#include <mma.h>
#include <math.h>

using namespace nvcuda;

#define N0   3000
#define KK1  1500
#define KK2  750
#define A2LD 752
#define HID  128
#define INC  32
#define OUTC 3
#define EMAX 48000

#define KP1  1536   // padded K/M for bf16 ops (KK1 -> 1536)
#define MP2  768    // padded KK2 -> 768

#define CDIV(a,b) (((a)+(b)-1)/(b))

// ---------------- float scratch ----------------
static const size_t O_A1   = 0;                                  // KK1*KK1
static const size_t O_RS1  = O_A1  + (size_t)KK1*KK1;            // KK1
static const size_t O_RS2  = O_RS1 + KK1;                        // 768
static const size_t O_A2   = O_RS2 + 768;                        // KK2*A2LD
static const size_t O_PART = O_A2  + (size_t)KK2*A2LD;           // 2,359,296
static const size_t O_XW0  = O_PART+ (size_t)2359296;
static const size_t O_H0   = O_XW0 + (size_t)N0*HID;
static const size_t O_XW   = O_H0  + (size_t)N0*HID;
static const size_t O_H1   = O_XW  + (size_t)KK1*HID;
static const size_t O_U1B  = O_H1  + (size_t)KK1*HID;
static const size_t O_H2   = O_U1B + (size_t)KK1*HID;
static const size_t O_XW3  = O_H2  + (size_t)KK2*HID;
static const size_t O_SC   = O_XW3 + (size_t)N0*4;
static const size_t O_VL1  = O_SC  + N0;
static const size_t O_VL2  = O_VL1 + 1536;
static const size_t FTOT   = O_VL2 + 768;

__device__ float g_f[FTOT];

// ---------------- bf16 scratch ----------------
static const size_t HB_A1 = 0;                                   // KP1*KP1
static const size_t HB_AR = HB_A1 + (size_t)KP1*KP1;             // MP2*KP1
static const size_t HB_BC = HB_AR + (size_t)MP2*KP1;             // KP1*MP2
static const size_t HB_XH = HB_BC + (size_t)KP1*MP2;             // KP1*HID
static const size_t HB_XL = HB_XH + (size_t)KP1*HID;             // KP1*HID
static const size_t HTOT  = HB_XL + (size_t)KP1*HID;

__device__ __nv_bfloat16 g_h[HTOT];

// ---------------- int scratch ----------------
static const size_t IO_CNTS = 0;
static const size_t IO_CNTD = 3000;
static const size_t IO_CURS = 6000;
static const size_t IO_CURD = 9000;
static const size_t IO_OFFS = 12000;
static const size_t IO_OFFD = 15008;
static const size_t IO_COLS = 18016;
static const size_t IO_COLD = IO_COLS + EMAX;
static const size_t IO_P1   = IO_COLD + EMAX;
static const size_t IO_P2   = IO_P1 + 1536;
static const size_t IO_INV1 = IO_P2 + 768;
static const size_t IO_INV2 = IO_INV1 + 3072;
static const size_t ITOT    = IO_INV2 + 1536;

__device__ int g_i[ITOT];

// ---------------- CSR build ----------------
__global__ void k_count(const int* ei, int E, int* cnt_s, int* cnt_d) {
    int e = blockIdx.x * blockDim.x + threadIdx.x;
    if (e < E) {
        atomicAdd(&cnt_s[ei[e]], 1);
        atomicAdd(&cnt_d[ei[E + e]], 1);
    }
}

__global__ void k_scan(const int* cnt, int n, int* off) {
    __shared__ int sh[3072];
    __shared__ int ps[1024];
    int tid = threadIdx.x;
    for (int i = tid; i < 3072; i += 1024) sh[i] = (i < n) ? cnt[i] : 0;
    __syncthreads();
    int a = sh[3*tid], b = sh[3*tid+1], c = sh[3*tid+2];
    int s = a + b + c;
    ps[tid] = s;
    __syncthreads();
    for (int d = 1; d < 1024; d <<= 1) {
        int v = 0;
        if (tid >= d) v = ps[tid - d];
        __syncthreads();
        if (tid >= d) ps[tid] += v;
        __syncthreads();
    }
    int excl = ps[tid] - s;
    if (3*tid   < n) off[3*tid]   = excl;
    if (3*tid+1 < n) off[3*tid+1] = excl + a;
    if (3*tid+2 < n) off[3*tid+2] = excl + a + b;
    if (tid == 1023) off[n] = ps[1023];
}

__global__ void k_fill(const int* ei, int E, const int* off_s, const int* off_d,
                       int* cur_s, int* cur_d, int* col_s, int* col_d) {
    int e = blockIdx.x * blockDim.x + threadIdx.x;
    if (e < E) {
        int s = ei[e], t = ei[E + e];
        int p = atomicAdd(&cur_s[s], 1); col_s[off_s[s] + p] = t;
        int q = atomicAdd(&cur_d[t], 1); col_d[off_d[t] + q] = s;
    }
}

// ---------------- fp32 SGEMM 128x128 tile, BK=16, 8x8 microtile ----------------
// AM: 0 plain; 1 gather-gate; 3 add-scatter. BS: 1 => B row scaled by rsqrt(rs[k]+2).
template<int AM, int BS>
__global__ __launch_bounds__(256) void k_gemm128(
    const float* __restrict__ A, int lda,
    const float* __restrict__ B, int ldb,
    float* __restrict__ C, int ldc,
    int M, int N, int K, int Kc,
    const float* __restrict__ rs,
    const int* __restrict__ aperm, const float* __restrict__ avals,
    const float* __restrict__ adelta, const int* __restrict__ ainv)
{
    __shared__ float As[16][132];
    __shared__ float Bs[16][128];
    int bm = blockIdx.y * 128, bn = blockIdx.x * 128;
    int kstart = blockIdx.z * Kc;
    int kend = min(K, kstart + Kc);
    if (gridDim.z > 1) C += (size_t)blockIdx.z * M * ldc;
    int tid = threadIdx.x, tx = tid & 15, ty = tid >> 4;
    float acc[8][8] = {};
    for (int k0 = kstart; k0 < kend; k0 += 16) {
        #pragma unroll
        for (int l = 0; l < 2; l++) {
            int idx = tid + l * 256;
            int m = idx >> 2, k4 = idx & 3;
            int gm = bm + m, gk = k0 + k4 * 4;
            float4 v = make_float4(0.f, 0.f, 0.f, 0.f);
            if (gm < M) {
                const float* src;
                float scale = 1.0f;
                if (AM == 1)      { scale = avals[gm]; src = A + (size_t)aperm[gm] * lda; }
                else               src = A + (size_t)gm * lda;
                if (gk + 3 < kend) v = *(const float4*)(src + gk);
                else {
                    float* vv = &v.x;
                    #pragma unroll
                    for (int q = 0; q < 4; q++) if (gk + q < kend) vv[q] = src[gk + q];
                }
                if (AM == 1) { v.x *= scale; v.y *= scale; v.z *= scale; v.w *= scale; }
                if (AM == 3) {
                    int r = ainv[gm];
                    if (r >= 0) {
                        const float* ds = adelta + (size_t)r * lda;
                        if (gk + 3 < kend) {
                            float4 d4 = *(const float4*)(ds + gk);
                            v.x += d4.x; v.y += d4.y; v.z += d4.z; v.w += d4.w;
                        } else {
                            float* vv = &v.x;
                            #pragma unroll
                            for (int q = 0; q < 4; q++) if (gk + q < kend) vv[q] += ds[gk + q];
                        }
                    }
                }
            }
            As[k4*4+0][m] = v.x; As[k4*4+1][m] = v.y;
            As[k4*4+2][m] = v.z; As[k4*4+3][m] = v.w;
        }
        #pragma unroll
        for (int l = 0; l < 2; l++) {
            int idx = tid + l * 256;
            int kk = idx >> 5, n4 = idx & 31;
            int gk = k0 + kk, gn = bn + n4 * 4;
            float4 v = make_float4(0.f, 0.f, 0.f, 0.f);
            if (gk < kend && gn < N) {
                if (gn + 3 < N) v = *(const float4*)(B + (size_t)gk * ldb + gn);
                else {
                    float* vv = &v.x;
                    #pragma unroll
                    for (int q = 0; q < 4; q++) if (gn + q < N) vv[q] = B[(size_t)gk * ldb + gn + q];
                }
                if (BS == 1) {
                    float sc = rsqrtf(rs[gk] + 2.0f);
                    v.x *= sc; v.y *= sc; v.z *= sc; v.w *= sc;
                }
            }
            *(float4*)&Bs[kk][n4*4] = v;
        }
        __syncthreads();
        #pragma unroll
        for (int kk = 0; kk < 16; kk++) {
            float a[8], b[8];
            *(float4*)&a[0] = *(const float4*)&As[kk][ty*8];
            *(float4*)&a[4] = *(const float4*)&As[kk][ty*8+4];
            *(float4*)&b[0] = *(const float4*)&Bs[kk][tx*8];
            *(float4*)&b[4] = *(const float4*)&Bs[kk][tx*8+4];
            #pragma unroll
            for (int r = 0; r < 8; r++)
                #pragma unroll
                for (int c = 0; c < 8; c++)
                    acc[r][c] += a[r] * b[c];
        }
        __syncthreads();
    }
    #pragma unroll
    for (int r = 0; r < 8; r++) {
        int gm = bm + ty*8 + r;
        if (gm >= M) continue;
        #pragma unroll
        for (int c = 0; c < 8; c++) {
            int gn = bn + tx*8 + c;
            if (gn < N) C[(size_t)gm * ldc + gn] = acc[r][c];
        }
    }
}

// ---------------- bf16 WMMA GEMM: 128x128 tile, 8 warps of 64x32 ----------------
// All operands padded (no bounds checks). SPLIT=1: C += A@Bh + A@Bl (hi/lo split).
template<int SPLIT>
__global__ __launch_bounds__(256) void k_wgemm(
    const __nv_bfloat16* __restrict__ A, int lda,
    const __nv_bfloat16* __restrict__ Bh, const __nv_bfloat16* __restrict__ Bl, int ldb,
    float* __restrict__ C, int ldc, int Kc, size_t zstride)
{
    __shared__ __nv_bfloat16 As[128][48];
    __shared__ __nv_bfloat16 Bsh[32][136];
    __shared__ __nv_bfloat16 Bsl[SPLIT ? 32 : 1][SPLIT ? 136 : 8];
    int bm = blockIdx.y * 128, bn = blockIdx.x * 128;
    int k0beg = blockIdx.z * Kc;
    C += (size_t)blockIdx.z * zstride;
    int tid = threadIdx.x;
    int wid = tid >> 5;
    int wm = wid >> 2, wn = wid & 3;

    wmma::fragment<wmma::accumulator,16,16,16,float> cf[4][2];
    #pragma unroll
    for (int i = 0; i < 4; i++)
        #pragma unroll
        for (int j = 0; j < 2; j++)
            wmma::fill_fragment(cf[i][j], 0.0f);

    for (int k0 = k0beg; k0 < k0beg + Kc; k0 += 32) {
        #pragma unroll
        for (int l = 0; l < 2; l++) {
            int idx = tid + l * 256;
            int m = idx >> 2, q = idx & 3;
            *(uint4*)&As[m][q*8] = *(const uint4*)(A + (size_t)(bm + m)*lda + k0 + q*8);
        }
        #pragma unroll
        for (int l = 0; l < 2; l++) {
            int idx = tid + l * 256;
            int kk = idx >> 4, q = idx & 15;
            *(uint4*)&Bsh[kk][q*8] = *(const uint4*)(Bh + (size_t)(k0 + kk)*ldb + bn + q*8);
        }
        if (SPLIT) {
            #pragma unroll
            for (int l = 0; l < 2; l++) {
                int idx = tid + l * 256;
                int kk = idx >> 4, q = idx & 15;
                *(uint4*)&Bsl[kk][q*8] = *(const uint4*)(Bl + (size_t)(k0 + kk)*ldb + bn + q*8);
            }
        }
        __syncthreads();
        #pragma unroll
        for (int ks = 0; ks < 2; ks++) {
            wmma::fragment<wmma::matrix_a,16,16,16,__nv_bfloat16,wmma::row_major> af[4];
            #pragma unroll
            for (int i = 0; i < 4; i++)
                wmma::load_matrix_sync(af[i], &As[wm*64 + i*16][ks*16], 48);
            wmma::fragment<wmma::matrix_b,16,16,16,__nv_bfloat16,wmma::row_major> bf[2];
            #pragma unroll
            for (int j = 0; j < 2; j++)
                wmma::load_matrix_sync(bf[j], &Bsh[ks*16][wn*32 + j*16], 136);
            #pragma unroll
            for (int i = 0; i < 4; i++)
                #pragma unroll
                for (int j = 0; j < 2; j++)
                    wmma::mma_sync(cf[i][j], af[i], bf[j], cf[i][j]);
            if (SPLIT) {
                #pragma unroll
                for (int j = 0; j < 2; j++)
                    wmma::load_matrix_sync(bf[j], &Bsl[ks*16][wn*32 + j*16], 136);
                #pragma unroll
                for (int i = 0; i < 4; i++)
                    #pragma unroll
                    for (int j = 0; j < 2; j++)
                        wmma::mma_sync(cf[i][j], af[i], bf[j], cf[i][j]);
            }
        }
        __syncthreads();
    }
    #pragma unroll
    for (int i = 0; i < 4; i++)
        #pragma unroll
        for (int j = 0; j < 2; j++)
            wmma::store_matrix_sync(C + (size_t)(bm + wm*64 + i*16)*ldc + bn + wn*32 + j*16,
                                    cf[i][j], ldc, wmma::mem_row_major);
}

// ---------------- bf16 conversions (row per block, padded writes) ----------------
__global__ void k_conv_A1(const float* __restrict__ A1, __nv_bfloat16* __restrict__ dst) {
    int r = blockIdx.x;  // [0,1536)
    for (int c = threadIdx.x; c < KP1; c += 256) {
        float v = (r < KK1 && c < KK1) ? A1[(size_t)r*KK1 + c] : 0.0f;
        dst[(size_t)r*KP1 + c] = __float2bfloat16(v);
    }
}

// Ar[r][c] = A1[perm2[r]][c] + (c==perm2[r]), padded to 768x1536
__global__ void k_conv_ar(const float* __restrict__ A1, const int* __restrict__ perm,
                          __nv_bfloat16* __restrict__ dst) {
    int r = blockIdx.x;  // [0,768)
    int pr = (r < KK2) ? perm[r] : -1;
    for (int c = threadIdx.x; c < KP1; c += 256) {
        float v = 0.0f;
        if (pr >= 0 && c < KK1) v = A1[(size_t)pr*KK1 + c] + (c == pr ? 1.0f : 0.0f);
        dst[(size_t)r*KP1 + c] = __float2bfloat16(v);
    }
}

// Bc[k][b] = A1[k][perm2[b]] + (k==perm2[b]), padded to 1536x768
__global__ void k_conv_bc(const float* __restrict__ A1, const int* __restrict__ perm,
                          __nv_bfloat16* __restrict__ dst) {
    int k = blockIdx.x;  // [0,1536)
    for (int b = threadIdx.x; b < MP2; b += 256) {
        float v = 0.0f;
        if (k < KK1 && b < KK2) {
            int pb = perm[b];
            v = A1[(size_t)k*KK1 + pb] + (k == pb ? 1.0f : 0.0f);
        }
        dst[(size_t)k*MP2 + b] = __float2bfloat16(v);
    }
}

// hi/lo split of XW (n real rows, padded to 1536)
__global__ void k_conv_hilo(const float* __restrict__ XW, int n,
                            __nv_bfloat16* __restrict__ hi, __nv_bfloat16* __restrict__ lo) {
    int r = blockIdx.x;  // [0,1536)
    for (int c = threadIdx.x; c < HID; c += 256) {
        __nv_bfloat16 h = __float2bfloat16(0.0f), l = __float2bfloat16(0.0f);
        if (r < n) {
            float v = XW[(size_t)r*HID + c];
            h = __float2bfloat16(v);
            l = __float2bfloat16(v - __bfloat162float(h));
        }
        hi[(size_t)r*HID + c] = h;
        lo[(size_t)r*HID + c] = l;
    }
}

// ---------------- sparse GCN on A0 ----------------
__global__ void k_gcn0(const float* __restrict__ XW, const float* __restrict__ b,
                       const int* __restrict__ cnt, const int* __restrict__ off,
                       const int* __restrict__ col, float* __restrict__ out) {
    __shared__ int   snb[128];
    __shared__ float sds[128];
    int i = blockIdx.x, c = threadIdx.x;
    float di = rsqrtf((float)cnt[i] + 2.0f);
    float acc = 2.0f * di * XW[(size_t)i*HID + c];
    int s0 = off[i], s1 = off[i+1];
    for (int base = s0; base < s1; base += 128) {
        int e = base + c;
        if (e < s1) { int s = col[e]; snb[c] = s; sds[c] = rsqrtf((float)cnt[s] + 2.0f); }
        __syncthreads();
        int lim = min(128, s1 - base);
        for (int t = 0; t < lim; t++)
            acc += sds[t] * XW[(size_t)snb[t]*HID + c];
        __syncthreads();
    }
    out[(size_t)i*HID + c] = tanhf(di * acc + b[c]);
}

// ---------------- pooling ----------------
__global__ void k_score(const float* __restrict__ h, const float* __restrict__ p,
                        float* __restrict__ s, int* __restrict__ inv) {
    __shared__ float sh[128];
    __shared__ float sp[128];
    int i = blockIdx.x, c = threadIdx.x;
    float pc = p[c];
    sp[c] = pc * pc;
    sh[c] = h[(size_t)i*HID + c] * pc;
    __syncthreads();
    for (int st = 64; st > 0; st >>= 1) {
        if (c < st) { sh[c] += sh[c+st]; sp[c] += sp[c+st]; }
        __syncthreads();
    }
    if (c == 0) { s[i] = tanhf(sh[0] * rsqrtf(sp[0])); inv[i] = -1; }
}

__global__ void k_topk(const float* __restrict__ s, int n, int K,
                       int* __restrict__ perm, float* __restrict__ vals,
                       int* __restrict__ inv) {
    __shared__ float sh[256];
    int i = blockIdx.x * blockDim.x + threadIdx.x;
    float si = (i < n) ? s[i] : -1e30f;
    int rank = 0;
    for (int j0 = 0; j0 < n; j0 += 256) {
        int j = j0 + threadIdx.x;
        sh[threadIdx.x] = (j < n) ? s[j] : -1e30f;
        __syncthreads();
        const float4* sh4 = (const float4*)sh;
        #pragma unroll 4
        for (int t = 0; t < 64; t++) {
            float4 v = sh4[t];
            int jj = j0 + 4*t;
            rank += (v.x > si) || (v.x == si && jj   < i);
            rank += (v.y > si) || (v.y == si && jj+1 < i);
            rank += (v.z > si) || (v.z == si && jj+2 < i);
            rank += (v.w > si) || (v.w == si && jj+3 < i);
        }
        __syncthreads();
    }
    if (i < n && rank < K) { perm[rank] = i; vals[rank] = si; inv[i] = rank; }
}

// ---------------- sparse augment(A0) into A1 submatrix + rowsum ----------------
__global__ void k_aug_pairs(const int* __restrict__ off_s, const int* __restrict__ col_s,
                            const int* __restrict__ off_d, const int* __restrict__ col_d,
                            const int* __restrict__ inv, float* __restrict__ A1,
                            float* __restrict__ rs) {
    int k = blockIdx.x;
    int os = off_s[k], ns = off_s[k+1] - os;
    int od = off_d[k], nd = off_d[k+1] - od;
    int tot = ns * nd;
    for (int t = threadIdx.x; t < tot; t += 128) {
        int i = col_s[os + t / nd];
        int j = col_d[od + t % nd];
        if (i != k && j != k && i != j) {
            int r = inv[i], c = inv[j];
            if (r >= 0 && c >= 0) {
                atomicAdd(&A1[(size_t)r*KK1 + c], 1.0f);
                atomicAdd(&rs[r], 1.0f);
            }
        }
    }
}

__global__ void k_aug_edges(const int* ei, int E, const int* __restrict__ inv,
                            float* __restrict__ A1, float* __restrict__ rs) {
    int e = blockIdx.x * blockDim.x + threadIdx.x;
    if (e < E) {
        int s = ei[e], t = ei[E + e];
        if (s != t) {
            int r = inv[t], c = inv[s];
            if (r >= 0 && c >= 0) {
                atomicAdd(&A1[(size_t)r*KK1 + c], 2.0f);
                atomicAdd(&rs[r], 2.0f);
            }
        }
    }
}

// sum 4 partials (ld 768, 768-row chunks), zero diag, rowsum -> rs2, store A2 (ld A2LD)
__global__ void k_a2_finish(const float* __restrict__ part, float* __restrict__ A2,
                            float* __restrict__ rs2) {
    __shared__ float sh[256];
    int i = blockIdx.x;
    float rsum = 0.0f;
    for (int j = threadIdx.x; j < KK2; j += 256) {
        float s = 0.0f;
        #pragma unroll
        for (int zz = 0; zz < 4; zz++)
            s += part[((size_t)zz*MP2 + i)*MP2 + j];
        if (j == i) s = 0.0f;
        A2[(size_t)i*A2LD + j] = s;
        rsum += s;
    }
    sh[threadIdx.x] = rsum;
    __syncthreads();
    for (int st = 128; st > 0; st >>= 1) {
        if (threadIdx.x < st) sh[threadIdx.x] += sh[threadIdx.x + st];
        __syncthreads();
    }
    if (threadIdx.x == 0) rs2[i] = sh[0];
}

// out = tanh(d*(sum_z part[z]) + 2*d^2*XW + bias), d = rsqrt(rs+2)
__global__ void k_agg_epi(const float* __restrict__ part, int S, size_t zstride,
                          const float* __restrict__ XW, const float* __restrict__ bias,
                          const float* __restrict__ rs, float* __restrict__ out, int n) {
    int idx = blockIdx.x * blockDim.x + threadIdx.x;
    if (idx < n*HID) {
        int i = idx >> 7, c = idx & 127;
        size_t base = (size_t)i * HID + c;
        float a = part[base];
        #pragma unroll 4
        for (int zz = 1; zz < S; zz++) a += part[base + zz*zstride];
        float d = rsqrtf(rs[i] + 2.0f);
        out[idx] = tanhf(d * a + 2.0f * d * d * XW[idx] + bias[c]);
    }
}

// scaled agg: d applied to the partial sum of A@(dis*XW)? -- d goes outside; B not prescaled
// (wgemm computes A1@XW; epi must apply dis to both sides: d_i * sum_k a_ik d_k xw_k.
//  So B must carry d_k. We fold d_k into the hi/lo conversion instead.)
__global__ void k_conv_hilo_scaled(const float* __restrict__ XW, int n,
                                   const float* __restrict__ rs,
                                   __nv_bfloat16* __restrict__ hi, __nv_bfloat16* __restrict__ lo) {
    int r = blockIdx.x;  // [0,1536)
    float d = (r < n) ? rsqrtf(rs[r] + 2.0f) : 0.0f;
    for (int c = threadIdx.x; c < HID; c += 256) {
        __nv_bfloat16 h = __float2bfloat16(0.0f), l = __float2bfloat16(0.0f);
        if (r < n) {
            float v = XW[(size_t)r*HID + c] * d;
            h = __float2bfloat16(v);
            l = __float2bfloat16(v - __bfloat162float(h));
        }
        hi[(size_t)r*HID + c] = h;
        lo[(size_t)r*HID + c] = l;
    }
}

// XW3 = (h0 + scatter(u1b, inv1)) @ Wu1  (N=3), warp per row
__global__ void k_xw3(const float* __restrict__ h0, const float* __restrict__ u1b,
                      const int* __restrict__ inv1, const float* __restrict__ W,
                      float* __restrict__ XW3) {
    int w = (blockIdx.x * blockDim.x + threadIdx.x) >> 5;
    int lane = threadIdx.x & 31;
    if (w >= N0) return;
    int r = inv1[w];
    float a0 = 0.f, a1 = 0.f, a2 = 0.f;
    #pragma unroll
    for (int q = 0; q < 4; q++) {
        int k = lane + q * 32;
        float v = h0[(size_t)w*HID + k];
        if (r >= 0) v += u1b[(size_t)r*HID + k];
        a0 += v * W[k*3+0];
        a1 += v * W[k*3+1];
        a2 += v * W[k*3+2];
    }
    #pragma unroll
    for (int off = 16; off > 0; off >>= 1) {
        a0 += __shfl_down_sync(0xffffffffu, a0, off);
        a1 += __shfl_down_sync(0xffffffffu, a1, off);
        a2 += __shfl_down_sync(0xffffffffu, a2, off);
    }
    if (lane == 0) { XW3[w*3+0] = a0; XW3[w*3+1] = a1; XW3[w*3+2] = a2; }
}

// final sparse GCN (OUTC=3) + noise
__global__ void k_gcn_final(const float* __restrict__ XW3, const float* __restrict__ b,
                            const int* __restrict__ cnt, const int* __restrict__ off,
                            const int* __restrict__ col, const float* __restrict__ z,
                            float* __restrict__ out) {
    int i = blockIdx.x * blockDim.x + threadIdx.x;
    if (i >= N0) return;
    float di = rsqrtf((float)cnt[i] + 2.0f);
    float a0 = 2.0f * di * XW3[i*3+0];
    float a1 = 2.0f * di * XW3[i*3+1];
    float a2 = 2.0f * di * XW3[i*3+2];
    int s0 = off[i], s1 = off[i+1];
    for (int e = s0; e < s1; e++) {
        int s = col[e];
        float ds = rsqrtf((float)cnt[s] + 2.0f);
        a0 += ds * XW3[s*3+0];
        a1 += ds * XW3[s*3+1];
        a2 += ds * XW3[s*3+2];
    }
    out[i*3+0] = di*a0 + b[0] + 0.1f*z[i*3+0];
    out[i*3+1] = di*a1 + b[1] + 0.1f*z[i*3+1];
    out[i*3+2] = di*a2 + b[2] + 0.1f*z[i*3+2];
}

// epilogue for scaled-B wgemm aggregation: out = tanh(d*sumpart + 2*d^2*XW + bias)
// (B already carried d_k, so sum is d-free on the k side; only outer d_i here)
// -- same as k_agg_epi; reuse it.

// ---------------- launch ----------------
extern "C" void kernel_launch(void* const* d_in, const int* in_sizes, int n_in,
                              void* d_out, int out_size) {
    const float* x   = (const float*)d_in[0];
    const float* z   = (const float*)d_in[1];
    const float* W0  = (const float*)d_in[2];
    const float* b0  = (const float*)d_in[3];
    const float* W1  = (const float*)d_in[4];
    const float* b1  = (const float*)d_in[5];
    const float* W2  = (const float*)d_in[6];
    const float* b2  = (const float*)d_in[7];
    const float* p1  = (const float*)d_in[8];
    const float* p2  = (const float*)d_in[9];
    const float* Wu0 = (const float*)d_in[10];
    const float* bu0 = (const float*)d_in[11];
    const float* Wu1 = (const float*)d_in[12];
    const float* bu1 = (const float*)d_in[13];
    const int*   ei  = (const int*)d_in[14];
    int E = in_sizes[14] / 2;
    if (E > EMAX) E = EMAX;

    float* F; cudaGetSymbolAddress((void**)&F, g_f);
    int*   I; cudaGetSymbolAddress((void**)&I, g_i);
    __nv_bfloat16* H; cudaGetSymbolAddress((void**)&H, g_h);
    float* out = (float*)d_out;

    float *A1 = F+O_A1, *rs1 = F+O_RS1, *rs2 = F+O_RS2;
    float *A2 = F+O_A2, *part = F+O_PART;
    float *XW0 = F+O_XW0, *h0 = F+O_H0, *XW = F+O_XW;
    float *h1 = F+O_H1, *u1b = F+O_U1B, *h2 = F+O_H2, *XW3 = F+O_XW3;
    float *score = F+O_SC, *vals1 = F+O_VL1, *vals2 = F+O_VL2;
    __nv_bfloat16 *A1bf = H+HB_A1, *Ar = H+HB_AR, *Bc = H+HB_BC;
    __nv_bfloat16 *XWh = H+HB_XH, *XWl = H+HB_XL;
    int *perm1 = I+IO_P1, *perm2 = I+IO_P2, *inv1 = I+IO_INV1, *inv2 = I+IO_INV2;

    cudaMemsetAsync(A1, 0, ((size_t)KK1*KK1 + KK1 + 768)*sizeof(float));
    cudaMemsetAsync(I, 0, 12000*sizeof(int));
    cudaMemsetAsync(d_out, 0, (size_t)out_size*sizeof(float));

    // CSR
    k_count<<<CDIV(E,256),256>>>(ei, E, I+IO_CNTS, I+IO_CNTD);
    k_scan<<<1,1024>>>(I+IO_CNTS, N0, I+IO_OFFS);
    k_scan<<<1,1024>>>(I+IO_CNTD, N0, I+IO_OFFD);
    k_fill<<<CDIV(E,256),256>>>(ei, E, I+IO_OFFS, I+IO_OFFD, I+IO_CURS, I+IO_CURD, I+IO_COLS, I+IO_COLD);

    // down0
    k_gemm128<0,0><<<dim3(1, CDIV(N0,128), 1),256>>>(x, INC, W0, HID, XW0, HID,
        N0, HID, INC, INC, 0, 0, 0, 0, 0);
    k_gcn0<<<N0,128>>>(XW0, b0, I+IO_CNTD, I+IO_OFFD, I+IO_COLD, h0);

    // pool1
    k_score<<<N0,128>>>(h0, p1, score, inv1);
    k_topk<<<CDIV(N0,256),256>>>(score, N0, KK1, perm1, vals1, inv1);

    // augment(A0) -> A1 + rowsum; bf16 copy
    k_aug_pairs<<<N0,128>>>(I+IO_OFFS, I+IO_COLS, I+IO_OFFD, I+IO_COLD, inv1, A1, rs1);
    k_aug_edges<<<CDIV(E,256),256>>>(ei, E, inv1, A1, rs1);
    k_conv_A1<<<KP1,256>>>(A1, A1bf);

    // down1: XW = gate(h0)@W1 ; bf16 agg (B carries dis) ; epi -> h1
    k_gemm128<1,0><<<dim3(1, CDIV(KK1,128), 1),256>>>(h0, HID, W1, HID, XW, HID,
        KK1, HID, HID, HID, 0, perm1, vals1, 0, 0);
    k_conv_hilo_scaled<<<KP1,256>>>(XW, KK1, rs1, XWh, XWl);
    k_wgemm<1><<<dim3(1, 12, 12),256>>>(A1bf, KP1, XWh, XWl, HID, part, HID, 128, (size_t)KP1*HID);
    k_agg_epi<<<CDIV(KK1*HID,256),256>>>(part, 12, (size_t)KP1*HID, XW, b1, rs1, h1, KK1);

    // pool2
    k_score<<<KK1,128>>>(h1, p2, score, inv2);
    k_topk<<<CDIV(KK1,256),256>>>(score, KK1, KK2, perm2, vals2, inv2);

    // A2 = (A1+I)[perm2,:] @ (A1+I)[:,perm2]  — exact bf16 tensor-core product
    k_conv_ar<<<MP2,256>>>(A1, perm2, Ar);
    k_conv_bc<<<KP1,256>>>(A1, perm2, Bc);
    k_wgemm<0><<<dim3(6, 6, 4),256>>>(Ar, KP1, Bc, Bc, MP2, part, MP2, 384, (size_t)MP2*MP2);
    k_a2_finish<<<KK2,256>>>(part, A2, rs2);

    // down2: XW = gate(h1)@W2 ; fp32 split-K agg (A2 not bf16-exact) ; epi -> h2
    k_gemm128<1,0><<<dim3(1, CDIV(KK2,128), 1),256>>>(h1, HID, W2, HID, XW, HID,
        KK2, HID, HID, HID, 0, perm2, vals2, 0, 0);
    k_gemm128<0,1><<<dim3(1, CDIV(KK2,128), 24),256>>>(A2, A2LD, XW, HID, part, HID,
        KK2, HID, KK2, 32, rs2, 0, 0, 0, 0);
    k_agg_epi<<<CDIV(KK2*HID,256),256>>>(part, 24, (size_t)KK2*HID, XW, b2, rs2, h2, KK2);

    // up0: XW = (h1 + scatter(h2,inv2))@Wu0 ; bf16 agg ; epi -> u1b
    k_gemm128<3,0><<<dim3(1, CDIV(KK1,128), 1),256>>>(h1, HID, Wu0, HID, XW, HID,
        KK1, HID, HID, HID, 0, 0, 0, h2, inv2);
    k_conv_hilo_scaled<<<KP1,256>>>(XW, KK1, rs1, XWh, XWl);
    k_wgemm<1><<<dim3(1, 12, 12),256>>>(A1bf, KP1, XWh, XWl, HID, part, HID, 128, (size_t)KP1*HID);
    k_agg_epi<<<CDIV(KK1*HID,256),256>>>(part, 12, (size_t)KP1*HID, XW, bu0, rs1, u1b, KK1);

    // up1: XW3 = (h0 + scatter(u1b,inv1))@Wu1 ; final sparse GCN + noise
    k_xw3<<<CDIV(N0*32,256),256>>>(h0, u1b, inv1, Wu1, XW3);
    k_gcn_final<<<CDIV(N0,128),128>>>(XW3, bu1, I+IO_CNTD, I+IO_OFFD, I+IO_COLD, z, out);
}

// round 13
// speedup vs baseline: 3.6228x; 1.2753x over previous
#include <cuda_runtime.h>
#include <cuda_bf16.h>
#include <mma.h>
#include <math.h>

using namespace nvcuda;

#define N0   3000
#define KK1  1500
#define KK2  750
#define A2LD 752
#define HID  128
#define INC  32
#define OUTC 3
#define EMAX 48000

#define KP1  1536
#define MP2  768

#define CDIV(a,b) (((a)+(b)-1)/(b))

// ---------------- float scratch ----------------
static const size_t O_A1   = 0;                                  // KK1*KK1
static const size_t O_RS1  = O_A1  + (size_t)KK1*KK1;            // KK1
static const size_t O_RS2  = O_RS1 + KK1;                        // 768
static const size_t O_A2   = O_RS2 + 768;                        // KK2*A2LD
static const size_t O_PART = O_A2  + (size_t)KK2*A2LD;           // 2,359,296
static const size_t O_XW0  = O_PART+ (size_t)2359296;
static const size_t O_H0   = O_XW0 + (size_t)N0*HID;
static const size_t O_XW   = O_H0  + (size_t)N0*HID;
static const size_t O_H1   = O_XW  + (size_t)KK1*HID;
static const size_t O_U1B  = O_H1  + (size_t)KK1*HID;
static const size_t O_H2   = O_U1B + (size_t)KK1*HID;
static const size_t O_XW3  = O_H2  + (size_t)KK2*HID;
static const size_t O_SC   = O_XW3 + (size_t)N0*4;
static const size_t O_VL1  = O_SC  + N0;
static const size_t O_VL2  = O_VL1 + 1536;
static const size_t FTOT   = O_VL2 + 768;

__device__ float g_f[FTOT];

// ---------------- bf16 scratch ----------------
static const size_t HB_A1 = 0;                                   // KP1*KP1
static const size_t HB_AR = HB_A1 + (size_t)KP1*KP1;             // MP2*KP1
static const size_t HB_BC = HB_AR + (size_t)MP2*KP1;             // KP1*MP2
static const size_t HB_XH = HB_BC + (size_t)KP1*MP2;             // KP1*HID
static const size_t HB_XL = HB_XH + (size_t)KP1*HID;             // KP1*HID
static const size_t HTOT  = HB_XL + (size_t)KP1*HID;

__device__ __nv_bfloat16 g_h[HTOT];

// ---------------- int scratch ----------------
static const size_t IO_CNTS = 0;
static const size_t IO_CNTD = 3000;
static const size_t IO_CURS = 6000;
static const size_t IO_CURD = 9000;
static const size_t IO_OFFS = 12000;
static const size_t IO_OFFD = 15008;
static const size_t IO_COLS = 18016;
static const size_t IO_COLD = IO_COLS + EMAX;
static const size_t IO_P1   = IO_COLD + EMAX;
static const size_t IO_P2   = IO_P1 + 1536;
static const size_t IO_INV1 = IO_P2 + 768;
static const size_t IO_INV2 = IO_INV1 + 3072;
static const size_t ITOT    = IO_INV2 + 1536;

__device__ int g_i[ITOT];

// ---------------- CSR build ----------------
__global__ void k_count(const int* ei, int E, int* cnt_s, int* cnt_d) {
    int e = blockIdx.x * blockDim.x + threadIdx.x;
    if (e < E) {
        atomicAdd(&cnt_s[ei[e]], 1);
        atomicAdd(&cnt_d[ei[E + e]], 1);
    }
}

// both scans in one launch: blockIdx.x = 0 -> (cnt_s,off_s), 1 -> (cnt_d,off_d)
__global__ void k_scan2(const int* cnt_s, int* off_s, const int* cnt_d, int* off_d, int n) {
    __shared__ int sh[3072];
    __shared__ int ps[1024];
    const int* cnt = blockIdx.x ? cnt_d : cnt_s;
    int* off       = blockIdx.x ? off_d : off_s;
    int tid = threadIdx.x;
    for (int i = tid; i < 3072; i += 1024) sh[i] = (i < n) ? cnt[i] : 0;
    __syncthreads();
    int a = sh[3*tid], b = sh[3*tid+1], c = sh[3*tid+2];
    int s = a + b + c;
    ps[tid] = s;
    __syncthreads();
    for (int d = 1; d < 1024; d <<= 1) {
        int v = 0;
        if (tid >= d) v = ps[tid - d];
        __syncthreads();
        if (tid >= d) ps[tid] += v;
        __syncthreads();
    }
    int excl = ps[tid] - s;
    if (3*tid   < n) off[3*tid]   = excl;
    if (3*tid+1 < n) off[3*tid+1] = excl + a;
    if (3*tid+2 < n) off[3*tid+2] = excl + a + b;
    if (tid == 1023) off[n] = ps[1023];
}

__global__ void k_fill(const int* ei, int E, const int* off_s, const int* off_d,
                       int* cur_s, int* cur_d, int* col_s, int* col_d) {
    int e = blockIdx.x * blockDim.x + threadIdx.x;
    if (e < E) {
        int s = ei[e], t = ei[E + e];
        int p = atomicAdd(&cur_s[s], 1); col_s[off_s[s] + p] = t;
        int q = atomicAdd(&cur_d[t], 1); col_d[off_d[t] + q] = s;
    }
}

// ---------------- fp32 SGEMM 128x128 tile, BK=16, 8x8 microtile ----------------
// AM: 0 plain; 1 gather-gate; 3 add-scatter. BS: 1 => B row scaled by rsqrt(rs[k]+2).
template<int AM, int BS>
__global__ __launch_bounds__(256) void k_gemm128(
    const float* __restrict__ A, int lda,
    const float* __restrict__ B, int ldb,
    float* __restrict__ C, int ldc,
    int M, int N, int K, int Kc,
    const float* __restrict__ rs,
    const int* __restrict__ aperm, const float* __restrict__ avals,
    const float* __restrict__ adelta, const int* __restrict__ ainv)
{
    __shared__ float As[16][132];
    __shared__ float Bs[16][128];
    int bm = blockIdx.y * 128, bn = blockIdx.x * 128;
    int kstart = blockIdx.z * Kc;
    int kend = min(K, kstart + Kc);
    if (gridDim.z > 1) C += (size_t)blockIdx.z * M * ldc;
    int tid = threadIdx.x, tx = tid & 15, ty = tid >> 4;
    float acc[8][8] = {};
    for (int k0 = kstart; k0 < kend; k0 += 16) {
        #pragma unroll
        for (int l = 0; l < 2; l++) {
            int idx = tid + l * 256;
            int m = idx >> 2, k4 = idx & 3;
            int gm = bm + m, gk = k0 + k4 * 4;
            float4 v = make_float4(0.f, 0.f, 0.f, 0.f);
            if (gm < M) {
                const float* src;
                float scale = 1.0f;
                if (AM == 1)      { scale = avals[gm]; src = A + (size_t)aperm[gm] * lda; }
                else               src = A + (size_t)gm * lda;
                if (gk + 3 < kend) v = *(const float4*)(src + gk);
                else {
                    float* vv = &v.x;
                    #pragma unroll
                    for (int q = 0; q < 4; q++) if (gk + q < kend) vv[q] = src[gk + q];
                }
                if (AM == 1) { v.x *= scale; v.y *= scale; v.z *= scale; v.w *= scale; }
                if (AM == 3) {
                    int r = ainv[gm];
                    if (r >= 0) {
                        const float* ds = adelta + (size_t)r * lda;
                        if (gk + 3 < kend) {
                            float4 d4 = *(const float4*)(ds + gk);
                            v.x += d4.x; v.y += d4.y; v.z += d4.z; v.w += d4.w;
                        } else {
                            float* vv = &v.x;
                            #pragma unroll
                            for (int q = 0; q < 4; q++) if (gk + q < kend) vv[q] += ds[gk + q];
                        }
                    }
                }
            }
            As[k4*4+0][m] = v.x; As[k4*4+1][m] = v.y;
            As[k4*4+2][m] = v.z; As[k4*4+3][m] = v.w;
        }
        #pragma unroll
        for (int l = 0; l < 2; l++) {
            int idx = tid + l * 256;
            int kk = idx >> 5, n4 = idx & 31;
            int gk = k0 + kk, gn = bn + n4 * 4;
            float4 v = make_float4(0.f, 0.f, 0.f, 0.f);
            if (gk < kend && gn < N) {
                if (gn + 3 < N) v = *(const float4*)(B + (size_t)gk * ldb + gn);
                else {
                    float* vv = &v.x;
                    #pragma unroll
                    for (int q = 0; q < 4; q++) if (gn + q < N) vv[q] = B[(size_t)gk * ldb + gn + q];
                }
                if (BS == 1) {
                    float sc = rsqrtf(rs[gk] + 2.0f);
                    v.x *= sc; v.y *= sc; v.z *= sc; v.w *= sc;
                }
            }
            *(float4*)&Bs[kk][n4*4] = v;
        }
        __syncthreads();
        #pragma unroll
        for (int kk = 0; kk < 16; kk++) {
            float a[8], b[8];
            *(float4*)&a[0] = *(const float4*)&As[kk][ty*8];
            *(float4*)&a[4] = *(const float4*)&As[kk][ty*8+4];
            *(float4*)&b[0] = *(const float4*)&Bs[kk][tx*8];
            *(float4*)&b[4] = *(const float4*)&Bs[kk][tx*8+4];
            #pragma unroll
            for (int r = 0; r < 8; r++)
                #pragma unroll
                for (int c = 0; c < 8; c++)
                    acc[r][c] += a[r] * b[c];
        }
        __syncthreads();
    }
    #pragma unroll
    for (int r = 0; r < 8; r++) {
        int gm = bm + ty*8 + r;
        if (gm >= M) continue;
        #pragma unroll
        for (int c = 0; c < 8; c++) {
            int gn = bn + tx*8 + c;
            if (gn < N) C[(size_t)gm * ldc + gn] = acc[r][c];
        }
    }
}

// ---------------- bf16 WMMA GEMM: 128x128 tile, 8 warps of 64x32 ----------------
template<int SPLIT>
__global__ __launch_bounds__(256) void k_wgemm(
    const __nv_bfloat16* __restrict__ A, int lda,
    const __nv_bfloat16* __restrict__ Bh, const __nv_bfloat16* __restrict__ Bl, int ldb,
    float* __restrict__ C, int ldc, int Kc, size_t zstride)
{
    __shared__ __nv_bfloat16 As[128][48];
    __shared__ __nv_bfloat16 Bsh[32][136];
    __shared__ __nv_bfloat16 Bsl[SPLIT ? 32 : 1][SPLIT ? 136 : 8];
    int bm = blockIdx.y * 128, bn = blockIdx.x * 128;
    int k0beg = blockIdx.z * Kc;
    C += (size_t)blockIdx.z * zstride;
    int tid = threadIdx.x;
    int wid = tid >> 5;
    int wm = wid >> 2, wn = wid & 3;

    wmma::fragment<wmma::accumulator,16,16,16,float> cf[4][2];
    #pragma unroll
    for (int i = 0; i < 4; i++)
        #pragma unroll
        for (int j = 0; j < 2; j++)
            wmma::fill_fragment(cf[i][j], 0.0f);

    for (int k0 = k0beg; k0 < k0beg + Kc; k0 += 32) {
        #pragma unroll
        for (int l = 0; l < 2; l++) {
            int idx = tid + l * 256;
            int m = idx >> 2, q = idx & 3;
            *(uint4*)&As[m][q*8] = *(const uint4*)(A + (size_t)(bm + m)*lda + k0 + q*8);
        }
        #pragma unroll
        for (int l = 0; l < 2; l++) {
            int idx = tid + l * 256;
            int kk = idx >> 4, q = idx & 15;
            *(uint4*)&Bsh[kk][q*8] = *(const uint4*)(Bh + (size_t)(k0 + kk)*ldb + bn + q*8);
        }
        if (SPLIT) {
            #pragma unroll
            for (int l = 0; l < 2; l++) {
                int idx = tid + l * 256;
                int kk = idx >> 4, q = idx & 15;
                *(uint4*)&Bsl[kk][q*8] = *(const uint4*)(Bl + (size_t)(k0 + kk)*ldb + bn + q*8);
            }
        }
        __syncthreads();
        #pragma unroll
        for (int ks = 0; ks < 2; ks++) {
            wmma::fragment<wmma::matrix_a,16,16,16,__nv_bfloat16,wmma::row_major> af[4];
            #pragma unroll
            for (int i = 0; i < 4; i++)
                wmma::load_matrix_sync(af[i], &As[wm*64 + i*16][ks*16], 48);
            wmma::fragment<wmma::matrix_b,16,16,16,__nv_bfloat16,wmma::row_major> bf[2];
            #pragma unroll
            for (int j = 0; j < 2; j++)
                wmma::load_matrix_sync(bf[j], &Bsh[ks*16][wn*32 + j*16], 136);
            #pragma unroll
            for (int i = 0; i < 4; i++)
                #pragma unroll
                for (int j = 0; j < 2; j++)
                    wmma::mma_sync(cf[i][j], af[i], bf[j], cf[i][j]);
            if (SPLIT) {
                #pragma unroll
                for (int j = 0; j < 2; j++)
                    wmma::load_matrix_sync(bf[j], &Bsl[ks*16][wn*32 + j*16], 136);
                #pragma unroll
                for (int i = 0; i < 4; i++)
                    #pragma unroll
                    for (int j = 0; j < 2; j++)
                        wmma::mma_sync(cf[i][j], af[i], bf[j], cf[i][j]);
            }
        }
        __syncthreads();
    }
    #pragma unroll
    for (int i = 0; i < 4; i++)
        #pragma unroll
        for (int j = 0; j < 2; j++)
            wmma::store_matrix_sync(C + (size_t)(bm + wm*64 + i*16)*ldc + bn + wn*32 + j*16,
                                    cf[i][j], ldc, wmma::mem_row_major);
}

// ---------------- bf16 conversions ----------------
// A1 -> bf16 (padded), fused rowsum -> rs1
__global__ void k_conv_A1(const float* __restrict__ A1, __nv_bfloat16* __restrict__ dst,
                          float* __restrict__ rs1) {
    __shared__ float sh[256];
    int r = blockIdx.x;  // [0,1536)
    float rsum = 0.0f;
    for (int c = threadIdx.x; c < KP1; c += 256) {
        float v = (r < KK1 && c < KK1) ? A1[(size_t)r*KK1 + c] : 0.0f;
        rsum += v;
        dst[(size_t)r*KP1 + c] = __float2bfloat16(v);
    }
    sh[threadIdx.x] = rsum;
    __syncthreads();
    for (int st = 128; st > 0; st >>= 1) {
        if (threadIdx.x < st) sh[threadIdx.x] += sh[threadIdx.x + st];
        __syncthreads();
    }
    if (threadIdx.x == 0 && r < KK1) rs1[r] = sh[0];
}

__global__ void k_conv_ar(const float* __restrict__ A1, const int* __restrict__ perm,
                          __nv_bfloat16* __restrict__ dst) {
    int r = blockIdx.x;  // [0,768)
    int pr = (r < KK2) ? perm[r] : -1;
    for (int c = threadIdx.x; c < KP1; c += 256) {
        float v = 0.0f;
        if (pr >= 0 && c < KK1) v = A1[(size_t)pr*KK1 + c] + (c == pr ? 1.0f : 0.0f);
        dst[(size_t)r*KP1 + c] = __float2bfloat16(v);
    }
}

__global__ void k_conv_bc(const float* __restrict__ A1, const int* __restrict__ perm,
                          __nv_bfloat16* __restrict__ dst) {
    int k = blockIdx.x;  // [0,1536)
    for (int b = threadIdx.x; b < MP2; b += 256) {
        float v = 0.0f;
        if (k < KK1 && b < KK2) {
            int pb = perm[b];
            v = A1[(size_t)k*KK1 + pb] + (k == pb ? 1.0f : 0.0f);
        }
        dst[(size_t)k*MP2 + b] = __float2bfloat16(v);
    }
}

// sum 4 split-K partials -> XW fp32; if HILO also write dis-scaled hi/lo bf16 (padded rows)
template<int HILO>
__global__ void k_xw_finish(const float* __restrict__ part, size_t zstride, int n,
                            const float* __restrict__ rs, float* __restrict__ XW,
                            __nv_bfloat16* __restrict__ hi, __nv_bfloat16* __restrict__ lo) {
    int r = blockIdx.x;
    int c = threadIdx.x;  // 128
    if (r < n) {
        size_t base = (size_t)r * HID + c;
        float a = part[base] + part[base + zstride] + part[base + 2*zstride] + part[base + 3*zstride];
        XW[base] = a;
        if (HILO) {
            float d = rsqrtf(rs[r] + 2.0f);
            float v = a * d;
            __nv_bfloat16 h = __float2bfloat16(v);
            hi[base] = h;
            lo[base] = __float2bfloat16(v - __bfloat162float(h));
        }
    } else if (HILO) {
        size_t base = (size_t)r * HID + c;
        hi[base] = __float2bfloat16(0.0f);
        lo[base] = __float2bfloat16(0.0f);
    }
}

// ---------------- sparse GCN on A0, fused pool1 score ----------------
__global__ void k_gcn0(const float* __restrict__ XW, const float* __restrict__ b,
                       const int* __restrict__ cnt, const int* __restrict__ off,
                       const int* __restrict__ col, float* __restrict__ out,
                       const float* __restrict__ p, float* __restrict__ score,
                       int* __restrict__ inv) {
    __shared__ int   snb[128];
    __shared__ float sds[128];
    __shared__ float sh[128];
    __shared__ float sp[128];
    int i = blockIdx.x, c = threadIdx.x;
    float di = rsqrtf((float)cnt[i] + 2.0f);
    float acc = 2.0f * di * XW[(size_t)i*HID + c];
    int s0 = off[i], s1 = off[i+1];
    for (int base = s0; base < s1; base += 128) {
        int e = base + c;
        if (e < s1) { int s = col[e]; snb[c] = s; sds[c] = rsqrtf((float)cnt[s] + 2.0f); }
        __syncthreads();
        int lim = min(128, s1 - base);
        for (int t = 0; t < lim; t++)
            acc += sds[t] * XW[(size_t)snb[t]*HID + c];
        __syncthreads();
    }
    float val = tanhf(di * acc + b[c]);
    out[(size_t)i*HID + c] = val;
    float pc = p[c];
    sh[c] = val * pc;
    sp[c] = pc * pc;
    __syncthreads();
    for (int st = 64; st > 0; st >>= 1) {
        if (c < st) { sh[c] += sh[c+st]; sp[c] += sp[c+st]; }
        __syncthreads();
    }
    if (c == 0) { score[i] = tanhf(sh[0] * rsqrtf(sp[0])); inv[i] = -1; }
}

__global__ void k_topk(const float* __restrict__ s, int n, int K,
                       int* __restrict__ perm, float* __restrict__ vals,
                       int* __restrict__ inv) {
    __shared__ float sh[256];
    int i = blockIdx.x * blockDim.x + threadIdx.x;
    float si = (i < n) ? s[i] : -1e30f;
    int rank = 0;
    for (int j0 = 0; j0 < n; j0 += 256) {
        int j = j0 + threadIdx.x;
        sh[threadIdx.x] = (j < n) ? s[j] : -1e30f;
        __syncthreads();
        const float4* sh4 = (const float4*)sh;
        #pragma unroll 4
        for (int t = 0; t < 64; t++) {
            float4 v = sh4[t];
            int jj = j0 + 4*t;
            rank += (v.x > si) || (v.x == si && jj   < i);
            rank += (v.y > si) || (v.y == si && jj+1 < i);
            rank += (v.z > si) || (v.z == si && jj+2 < i);
            rank += (v.w > si) || (v.w == si && jj+3 < i);
        }
        __syncthreads();
    }
    if (i < n && rank < K) { perm[rank] = i; vals[rank] = si; inv[i] = rank; }
}

// ---------------- sparse augment(A0) into A1 submatrix ----------------
__global__ void k_aug_pairs(const int* __restrict__ off_s, const int* __restrict__ col_s,
                            const int* __restrict__ off_d, const int* __restrict__ col_d,
                            const int* __restrict__ inv, float* __restrict__ A1) {
    int k = blockIdx.x;
    int os = off_s[k], ns = off_s[k+1] - os;
    int od = off_d[k], nd = off_d[k+1] - od;
    int tot = ns * nd;
    for (int t = threadIdx.x; t < tot; t += 128) {
        int i = col_s[os + t / nd];
        int j = col_d[od + t % nd];
        if (i != k && j != k && i != j) {
            int r = inv[i], c = inv[j];
            if (r >= 0 && c >= 0) atomicAdd(&A1[(size_t)r*KK1 + c], 1.0f);
        }
    }
}

__global__ void k_aug_edges(const int* ei, int E, const int* __restrict__ inv,
                            float* __restrict__ A1) {
    int e = blockIdx.x * blockDim.x + threadIdx.x;
    if (e < E) {
        int s = ei[e], t = ei[E + e];
        if (s != t) {
            int r = inv[t], c = inv[s];
            if (r >= 0 && c >= 0) atomicAdd(&A1[(size_t)r*KK1 + c], 2.0f);
        }
    }
}

// sum 4 partials, zero diag, rowsum -> rs2, store A2 (ld A2LD)
__global__ void k_a2_finish(const float* __restrict__ part, float* __restrict__ A2,
                            float* __restrict__ rs2) {
    __shared__ float sh[256];
    int i = blockIdx.x;
    float rsum = 0.0f;
    for (int j = threadIdx.x; j < KK2; j += 256) {
        float s = 0.0f;
        #pragma unroll
        for (int zz = 0; zz < 4; zz++)
            s += part[((size_t)zz*MP2 + i)*MP2 + j];
        if (j == i) s = 0.0f;
        A2[(size_t)i*A2LD + j] = s;
        rsum += s;
    }
    sh[threadIdx.x] = rsum;
    __syncthreads();
    for (int st = 128; st > 0; st >>= 1) {
        if (threadIdx.x < st) sh[threadIdx.x] += sh[threadIdx.x + st];
        __syncthreads();
    }
    if (threadIdx.x == 0) rs2[i] = sh[0];
}

// row-per-block epilogue: out = tanh(d*sumpart + 2*d^2*XW + bias); optional fused score
template<int SCORE>
__global__ void k_agg_epi(const float* __restrict__ part, int S, size_t zstride,
                          const float* __restrict__ XW, const float* __restrict__ bias,
                          const float* __restrict__ rs, float* __restrict__ out,
                          const float* __restrict__ p, float* __restrict__ score,
                          int* __restrict__ inv) {
    __shared__ float sh[128];
    __shared__ float sp[128];
    int i = blockIdx.x, c = threadIdx.x;
    size_t base = (size_t)i * HID + c;
    float a = part[base];
    #pragma unroll 4
    for (int zz = 1; zz < S; zz++) a += part[base + zz*zstride];
    float d = rsqrtf(rs[i] + 2.0f);
    float val = tanhf(d * a + 2.0f * d * d * XW[base] + bias[c]);
    out[base] = val;
    if (SCORE) {
        float pc = p[c];
        sh[c] = val * pc;
        sp[c] = pc * pc;
        __syncthreads();
        for (int st = 64; st > 0; st >>= 1) {
            if (c < st) { sh[c] += sh[c+st]; sp[c] += sp[c+st]; }
            __syncthreads();
        }
        if (c == 0) { score[i] = tanhf(sh[0] * rsqrtf(sp[0])); inv[i] = -1; }
    }
}

// XW3 = (h0 + scatter(u1b, inv1)) @ Wu1  (N=3), warp per row
__global__ void k_xw3(const float* __restrict__ h0, const float* __restrict__ u1b,
                      const int* __restrict__ inv1, const float* __restrict__ W,
                      float* __restrict__ XW3) {
    int w = (blockIdx.x * blockDim.x + threadIdx.x) >> 5;
    int lane = threadIdx.x & 31;
    if (w >= N0) return;
    int r = inv1[w];
    float a0 = 0.f, a1 = 0.f, a2 = 0.f;
    #pragma unroll
    for (int q = 0; q < 4; q++) {
        int k = lane + q * 32;
        float v = h0[(size_t)w*HID + k];
        if (r >= 0) v += u1b[(size_t)r*HID + k];
        a0 += v * W[k*3+0];
        a1 += v * W[k*3+1];
        a2 += v * W[k*3+2];
    }
    #pragma unroll
    for (int off = 16; off > 0; off >>= 1) {
        a0 += __shfl_down_sync(0xffffffffu, a0, off);
        a1 += __shfl_down_sync(0xffffffffu, a1, off);
        a2 += __shfl_down_sync(0xffffffffu, a2, off);
    }
    if (lane == 0) { XW3[w*3+0] = a0; XW3[w*3+1] = a1; XW3[w*3+2] = a2; }
}

// final sparse GCN (OUTC=3) + noise
__global__ void k_gcn_final(const float* __restrict__ XW3, const float* __restrict__ b,
                            const int* __restrict__ cnt, const int* __restrict__ off,
                            const int* __restrict__ col, const float* __restrict__ z,
                            float* __restrict__ out) {
    int i = blockIdx.x * blockDim.x + threadIdx.x;
    if (i >= N0) return;
    float di = rsqrtf((float)cnt[i] + 2.0f);
    float a0 = 2.0f * di * XW3[i*3+0];
    float a1 = 2.0f * di * XW3[i*3+1];
    float a2 = 2.0f * di * XW3[i*3+2];
    int s0 = off[i], s1 = off[i+1];
    for (int e = s0; e < s1; e++) {
        int s = col[e];
        float ds = rsqrtf((float)cnt[s] + 2.0f);
        a0 += ds * XW3[s*3+0];
        a1 += ds * XW3[s*3+1];
        a2 += ds * XW3[s*3+2];
    }
    out[i*3+0] = di*a0 + b[0] + 0.1f*z[i*3+0];
    out[i*3+1] = di*a1 + b[1] + 0.1f*z[i*3+1];
    out[i*3+2] = di*a2 + b[2] + 0.1f*z[i*3+2];
}

// ---------------- launch ----------------
extern "C" void kernel_launch(void* const* d_in, const int* in_sizes, int n_in,
                              void* d_out, int out_size) {
    const float* x   = (const float*)d_in[0];
    const float* z   = (const float*)d_in[1];
    const float* W0  = (const float*)d_in[2];
    const float* b0  = (const float*)d_in[3];
    const float* W1  = (const float*)d_in[4];
    const float* b1  = (const float*)d_in[5];
    const float* W2  = (const float*)d_in[6];
    const float* b2  = (const float*)d_in[7];
    const float* p1  = (const float*)d_in[8];
    const float* p2  = (const float*)d_in[9];
    const float* Wu0 = (const float*)d_in[10];
    const float* bu0 = (const float*)d_in[11];
    const float* Wu1 = (const float*)d_in[12];
    const float* bu1 = (const float*)d_in[13];
    const int*   ei  = (const int*)d_in[14];
    int E = in_sizes[14] / 2;
    if (E > EMAX) E = EMAX;

    float* F; cudaGetSymbolAddress((void**)&F, g_f);
    int*   I; cudaGetSymbolAddress((void**)&I, g_i);
    __nv_bfloat16* H; cudaGetSymbolAddress((void**)&H, g_h);
    float* out = (float*)d_out;

    float *A1 = F+O_A1, *rs1 = F+O_RS1, *rs2 = F+O_RS2;
    float *A2 = F+O_A2, *part = F+O_PART;
    float *XW0 = F+O_XW0, *h0 = F+O_H0, *XW = F+O_XW;
    float *h1 = F+O_H1, *u1b = F+O_U1B, *h2 = F+O_H2, *XW3 = F+O_XW3;
    float *score = F+O_SC, *vals1 = F+O_VL1, *vals2 = F+O_VL2;
    __nv_bfloat16 *A1bf = H+HB_A1, *Ar = H+HB_AR, *Bc = H+HB_BC;
    __nv_bfloat16 *XWh = H+HB_XH, *XWl = H+HB_XL;
    int *perm1 = I+IO_P1, *perm2 = I+IO_P2, *inv1 = I+IO_INV1, *inv2 = I+IO_INV2;

    cudaMemsetAsync(A1, 0, ((size_t)KK1*KK1 + KK1 + 768)*sizeof(float));
    cudaMemsetAsync(I, 0, 12000*sizeof(int));
    cudaMemsetAsync(d_out, 0, (size_t)out_size*sizeof(float));

    // CSR
    k_count<<<CDIV(E,256),256>>>(ei, E, I+IO_CNTS, I+IO_CNTD);
    k_scan2<<<2,1024>>>(I+IO_CNTS, I+IO_OFFS, I+IO_CNTD, I+IO_OFFD, N0);
    k_fill<<<CDIV(E,256),256>>>(ei, E, I+IO_OFFS, I+IO_OFFD, I+IO_CURS, I+IO_CURD, I+IO_COLS, I+IO_COLD);

    // down0 (+ fused pool1 score)
    k_gemm128<0,0><<<dim3(1, CDIV(N0,128), 1),256>>>(x, INC, W0, HID, XW0, HID,
        N0, HID, INC, INC, 0, 0, 0, 0, 0);
    k_gcn0<<<N0,128>>>(XW0, b0, I+IO_CNTD, I+IO_OFFD, I+IO_COLD, h0, p1, score, inv1);
    k_topk<<<CDIV(N0,256),256>>>(score, N0, KK1, perm1, vals1, inv1);

    // augment(A0) -> A1 ; bf16 copy + rowsum
    k_aug_pairs<<<N0,128>>>(I+IO_OFFS, I+IO_COLS, I+IO_OFFD, I+IO_COLD, inv1, A1);
    k_aug_edges<<<CDIV(E,256),256>>>(ei, E, inv1, A1);
    k_conv_A1<<<KP1,256>>>(A1, A1bf, rs1);

    // down1: XW = gate(h0)@W1 (split-K) ; finish(+hilo) ; bf16 agg ; epi(+pool2 score) -> h1
    k_gemm128<1,0><<<dim3(1, CDIV(KK1,128), 4),256>>>(h0, HID, W1, HID, part, HID,
        KK1, HID, HID, 32, 0, perm1, vals1, 0, 0);
    k_xw_finish<1><<<KP1,128>>>(part, (size_t)KK1*HID, KK1, rs1, XW, XWh, XWl);
    k_wgemm<1><<<dim3(1, 12, 12),256>>>(A1bf, KP1, XWh, XWl, HID, part, HID, 128, (size_t)KP1*HID);
    k_agg_epi<1><<<KK1,128>>>(part, 12, (size_t)KP1*HID, XW, b1, rs1, h1, p2, score, inv2);
    k_topk<<<CDIV(KK1,256),256>>>(score, KK1, KK2, perm2, vals2, inv2);

    // A2 = (A1+I)[perm2,:] @ (A1+I)[:,perm2]  — exact bf16 tensor-core product
    k_conv_ar<<<MP2,256>>>(A1, perm2, Ar);
    k_conv_bc<<<KP1,256>>>(A1, perm2, Bc);
    k_wgemm<0><<<dim3(6, 6, 4),256>>>(Ar, KP1, Bc, Bc, MP2, part, MP2, 384, (size_t)MP2*MP2);
    k_a2_finish<<<KK2,256>>>(part, A2, rs2);

    // down2: XW = gate(h1)@W2 (split-K) ; finish ; fp32 split-K agg ; epi -> h2
    k_gemm128<1,0><<<dim3(1, CDIV(KK2,128), 4),256>>>(h1, HID, W2, HID, part, HID,
        KK2, HID, HID, 32, 0, perm2, vals2, 0, 0);
    k_xw_finish<0><<<KK2,128>>>(part, (size_t)KK2*HID, KK2, 0, XW, 0, 0);
    k_gemm128<0,1><<<dim3(1, CDIV(KK2,128), 24),256>>>(A2, A2LD, XW, HID, part, HID,
        KK2, HID, KK2, 32, rs2, 0, 0, 0, 0);
    k_agg_epi<0><<<KK2,128>>>(part, 24, (size_t)KK2*HID, XW, b2, rs2, h2, 0, 0, 0);

    // up0: XW = (h1 + scatter(h2,inv2))@Wu0 (split-K) ; finish(+hilo) ; bf16 agg ; epi -> u1b
    k_gemm128<3,0><<<dim3(1, CDIV(KK1,128), 4),256>>>(h1, HID, Wu0, HID, part, HID,
        KK1, HID, HID, 32, 0, 0, 0, h2, inv2);
    k_xw_finish<1><<<KP1,128>>>(part, (size_t)KK1*HID, KK1, rs1, XW, XWh, XWl);
    k_wgemm<1><<<dim3(1, 12, 12),256>>>(A1bf, KP1, XWh, XWl, HID, part, HID, 128, (size_t)KP1*HID);
    k_agg_epi<0><<<KK1,128>>>(part, 12, (size_t)KP1*HID, XW, bu0, rs1, u1b, 0, 0, 0);

    // up1: XW3 = (h0 + scatter(u1b,inv1))@Wu1 ; final sparse GCN + noise
    k_xw3<<<CDIV(N0*32,256),256>>>(h0, u1b, inv1, Wu1, XW3);
    k_gcn_final<<<CDIV(N0,128),128>>>(XW3, bu1, I+IO_CNTD, I+IO_OFFD, I+IO_COLD, z, out);
}

// round 15
// speedup vs baseline: 3.9675x; 1.0951x over previous
#include <cuda_runtime.h>
#include <cuda_bf16.h>
#include <mma.h>
#include <math.h>

using namespace nvcuda;

#define N0   3000
#define KK1  1500
#define KK2  750
#define A2LD 752
#define HID  128
#define INC  32
#define OUTC 3
#define EMAX 48000

#define KP1  1536
#define MP2  768

#define CDIV(a,b) (((a)+(b)-1)/(b))

// ---------------- float scratch ----------------
static const size_t O_A1   = 0;                                  // KK1*KK1
static const size_t O_RS1  = O_A1  + (size_t)KK1*KK1;            // KK1
static const size_t O_RS2  = O_RS1 + KK1;                        // 768
static const size_t O_A2   = O_RS2 + 768;                        // KK2*A2LD
static const size_t O_PART = O_A2  + (size_t)KK2*A2LD;           // 2,359,296
static const size_t O_XW0  = O_PART+ (size_t)2359296;
static const size_t O_H0   = O_XW0 + (size_t)N0*HID;
static const size_t O_XW   = O_H0  + (size_t)N0*HID;
static const size_t O_H1   = O_XW  + (size_t)KK1*HID;
static const size_t O_U1B  = O_H1  + (size_t)KK1*HID;
static const size_t O_H2   = O_U1B + (size_t)KK1*HID;
static const size_t O_XW3  = O_H2  + (size_t)KK2*HID;
static const size_t O_SC   = O_XW3 + (size_t)N0*4;
static const size_t O_VL1  = O_SC  + N0;
static const size_t O_VL2  = O_VL1 + 1536;
static const size_t FTOT   = O_VL2 + 768;

__device__ float g_f[FTOT];

// ---------------- bf16 scratch ----------------
static const size_t HB_A1 = 0;                                   // KP1*KP1
static const size_t HB_AR = HB_A1 + (size_t)KP1*KP1;             // MP2*KP1
static const size_t HB_BC = HB_AR + (size_t)MP2*KP1;             // KP1*MP2
static const size_t HB_XH = HB_BC + (size_t)KP1*MP2;             // KP1*HID
static const size_t HB_XL = HB_XH + (size_t)KP1*HID;             // KP1*HID
static const size_t HTOT  = HB_XL + (size_t)KP1*HID;

__device__ __nv_bfloat16 g_h[HTOT];

// ---------------- int scratch ----------------
static const size_t IO_CNTS = 0;
static const size_t IO_CNTD = 3000;
static const size_t IO_CURS = 6000;
static const size_t IO_CURD = 9000;
static const size_t IO_OFFS = 12000;
static const size_t IO_OFFD = 15008;
static const size_t IO_COLS = 18016;
static const size_t IO_COLD = IO_COLS + EMAX;
static const size_t IO_P1   = IO_COLD + EMAX;
static const size_t IO_P2   = IO_P1 + 1536;
static const size_t IO_INV1 = IO_P2 + 768;
static const size_t IO_INV2 = IO_INV1 + 3072;
static const size_t ITOT    = IO_INV2 + 1536;

__device__ int g_i[ITOT];

// ---------------- CSR build ----------------
__global__ void k_count(const int* ei, int E, int* cnt_s, int* cnt_d) {
    int e = blockIdx.x * blockDim.x + threadIdx.x;
    if (e < E) {
        atomicAdd(&cnt_s[ei[e]], 1);
        atomicAdd(&cnt_d[ei[E + e]], 1);
    }
}

__global__ void k_scan2(const int* cnt_s, int* off_s, const int* cnt_d, int* off_d, int n) {
    __shared__ int sh[3072];
    __shared__ int ps[1024];
    const int* cnt = blockIdx.x ? cnt_d : cnt_s;
    int* off       = blockIdx.x ? off_d : off_s;
    int tid = threadIdx.x;
    for (int i = tid; i < 3072; i += 1024) sh[i] = (i < n) ? cnt[i] : 0;
    __syncthreads();
    int a = sh[3*tid], b = sh[3*tid+1], c = sh[3*tid+2];
    int s = a + b + c;
    ps[tid] = s;
    __syncthreads();
    for (int d = 1; d < 1024; d <<= 1) {
        int v = 0;
        if (tid >= d) v = ps[tid - d];
        __syncthreads();
        if (tid >= d) ps[tid] += v;
        __syncthreads();
    }
    int excl = ps[tid] - s;
    if (3*tid   < n) off[3*tid]   = excl;
    if (3*tid+1 < n) off[3*tid+1] = excl + a;
    if (3*tid+2 < n) off[3*tid+2] = excl + a + b;
    if (tid == 1023) off[n] = ps[1023];
}

__global__ void k_fill(const int* ei, int E, const int* off_s, const int* off_d,
                       int* cur_s, int* cur_d, int* col_s, int* col_d) {
    int e = blockIdx.x * blockDim.x + threadIdx.x;
    if (e < E) {
        int s = ei[e], t = ei[E + e];
        int p = atomicAdd(&cur_s[s], 1); col_s[off_s[s] + p] = t;
        int q = atomicAdd(&cur_d[t], 1); col_d[off_d[t] + q] = s;
    }
}

// ---------------- down0 GEMM: XW0 = x[3000,32] @ W0[32,128], 8 rows/block ----------------
__global__ __launch_bounds__(256) void k_xw0(const float* __restrict__ x,
                                             const float* __restrict__ W0,
                                             float* __restrict__ XW0) {
    __shared__ float ws[INC * HID];   // 16 KB
    __shared__ float xs[8][INC];
    int tid = threadIdx.x;
    int r0 = blockIdx.x * 8;
    #pragma unroll
    for (int l = 0; l < 16; l++) ws[tid + l * 256] = W0[tid + l * 256];
    if (tid < 8 * INC) xs[tid >> 5][tid & 31] = x[(size_t)r0 * INC + tid];
    __syncthreads();
    int c = tid & 127, g = tid >> 7;   // g in {0,1}
    float acc[4] = {};
    #pragma unroll
    for (int k = 0; k < INC; k++) {
        float wv = ws[k * HID + c];
        #pragma unroll
        for (int j = 0; j < 4; j++)
            acc[j] += xs[g + j * 2][k] * wv;
    }
    #pragma unroll
    for (int j = 0; j < 4; j++)
        XW0[(size_t)(r0 + g + j * 2) * HID + c] = acc[j];
}

// ---------------- fp32 SGEMM 128x128 tile, BK=16, 8x8 microtile ----------------
// AM: 0 plain; 1 gather-gate; 3 add-scatter. BS: 1 => B row scaled by rsqrt(rs[k]+2).
template<int AM, int BS>
__global__ __launch_bounds__(256) void k_gemm128(
    const float* __restrict__ A, int lda,
    const float* __restrict__ B, int ldb,
    float* __restrict__ C, int ldc,
    int M, int N, int K, int Kc,
    const float* __restrict__ rs,
    const int* __restrict__ aperm, const float* __restrict__ avals,
    const float* __restrict__ adelta, const int* __restrict__ ainv)
{
    __shared__ float As[16][132];
    __shared__ float Bs[16][128];
    int bm = blockIdx.y * 128, bn = blockIdx.x * 128;
    int kstart = blockIdx.z * Kc;
    int kend = min(K, kstart + Kc);
    if (gridDim.z > 1) C += (size_t)blockIdx.z * M * ldc;
    int tid = threadIdx.x, tx = tid & 15, ty = tid >> 4;
    float acc[8][8] = {};
    for (int k0 = kstart; k0 < kend; k0 += 16) {
        #pragma unroll
        for (int l = 0; l < 2; l++) {
            int idx = tid + l * 256;
            int m = idx >> 2, k4 = idx & 3;
            int gm = bm + m, gk = k0 + k4 * 4;
            float4 v = make_float4(0.f, 0.f, 0.f, 0.f);
            if (gm < M) {
                const float* src;
                float scale = 1.0f;
                if (AM == 1)      { scale = avals[gm]; src = A + (size_t)aperm[gm] * lda; }
                else               src = A + (size_t)gm * lda;
                if (gk + 3 < kend) v = *(const float4*)(src + gk);
                else {
                    float* vv = &v.x;
                    #pragma unroll
                    for (int q = 0; q < 4; q++) if (gk + q < kend) vv[q] = src[gk + q];
                }
                if (AM == 1) { v.x *= scale; v.y *= scale; v.z *= scale; v.w *= scale; }
                if (AM == 3) {
                    int r = ainv[gm];
                    if (r >= 0) {
                        const float* ds = adelta + (size_t)r * lda;
                        if (gk + 3 < kend) {
                            float4 d4 = *(const float4*)(ds + gk);
                            v.x += d4.x; v.y += d4.y; v.z += d4.z; v.w += d4.w;
                        } else {
                            float* vv = &v.x;
                            #pragma unroll
                            for (int q = 0; q < 4; q++) if (gk + q < kend) vv[q] += ds[gk + q];
                        }
                    }
                }
            }
            As[k4*4+0][m] = v.x; As[k4*4+1][m] = v.y;
            As[k4*4+2][m] = v.z; As[k4*4+3][m] = v.w;
        }
        #pragma unroll
        for (int l = 0; l < 2; l++) {
            int idx = tid + l * 256;
            int kk = idx >> 5, n4 = idx & 31;
            int gk = k0 + kk, gn = bn + n4 * 4;
            float4 v = make_float4(0.f, 0.f, 0.f, 0.f);
            if (gk < kend && gn < N) {
                if (gn + 3 < N) v = *(const float4*)(B + (size_t)gk * ldb + gn);
                else {
                    float* vv = &v.x;
                    #pragma unroll
                    for (int q = 0; q < 4; q++) if (gn + q < N) vv[q] = B[(size_t)gk * ldb + gn + q];
                }
                if (BS == 1) {
                    float sc = rsqrtf(rs[gk] + 2.0f);
                    v.x *= sc; v.y *= sc; v.z *= sc; v.w *= sc;
                }
            }
            *(float4*)&Bs[kk][n4*4] = v;
        }
        __syncthreads();
        #pragma unroll
        for (int kk = 0; kk < 16; kk++) {
            float a[8], b[8];
            *(float4*)&a[0] = *(const float4*)&As[kk][ty*8];
            *(float4*)&a[4] = *(const float4*)&As[kk][ty*8+4];
            *(float4*)&b[0] = *(const float4*)&Bs[kk][tx*8];
            *(float4*)&b[4] = *(const float4*)&Bs[kk][tx*8+4];
            #pragma unroll
            for (int r = 0; r < 8; r++)
                #pragma unroll
                for (int c = 0; c < 8; c++)
                    acc[r][c] += a[r] * b[c];
        }
        __syncthreads();
    }
    #pragma unroll
    for (int r = 0; r < 8; r++) {
        int gm = bm + ty*8 + r;
        if (gm >= M) continue;
        #pragma unroll
        for (int c = 0; c < 8; c++) {
            int gn = bn + tx*8 + c;
            if (gn < N) C[(size_t)gm * ldc + gn] = acc[r][c];
        }
    }
}

// ---------------- bf16 WMMA GEMM: 128x128 tile, 8 warps of 64x32 ----------------
template<int SPLIT>
__global__ __launch_bounds__(256) void k_wgemm(
    const __nv_bfloat16* __restrict__ A, int lda,
    const __nv_bfloat16* __restrict__ Bh, const __nv_bfloat16* __restrict__ Bl, int ldb,
    float* __restrict__ C, int ldc, int Kc, size_t zstride)
{
    __shared__ __nv_bfloat16 As[128][48];
    __shared__ __nv_bfloat16 Bsh[32][136];
    __shared__ __nv_bfloat16 Bsl[SPLIT ? 32 : 1][SPLIT ? 136 : 8];
    int bm = blockIdx.y * 128, bn = blockIdx.x * 128;
    int k0beg = blockIdx.z * Kc;
    C += (size_t)blockIdx.z * zstride;
    int tid = threadIdx.x;
    int wid = tid >> 5;
    int wm = wid >> 2, wn = wid & 3;

    wmma::fragment<wmma::accumulator,16,16,16,float> cf[4][2];
    #pragma unroll
    for (int i = 0; i < 4; i++)
        #pragma unroll
        for (int j = 0; j < 2; j++)
            wmma::fill_fragment(cf[i][j], 0.0f);

    for (int k0 = k0beg; k0 < k0beg + Kc; k0 += 32) {
        #pragma unroll
        for (int l = 0; l < 2; l++) {
            int idx = tid + l * 256;
            int m = idx >> 2, q = idx & 3;
            *(uint4*)&As[m][q*8] = *(const uint4*)(A + (size_t)(bm + m)*lda + k0 + q*8);
        }
        #pragma unroll
        for (int l = 0; l < 2; l++) {
            int idx = tid + l * 256;
            int kk = idx >> 4, q = idx & 15;
            *(uint4*)&Bsh[kk][q*8] = *(const uint4*)(Bh + (size_t)(k0 + kk)*ldb + bn + q*8);
        }
        if (SPLIT) {
            #pragma unroll
            for (int l = 0; l < 2; l++) {
                int idx = tid + l * 256;
                int kk = idx >> 4, q = idx & 15;
                *(uint4*)&Bsl[kk][q*8] = *(const uint4*)(Bl + (size_t)(k0 + kk)*ldb + bn + q*8);
            }
        }
        __syncthreads();
        #pragma unroll
        for (int ks = 0; ks < 2; ks++) {
            wmma::fragment<wmma::matrix_a,16,16,16,__nv_bfloat16,wmma::row_major> af[4];
            #pragma unroll
            for (int i = 0; i < 4; i++)
                wmma::load_matrix_sync(af[i], &As[wm*64 + i*16][ks*16], 48);
            wmma::fragment<wmma::matrix_b,16,16,16,__nv_bfloat16,wmma::row_major> bf[2];
            #pragma unroll
            for (int j = 0; j < 2; j++)
                wmma::load_matrix_sync(bf[j], &Bsh[ks*16][wn*32 + j*16], 136);
            #pragma unroll
            for (int i = 0; i < 4; i++)
                #pragma unroll
                for (int j = 0; j < 2; j++)
                    wmma::mma_sync(cf[i][j], af[i], bf[j], cf[i][j]);
            if (SPLIT) {
                #pragma unroll
                for (int j = 0; j < 2; j++)
                    wmma::load_matrix_sync(bf[j], &Bsl[ks*16][wn*32 + j*16], 136);
                #pragma unroll
                for (int i = 0; i < 4; i++)
                    #pragma unroll
                    for (int j = 0; j < 2; j++)
                        wmma::mma_sync(cf[i][j], af[i], bf[j], cf[i][j]);
            }
        }
        __syncthreads();
    }
    #pragma unroll
    for (int i = 0; i < 4; i++)
        #pragma unroll
        for (int j = 0; j < 2; j++)
            wmma::store_matrix_sync(C + (size_t)(bm + wm*64 + i*16)*ldc + bn + wn*32 + j*16,
                                    cf[i][j], ldc, wmma::mem_row_major);
}

// ---------------- bf16 conversions ----------------
// A1 -> bf16 (padded), fused rowsum -> rs1
__global__ void k_conv_A1(const float* __restrict__ A1, __nv_bfloat16* __restrict__ dst,
                          float* __restrict__ rs1) {
    __shared__ float sh[256];
    int r = blockIdx.x;  // [0,1536)
    float rsum = 0.0f;
    for (int c = threadIdx.x; c < KP1; c += 256) {
        float v = (r < KK1 && c < KK1) ? A1[(size_t)r*KK1 + c] : 0.0f;
        rsum += v;
        dst[(size_t)r*KP1 + c] = __float2bfloat16(v);
    }
    sh[threadIdx.x] = rsum;
    __syncthreads();
    for (int st = 128; st > 0; st >>= 1) {
        if (threadIdx.x < st) sh[threadIdx.x] += sh[threadIdx.x + st];
        __syncthreads();
    }
    if (threadIdx.x == 0 && r < KK1) rs1[r] = sh[0];
}

// merged: blocks [0,MP2) -> Ar rows; blocks [MP2, MP2+KP1) -> Bc rows
__global__ void k_conv_arbc(const float* __restrict__ A1, const int* __restrict__ perm,
                            __nv_bfloat16* __restrict__ Ar, __nv_bfloat16* __restrict__ Bc) {
    int b = blockIdx.x;
    if (b < MP2) {
        int r = b;
        int pr = (r < KK2) ? perm[r] : -1;
        for (int c = threadIdx.x; c < KP1; c += 256) {
            float v = 0.0f;
            if (pr >= 0 && c < KK1) v = A1[(size_t)pr*KK1 + c] + (c == pr ? 1.0f : 0.0f);
            Ar[(size_t)r*KP1 + c] = __float2bfloat16(v);
        }
    } else {
        int k = b - MP2;
        for (int col = threadIdx.x; col < MP2; col += 256) {
            float v = 0.0f;
            if (k < KK1 && col < KK2) {
                int pb = perm[col];
                v = A1[(size_t)k*KK1 + pb] + (k == pb ? 1.0f : 0.0f);
            }
            Bc[(size_t)k*MP2 + col] = __float2bfloat16(v);
        }
    }
}

// sum S split-K partials -> XW fp32; if HILO also write dis-scaled hi/lo bf16 (padded rows)
template<int HILO, int S>
__global__ void k_xw_finish(const float* __restrict__ part, size_t zstride, int n,
                            const float* __restrict__ rs, float* __restrict__ XW,
                            __nv_bfloat16* __restrict__ hi, __nv_bfloat16* __restrict__ lo) {
    int r = blockIdx.x;
    int c = threadIdx.x;  // 128
    size_t base = (size_t)r * HID + c;
    if (r < n) {
        float a = part[base];
        #pragma unroll
        for (int zz = 1; zz < S; zz++) a += part[base + zz*zstride];
        XW[base] = a;
        if (HILO) {
            float d = rsqrtf(rs[r] + 2.0f);
            float v = a * d;
            __nv_bfloat16 h = __float2bfloat16(v);
            hi[base] = h;
            lo[base] = __float2bfloat16(v - __bfloat162float(h));
        }
    } else if (HILO) {
        hi[base] = __float2bfloat16(0.0f);
        lo[base] = __float2bfloat16(0.0f);
    }
}

// ---------------- sparse GCN on A0, fused pool1 score ----------------
__global__ void k_gcn0(const float* __restrict__ XW, const float* __restrict__ b,
                       const int* __restrict__ cnt, const int* __restrict__ off,
                       const int* __restrict__ col, float* __restrict__ out,
                       const float* __restrict__ p, float* __restrict__ score,
                       int* __restrict__ inv) {
    __shared__ int   snb[128];
    __shared__ float sds[128];
    __shared__ float sh[128];
    __shared__ float sp[128];
    int i = blockIdx.x, c = threadIdx.x;
    float di = rsqrtf((float)cnt[i] + 2.0f);
    float acc = 2.0f * di * XW[(size_t)i*HID + c];
    int s0 = off[i], s1 = off[i+1];
    for (int base = s0; base < s1; base += 128) {
        int e = base + c;
        if (e < s1) { int s = col[e]; snb[c] = s; sds[c] = rsqrtf((float)cnt[s] + 2.0f); }
        __syncthreads();
        int lim = min(128, s1 - base);
        for (int t = 0; t < lim; t++)
            acc += sds[t] * XW[(size_t)snb[t]*HID + c];
        __syncthreads();
    }
    float val = tanhf(di * acc + b[c]);
    out[(size_t)i*HID + c] = val;
    float pc = p[c];
    sh[c] = val * pc;
    sp[c] = pc * pc;
    __syncthreads();
    for (int st = 64; st > 0; st >>= 1) {
        if (c < st) { sh[c] += sh[c+st]; sp[c] += sp[c+st]; }
        __syncthreads();
    }
    if (c == 0) { score[i] = tanhf(sh[0] * rsqrtf(sp[0])); inv[i] = -1; }
}

__global__ void k_topk(const float* __restrict__ s, int n, int K,
                       int* __restrict__ perm, float* __restrict__ vals,
                       int* __restrict__ inv) {
    __shared__ float sh[256];
    int i = blockIdx.x * blockDim.x + threadIdx.x;
    float si = (i < n) ? s[i] : -1e30f;
    int rank = 0;
    for (int j0 = 0; j0 < n; j0 += 256) {
        int j = j0 + threadIdx.x;
        sh[threadIdx.x] = (j < n) ? s[j] : -1e30f;
        __syncthreads();
        const float4* sh4 = (const float4*)sh;
        #pragma unroll 4
        for (int t = 0; t < 64; t++) {
            float4 v = sh4[t];
            int jj = j0 + 4*t;
            rank += (v.x > si) || (v.x == si && jj   < i);
            rank += (v.y > si) || (v.y == si && jj+1 < i);
            rank += (v.z > si) || (v.z == si && jj+2 < i);
            rank += (v.w > si) || (v.w == si && jj+3 < i);
        }
        __syncthreads();
    }
    if (i < n && rank < K) { perm[rank] = i; vals[rank] = si; inv[i] = rank; }
}

// ---------------- sparse augment(A0) into A1 submatrix ----------------
__global__ void k_aug_pairs(const int* __restrict__ off_s, const int* __restrict__ col_s,
                            const int* __restrict__ off_d, const int* __restrict__ col_d,
                            const int* __restrict__ inv, float* __restrict__ A1) {
    int k = blockIdx.x;
    int os = off_s[k], ns = off_s[k+1] - os;
    int od = off_d[k], nd = off_d[k+1] - od;
    int tot = ns * nd;
    for (int t = threadIdx.x; t < tot; t += 128) {
        int i = col_s[os + t / nd];
        int j = col_d[od + t % nd];
        if (i != k && j != k && i != j) {
            int r = inv[i], c = inv[j];
            if (r >= 0 && c >= 0) atomicAdd(&A1[(size_t)r*KK1 + c], 1.0f);
        }
    }
}

__global__ void k_aug_edges(const int* ei, int E, const int* __restrict__ inv,
                            float* __restrict__ A1) {
    int e = blockIdx.x * blockDim.x + threadIdx.x;
    if (e < E) {
        int s = ei[e], t = ei[E + e];
        if (s != t) {
            int r = inv[t], c = inv[s];
            if (r >= 0 && c >= 0) atomicAdd(&A1[(size_t)r*KK1 + c], 2.0f);
        }
    }
}

// sum 4 partials, zero diag, rowsum -> rs2, store A2 (ld A2LD)
__global__ void k_a2_finish(const float* __restrict__ part, float* __restrict__ A2,
                            float* __restrict__ rs2) {
    __shared__ float sh[256];
    int i = blockIdx.x;
    float rsum = 0.0f;
    for (int j = threadIdx.x; j < KK2; j += 256) {
        float s = 0.0f;
        #pragma unroll
        for (int zz = 0; zz < 4; zz++)
            s += part[((size_t)zz*MP2 + i)*MP2 + j];
        if (j == i) s = 0.0f;
        A2[(size_t)i*A2LD + j] = s;
        rsum += s;
    }
    sh[threadIdx.x] = rsum;
    __syncthreads();
    for (int st = 128; st > 0; st >>= 1) {
        if (threadIdx.x < st) sh[threadIdx.x] += sh[threadIdx.x + st];
        __syncthreads();
    }
    if (threadIdx.x == 0) rs2[i] = sh[0];
}

// row-per-block epilogue: out = tanh(d*sumpart + 2*d^2*XW + bias); optional fused score
template<int SCORE>
__global__ void k_agg_epi(const float* __restrict__ part, int S, size_t zstride,
                          const float* __restrict__ XW, const float* __restrict__ bias,
                          const float* __restrict__ rs, float* __restrict__ out,
                          const float* __restrict__ p, float* __restrict__ score,
                          int* __restrict__ inv) {
    __shared__ float sh[128];
    __shared__ float sp[128];
    int i = blockIdx.x, c = threadIdx.x;
    size_t base = (size_t)i * HID + c;
    float a = part[base];
    #pragma unroll 4
    for (int zz = 1; zz < S; zz++) a += part[base + zz*zstride];
    float d = rsqrtf(rs[i] + 2.0f);
    float val = tanhf(d * a + 2.0f * d * d * XW[base] + bias[c]);
    out[base] = val;
    if (SCORE) {
        float pc = p[c];
        sh[c] = val * pc;
        sp[c] = pc * pc;
        __syncthreads();
        for (int st = 64; st > 0; st >>= 1) {
            if (c < st) { sh[c] += sh[c+st]; sp[c] += sp[c+st]; }
            __syncthreads();
        }
        if (c == 0) { score[i] = tanhf(sh[0] * rsqrtf(sp[0])); inv[i] = -1; }
    }
}

// XW3 = (h0 + scatter(u1b, inv1)) @ Wu1  (N=3), warp per row
__global__ void k_xw3(const float* __restrict__ h0, const float* __restrict__ u1b,
                      const int* __restrict__ inv1, const float* __restrict__ W,
                      float* __restrict__ XW3) {
    int w = (blockIdx.x * blockDim.x + threadIdx.x) >> 5;
    int lane = threadIdx.x & 31;
    if (w >= N0) return;
    int r = inv1[w];
    float a0 = 0.f, a1 = 0.f, a2 = 0.f;
    #pragma unroll
    for (int q = 0; q < 4; q++) {
        int k = lane + q * 32;
        float v = h0[(size_t)w*HID + k];
        if (r >= 0) v += u1b[(size_t)r*HID + k];
        a0 += v * W[k*3+0];
        a1 += v * W[k*3+1];
        a2 += v * W[k*3+2];
    }
    #pragma unroll
    for (int off = 16; off > 0; off >>= 1) {
        a0 += __shfl_down_sync(0xffffffffu, a0, off);
        a1 += __shfl_down_sync(0xffffffffu, a1, off);
        a2 += __shfl_down_sync(0xffffffffu, a2, off);
    }
    if (lane == 0) { XW3[w*3+0] = a0; XW3[w*3+1] = a1; XW3[w*3+2] = a2; }
}

// final sparse GCN (OUTC=3) + noise
__global__ void k_gcn_final(const float* __restrict__ XW3, const float* __restrict__ b,
                            const int* __restrict__ cnt, const int* __restrict__ off,
                            const int* __restrict__ col, const float* __restrict__ z,
                            float* __restrict__ out) {
    int i = blockIdx.x * blockDim.x + threadIdx.x;
    if (i >= N0) return;
    float di = rsqrtf((float)cnt[i] + 2.0f);
    float a0 = 2.0f * di * XW3[i*3+0];
    float a1 = 2.0f * di * XW3[i*3+1];
    float a2 = 2.0f * di * XW3[i*3+2];
    int s0 = off[i], s1 = off[i+1];
    for (int e = s0; e < s1; e++) {
        int s = col[e];
        float ds = rsqrtf((float)cnt[s] + 2.0f);
        a0 += ds * XW3[s*3+0];
        a1 += ds * XW3[s*3+1];
        a2 += ds * XW3[s*3+2];
    }
    out[i*3+0] = di*a0 + b[0] + 0.1f*z[i*3+0];
    out[i*3+1] = di*a1 + b[1] + 0.1f*z[i*3+1];
    out[i*3+2] = di*a2 + b[2] + 0.1f*z[i*3+2];
}

// ---------------- launch ----------------
extern "C" void kernel_launch(void* const* d_in, const int* in_sizes, int n_in,
                              void* d_out, int out_size) {
    const float* x   = (const float*)d_in[0];
    const float* z   = (const float*)d_in[1];
    const float* W0  = (const float*)d_in[2];
    const float* b0  = (const float*)d_in[3];
    const float* W1  = (const float*)d_in[4];
    const float* b1  = (const float*)d_in[5];
    const float* W2  = (const float*)d_in[6];
    const float* b2  = (const float*)d_in[7];
    const float* p1  = (const float*)d_in[8];
    const float* p2  = (const float*)d_in[9];
    const float* Wu0 = (const float*)d_in[10];
    const float* bu0 = (const float*)d_in[11];
    const float* Wu1 = (const float*)d_in[12];
    const float* bu1 = (const float*)d_in[13];
    const int*   ei  = (const int*)d_in[14];
    int E = in_sizes[14] / 2;
    if (E > EMAX) E = EMAX;

    float* F; cudaGetSymbolAddress((void**)&F, g_f);
    int*   I; cudaGetSymbolAddress((void**)&I, g_i);
    __nv_bfloat16* H; cudaGetSymbolAddress((void**)&H, g_h);
    float* out = (float*)d_out;

    float *A1 = F+O_A1, *rs1 = F+O_RS1, *rs2 = F+O_RS2;
    float *A2 = F+O_A2, *part = F+O_PART;
    float *XW0 = F+O_XW0, *h0 = F+O_H0, *XW = F+O_XW;
    float *h1 = F+O_H1, *u1b = F+O_U1B, *h2 = F+O_H2, *XW3 = F+O_XW3;
    float *score = F+O_SC, *vals1 = F+O_VL1, *vals2 = F+O_VL2;
    __nv_bfloat16 *A1bf = H+HB_A1, *Ar = H+HB_AR, *Bc = H+HB_BC;
    __nv_bfloat16 *XWh = H+HB_XH, *XWl = H+HB_XL;
    int *perm1 = I+IO_P1, *perm2 = I+IO_P2, *inv1 = I+IO_INV1, *inv2 = I+IO_INV2;

    cudaMemsetAsync(A1, 0, ((size_t)KK1*KK1 + KK1 + 768)*sizeof(float));
    cudaMemsetAsync(I, 0, 12000*sizeof(int));
    cudaMemsetAsync(d_out, 0, (size_t)out_size*sizeof(float));

    // CSR
    k_count<<<CDIV(E,256),256>>>(ei, E, I+IO_CNTS, I+IO_CNTD);
    k_scan2<<<2,1024>>>(I+IO_CNTS, I+IO_OFFS, I+IO_CNTD, I+IO_OFFD, N0);
    k_fill<<<CDIV(E,256),256>>>(ei, E, I+IO_OFFS, I+IO_OFFD, I+IO_CURS, I+IO_CURD, I+IO_COLS, I+IO_COLD);

    // down0 (+ fused pool1 score)
    k_xw0<<<N0/8,256>>>(x, W0, XW0);
    k_gcn0<<<N0,128>>>(XW0, b0, I+IO_CNTD, I+IO_OFFD, I+IO_COLD, h0, p1, score, inv1);
    k_topk<<<CDIV(N0,256),256>>>(score, N0, KK1, perm1, vals1, inv1);

    // augment(A0) -> A1 ; bf16 copy + rowsum
    k_aug_pairs<<<N0,128>>>(I+IO_OFFS, I+IO_COLS, I+IO_OFFD, I+IO_COLD, inv1, A1);
    k_aug_edges<<<CDIV(E,256),256>>>(ei, E, inv1, A1);
    k_conv_A1<<<KP1,256>>>(A1, A1bf, rs1);

    // down1: XW = gate(h0)@W1 (split-K z=8) ; finish(+hilo) ; bf16 agg ; epi(+pool2 score) -> h1
    k_gemm128<1,0><<<dim3(1, CDIV(KK1,128), 8),256>>>(h0, HID, W1, HID, part, HID,
        KK1, HID, HID, 16, 0, perm1, vals1, 0, 0);
    k_xw_finish<1,8><<<KP1,128>>>(part, (size_t)KK1*HID, KK1, rs1, XW, XWh, XWl);
    k_wgemm<1><<<dim3(1, 12, 12),256>>>(A1bf, KP1, XWh, XWl, HID, part, HID, 128, (size_t)KP1*HID);
    k_agg_epi<1><<<KK1,128>>>(part, 12, (size_t)KP1*HID, XW, b1, rs1, h1, p2, score, inv2);
    k_topk<<<CDIV(KK1,256),256>>>(score, KK1, KK2, perm2, vals2, inv2);

    // A2 = (A1+I)[perm2,:] @ (A1+I)[:,perm2]  — exact bf16 tensor-core product
    k_conv_arbc<<<MP2+KP1,256>>>(A1, perm2, Ar, Bc);
    k_wgemm<0><<<dim3(6, 6, 4),256>>>(Ar, KP1, Bc, Bc, MP2, part, MP2, 384, (size_t)MP2*MP2);
    k_a2_finish<<<KK2,256>>>(part, A2, rs2);

    // down2: XW = gate(h1)@W2 (split-K z=8) ; finish ; fp32 split-K agg ; epi -> h2
    k_gemm128<1,0><<<dim3(1, CDIV(KK2,128), 8),256>>>(h1, HID, W2, HID, part, HID,
        KK2, HID, HID, 16, 0, perm2, vals2, 0, 0);
    k_xw_finish<0,8><<<KK2,128>>>(part, (size_t)KK2*HID, KK2, 0, XW, 0, 0);
    k_gemm128<0,1><<<dim3(1, CDIV(KK2,128), 24),256>>>(A2, A2LD, XW, HID, part, HID,
        KK2, HID, KK2, 32, rs2, 0, 0, 0, 0);
    k_agg_epi<0><<<KK2,128>>>(part, 24, (size_t)KK2*HID, XW, b2, rs2, h2, 0, 0, 0);

    // up0: XW = (h1 + scatter(h2,inv2))@Wu0 (split-K z=8) ; finish(+hilo) ; bf16 agg ; epi -> u1b
    k_gemm128<3,0><<<dim3(1, CDIV(KK1,128), 8),256>>>(h1, HID, Wu0, HID, part, HID,
        KK1, HID, HID, 16, 0, 0, 0, h2, inv2);
    k_xw_finish<1,8><<<KP1,128>>>(part, (size_t)KK1*HID, KK1, rs1, XW, XWh, XWl);
    k_wgemm<1><<<dim3(1, 12, 12),256>>>(A1bf, KP1, XWh, XWl, HID, part, HID, 128, (size_t)KP1*HID);
    k_agg_epi<0><<<KK1,128>>>(part, 12, (size_t)KP1*HID, XW, bu0, rs1, u1b, 0, 0, 0);

    // up1: XW3 = (h0 + scatter(u1b,inv1))@Wu1 ; final sparse GCN + noise
    k_xw3<<<CDIV(N0*32,256),256>>>(h0, u1b, inv1, Wu1, XW3);
    k_gcn_final<<<CDIV(N0,128),128>>>(XW3, bu1, I+IO_CNTD, I+IO_OFFD, I+IO_COLD, z, out);
}

// round 16
// speedup vs baseline: 4.3354x; 1.0927x over previous
#include <cuda_runtime.h>
#include <cuda_bf16.h>
#include <mma.h>
#include <math.h>

using namespace nvcuda;

#define N0   3000
#define KK1  1500
#define KK2  750
#define HID  128
#define INC  32
#define OUTC 3
#define EMAX 48000
#define DMAX 64

#define KP1  1536
#define MP2  768

#define CDIV(a,b) (((a)+(b)-1)/(b))

// ---------------- float scratch ----------------
static const size_t O_A1   = 0;                                  // KK1*KK1
static const size_t O_RS1  = O_A1  + (size_t)KK1*KK1;            // KK1
static const size_t O_RS2  = O_RS1 + KK1;                        // 768
static const size_t O_PART = O_RS2 + 768;                        // 2,359,296
static const size_t O_XW0  = O_PART+ (size_t)2359296;
static const size_t O_H0   = O_XW0 + (size_t)N0*HID;
static const size_t O_XW   = O_H0  + (size_t)N0*HID;
static const size_t O_H1   = O_XW  + (size_t)KK1*HID;
static const size_t O_U1B  = O_H1  + (size_t)KK1*HID;
static const size_t O_H2   = O_U1B + (size_t)KK1*HID;
static const size_t O_XW3  = O_H2  + (size_t)KK2*HID;
static const size_t O_SC   = O_XW3 + (size_t)N0*4;
static const size_t O_VL1  = O_SC  + N0;
static const size_t O_VL2  = O_VL1 + 1536;
static const size_t FTOT   = O_VL2 + 768;

__device__ float g_f[FTOT];

// ---------------- bf16 scratch ----------------
static const size_t HB_A1  = 0;                                  // KP1*KP1
static const size_t HB_AR  = HB_A1 + (size_t)KP1*KP1;            // MP2*KP1
static const size_t HB_BC  = HB_AR + (size_t)MP2*KP1;            // KP1*MP2
static const size_t HB_XH  = HB_BC + (size_t)KP1*MP2;            // KP1*HID
static const size_t HB_XL  = HB_XH + (size_t)KP1*HID;            // KP1*HID
static const size_t HB_A2H = HB_XL + (size_t)KP1*HID;            // MP2*MP2
static const size_t HB_A2L = HB_A2H + (size_t)MP2*MP2;           // MP2*MP2
static const size_t HTOT   = HB_A2L + (size_t)MP2*MP2;

__device__ __nv_bfloat16 g_h[HTOT];

// ---------------- int scratch ----------------
static const size_t IO_CNTS = 0;                 // 3000
static const size_t IO_CNTD = 3000;              // 3000
static const size_t IO_COLS = 6000;              // 3000*64
static const size_t IO_COLD = IO_COLS + (size_t)N0*DMAX;
static const size_t IO_P1   = IO_COLD + (size_t)N0*DMAX;
static const size_t IO_P2   = IO_P1 + 1536;
static const size_t IO_INV1 = IO_P2 + 768;       // 3072
static const size_t IO_INV2 = IO_INV1 + 3072;    // 1536
static const size_t ITOT    = IO_INV2 + 1536;

__device__ int g_i[ITOT];

// ---------------- adjacency build: count + fixed-stride fill in one kernel ----------------
__global__ void k_build(const int* ei, int E, int* cnt_s, int* cnt_d,
                        int* col_s, int* col_d) {
    int e = blockIdx.x * blockDim.x + threadIdx.x;
    if (e < E) {
        int s = ei[e], t = ei[E + e];
        int p = atomicAdd(&cnt_s[s], 1);
        if (p < DMAX) col_s[s * DMAX + p] = t;
        int q = atomicAdd(&cnt_d[t], 1);
        if (q < DMAX) col_d[t * DMAX + q] = s;
    }
}

// ---------------- down0 GEMM: XW0 = x[3000,32] @ W0[32,128] ----------------
__global__ __launch_bounds__(256) void k_xw0(const float* __restrict__ x,
                                             const float* __restrict__ W0,
                                             float* __restrict__ XW0) {
    __shared__ float ws[INC * HID];
    __shared__ float xs[8][INC];
    int tid = threadIdx.x;
    int r0 = blockIdx.x * 8;
    #pragma unroll
    for (int l = 0; l < 16; l++) ws[tid + l * 256] = W0[tid + l * 256];
    if (tid < 8 * INC) xs[tid >> 5][tid & 31] = x[(size_t)r0 * INC + tid];
    __syncthreads();
    int c = tid & 127, g = tid >> 7;
    float acc[4] = {};
    #pragma unroll
    for (int k = 0; k < INC; k++) {
        float wv = ws[k * HID + c];
        #pragma unroll
        for (int j = 0; j < 4; j++)
            acc[j] += xs[g + j * 2][k] * wv;
    }
    #pragma unroll
    for (int j = 0; j < 4; j++)
        XW0[(size_t)(r0 + g + j * 2) * HID + c] = acc[j];
}

// ---------------- fp32 SGEMM 128x128 tile, BK=16, 8x8 microtile (gate/scatter XW) ----------------
// AM: 1 gather-gate; 3 add-scatter.
template<int AM>
__global__ __launch_bounds__(256) void k_gemm128(
    const float* __restrict__ A, int lda,
    const float* __restrict__ B, int ldb,
    float* __restrict__ C, int ldc,
    int M, int N, int K, int Kc,
    const int* __restrict__ aperm, const float* __restrict__ avals,
    const float* __restrict__ adelta, const int* __restrict__ ainv)
{
    __shared__ float As[16][132];
    __shared__ float Bs[16][128];
    int bm = blockIdx.y * 128, bn = blockIdx.x * 128;
    int kstart = blockIdx.z * Kc;
    int kend = min(K, kstart + Kc);
    if (gridDim.z > 1) C += (size_t)blockIdx.z * M * ldc;
    int tid = threadIdx.x, tx = tid & 15, ty = tid >> 4;
    float acc[8][8] = {};
    for (int k0 = kstart; k0 < kend; k0 += 16) {
        #pragma unroll
        for (int l = 0; l < 2; l++) {
            int idx = tid + l * 256;
            int m = idx >> 2, k4 = idx & 3;
            int gm = bm + m, gk = k0 + k4 * 4;
            float4 v = make_float4(0.f, 0.f, 0.f, 0.f);
            if (gm < M) {
                const float* src;
                float scale = 1.0f;
                if (AM == 1) { scale = avals[gm]; src = A + (size_t)aperm[gm] * lda; }
                else          src = A + (size_t)gm * lda;
                v = *(const float4*)(src + gk);
                if (AM == 1) { v.x *= scale; v.y *= scale; v.z *= scale; v.w *= scale; }
                if (AM == 3) {
                    int r = ainv[gm];
                    if (r >= 0) {
                        float4 d4 = *(const float4*)(adelta + (size_t)r * lda + gk);
                        v.x += d4.x; v.y += d4.y; v.z += d4.z; v.w += d4.w;
                    }
                }
            }
            As[k4*4+0][m] = v.x; As[k4*4+1][m] = v.y;
            As[k4*4+2][m] = v.z; As[k4*4+3][m] = v.w;
        }
        #pragma unroll
        for (int l = 0; l < 2; l++) {
            int idx = tid + l * 256;
            int kk = idx >> 5, n4 = idx & 31;
            int gk = k0 + kk, gn = bn + n4 * 4;
            float4 v = make_float4(0.f, 0.f, 0.f, 0.f);
            if (gk < kend && gn < N)
                v = *(const float4*)(B + (size_t)gk * ldb + gn);
            *(float4*)&Bs[kk][n4*4] = v;
        }
        __syncthreads();
        #pragma unroll
        for (int kk = 0; kk < 16; kk++) {
            float a[8], b[8];
            *(float4*)&a[0] = *(const float4*)&As[kk][ty*8];
            *(float4*)&a[4] = *(const float4*)&As[kk][ty*8+4];
            *(float4*)&b[0] = *(const float4*)&Bs[kk][tx*8];
            *(float4*)&b[4] = *(const float4*)&Bs[kk][tx*8+4];
            #pragma unroll
            for (int r = 0; r < 8; r++)
                #pragma unroll
                for (int c = 0; c < 8; c++)
                    acc[r][c] += a[r] * b[c];
        }
        __syncthreads();
    }
    #pragma unroll
    for (int r = 0; r < 8; r++) {
        int gm = bm + ty*8 + r;
        if (gm >= M) continue;
        #pragma unroll
        for (int c = 0; c < 8; c++) {
            int gn = bn + tx*8 + c;
            if (gn < N) C[(size_t)gm * ldc + gn] = acc[r][c];
        }
    }
}

// ---------------- bf16 WMMA GEMM: 128x128 tile, 8 warps of 64x32 ----------------
// SPLIT 0: A@Bh. SPLIT 1: A@(Bh+Bl).
template<int SPLIT>
__global__ __launch_bounds__(256) void k_wgemm(
    const __nv_bfloat16* __restrict__ A, int lda,
    const __nv_bfloat16* __restrict__ Bh, const __nv_bfloat16* __restrict__ Bl, int ldb,
    float* __restrict__ C, int ldc, int Kc, size_t zstride)
{
    __shared__ __nv_bfloat16 As[128][48];
    __shared__ __nv_bfloat16 Bsh[32][136];
    __shared__ __nv_bfloat16 Bsl[SPLIT ? 32 : 1][SPLIT ? 136 : 8];
    int bm = blockIdx.y * 128, bn = blockIdx.x * 128;
    int k0beg = blockIdx.z * Kc;
    C += (size_t)blockIdx.z * zstride;
    int tid = threadIdx.x;
    int wid = tid >> 5;
    int wm = wid >> 2, wn = wid & 3;

    wmma::fragment<wmma::accumulator,16,16,16,float> cf[4][2];
    #pragma unroll
    for (int i = 0; i < 4; i++)
        #pragma unroll
        for (int j = 0; j < 2; j++)
            wmma::fill_fragment(cf[i][j], 0.0f);

    for (int k0 = k0beg; k0 < k0beg + Kc; k0 += 32) {
        #pragma unroll
        for (int l = 0; l < 2; l++) {
            int idx = tid + l * 256;
            int m = idx >> 2, q = idx & 3;
            *(uint4*)&As[m][q*8] = *(const uint4*)(A + (size_t)(bm + m)*lda + k0 + q*8);
        }
        #pragma unroll
        for (int l = 0; l < 2; l++) {
            int idx = tid + l * 256;
            int kk = idx >> 4, q = idx & 15;
            *(uint4*)&Bsh[kk][q*8] = *(const uint4*)(Bh + (size_t)(k0 + kk)*ldb + bn + q*8);
        }
        if (SPLIT) {
            #pragma unroll
            for (int l = 0; l < 2; l++) {
                int idx = tid + l * 256;
                int kk = idx >> 4, q = idx & 15;
                *(uint4*)&Bsl[kk][q*8] = *(const uint4*)(Bl + (size_t)(k0 + kk)*ldb + bn + q*8);
            }
        }
        __syncthreads();
        #pragma unroll
        for (int ks = 0; ks < 2; ks++) {
            wmma::fragment<wmma::matrix_a,16,16,16,__nv_bfloat16,wmma::row_major> af[4];
            #pragma unroll
            for (int i = 0; i < 4; i++)
                wmma::load_matrix_sync(af[i], &As[wm*64 + i*16][ks*16], 48);
            wmma::fragment<wmma::matrix_b,16,16,16,__nv_bfloat16,wmma::row_major> bf[2];
            #pragma unroll
            for (int j = 0; j < 2; j++)
                wmma::load_matrix_sync(bf[j], &Bsh[ks*16][wn*32 + j*16], 136);
            #pragma unroll
            for (int i = 0; i < 4; i++)
                #pragma unroll
                for (int j = 0; j < 2; j++)
                    wmma::mma_sync(cf[i][j], af[i], bf[j], cf[i][j]);
            if (SPLIT) {
                #pragma unroll
                for (int j = 0; j < 2; j++)
                    wmma::load_matrix_sync(bf[j], &Bsl[ks*16][wn*32 + j*16], 136);
                #pragma unroll
                for (int i = 0; i < 4; i++)
                    #pragma unroll
                    for (int j = 0; j < 2; j++)
                        wmma::mma_sync(cf[i][j], af[i], bf[j], cf[i][j]);
            }
        }
        __syncthreads();
    }
    #pragma unroll
    for (int i = 0; i < 4; i++)
        #pragma unroll
        for (int j = 0; j < 2; j++)
            wmma::store_matrix_sync(C + (size_t)(bm + wm*64 + i*16)*ldc + bn + wn*32 + j*16,
                                    cf[i][j], ldc, wmma::mem_row_major);
}

// (Ah+Al) @ (Bh+Bl) via 3 products (Ah·Bh + Ah·Bl + Al·Bh) — for A2 aggregation
__global__ __launch_bounds__(256) void k_wgemm2(
    const __nv_bfloat16* __restrict__ Ah, const __nv_bfloat16* __restrict__ Al, int lda,
    const __nv_bfloat16* __restrict__ Bh, const __nv_bfloat16* __restrict__ Bl, int ldb,
    float* __restrict__ C, int ldc, int Kc, size_t zstride)
{
    __shared__ __nv_bfloat16 Ash[128][48];
    __shared__ __nv_bfloat16 Asl[128][48];
    __shared__ __nv_bfloat16 Bsh[32][136];
    __shared__ __nv_bfloat16 Bsl[32][136];
    int bm = blockIdx.y * 128, bn = blockIdx.x * 128;
    int k0beg = blockIdx.z * Kc;
    C += (size_t)blockIdx.z * zstride;
    int tid = threadIdx.x;
    int wid = tid >> 5;
    int wm = wid >> 2, wn = wid & 3;

    wmma::fragment<wmma::accumulator,16,16,16,float> cf[4][2];
    #pragma unroll
    for (int i = 0; i < 4; i++)
        #pragma unroll
        for (int j = 0; j < 2; j++)
            wmma::fill_fragment(cf[i][j], 0.0f);

    for (int k0 = k0beg; k0 < k0beg + Kc; k0 += 32) {
        #pragma unroll
        for (int l = 0; l < 2; l++) {
            int idx = tid + l * 256;
            int m = idx >> 2, q = idx & 3;
            *(uint4*)&Ash[m][q*8] = *(const uint4*)(Ah + (size_t)(bm + m)*lda + k0 + q*8);
            *(uint4*)&Asl[m][q*8] = *(const uint4*)(Al + (size_t)(bm + m)*lda + k0 + q*8);
        }
        #pragma unroll
        for (int l = 0; l < 2; l++) {
            int idx = tid + l * 256;
            int kk = idx >> 4, q = idx & 15;
            *(uint4*)&Bsh[kk][q*8] = *(const uint4*)(Bh + (size_t)(k0 + kk)*ldb + bn + q*8);
            *(uint4*)&Bsl[kk][q*8] = *(const uint4*)(Bl + (size_t)(k0 + kk)*ldb + bn + q*8);
        }
        __syncthreads();
        #pragma unroll
        for (int ks = 0; ks < 2; ks++) {
            wmma::fragment<wmma::matrix_a,16,16,16,__nv_bfloat16,wmma::row_major> afh[4], afl[4];
            #pragma unroll
            for (int i = 0; i < 4; i++) {
                wmma::load_matrix_sync(afh[i], &Ash[wm*64 + i*16][ks*16], 48);
                wmma::load_matrix_sync(afl[i], &Asl[wm*64 + i*16][ks*16], 48);
            }
            wmma::fragment<wmma::matrix_b,16,16,16,__nv_bfloat16,wmma::row_major> bfh[2], bfl[2];
            #pragma unroll
            for (int j = 0; j < 2; j++) {
                wmma::load_matrix_sync(bfh[j], &Bsh[ks*16][wn*32 + j*16], 136);
                wmma::load_matrix_sync(bfl[j], &Bsl[ks*16][wn*32 + j*16], 136);
            }
            #pragma unroll
            for (int i = 0; i < 4; i++)
                #pragma unroll
                for (int j = 0; j < 2; j++) {
                    wmma::mma_sync(cf[i][j], afh[i], bfh[j], cf[i][j]);
                    wmma::mma_sync(cf[i][j], afh[i], bfl[j], cf[i][j]);
                    wmma::mma_sync(cf[i][j], afl[i], bfh[j], cf[i][j]);
                }
        }
        __syncthreads();
    }
    #pragma unroll
    for (int i = 0; i < 4; i++)
        #pragma unroll
        for (int j = 0; j < 2; j++)
            wmma::store_matrix_sync(C + (size_t)(bm + wm*64 + i*16)*ldc + bn + wn*32 + j*16,
                                    cf[i][j], ldc, wmma::mem_row_major);
}

// ---------------- bf16 conversions ----------------
__global__ void k_conv_A1(const float* __restrict__ A1, __nv_bfloat16* __restrict__ dst,
                          float* __restrict__ rs1) {
    __shared__ float sh[256];
    int r = blockIdx.x;
    float rsum = 0.0f;
    for (int c = threadIdx.x; c < KP1; c += 256) {
        float v = (r < KK1 && c < KK1) ? A1[(size_t)r*KK1 + c] : 0.0f;
        rsum += v;
        dst[(size_t)r*KP1 + c] = __float2bfloat16(v);
    }
    sh[threadIdx.x] = rsum;
    __syncthreads();
    for (int st = 128; st > 0; st >>= 1) {
        if (threadIdx.x < st) sh[threadIdx.x] += sh[threadIdx.x + st];
        __syncthreads();
    }
    if (threadIdx.x == 0 && r < KK1) rs1[r] = sh[0];
}

__global__ void k_conv_arbc(const float* __restrict__ A1, const int* __restrict__ perm,
                            __nv_bfloat16* __restrict__ Ar, __nv_bfloat16* __restrict__ Bc) {
    int b = blockIdx.x;
    if (b < MP2) {
        int r = b;
        int pr = (r < KK2) ? perm[r] : -1;
        for (int c = threadIdx.x; c < KP1; c += 256) {
            float v = 0.0f;
            if (pr >= 0 && c < KK1) v = A1[(size_t)pr*KK1 + c] + (c == pr ? 1.0f : 0.0f);
            Ar[(size_t)r*KP1 + c] = __float2bfloat16(v);
        }
    } else {
        int k = b - MP2;
        for (int col = threadIdx.x; col < MP2; col += 256) {
            float v = 0.0f;
            if (k < KK1 && col < KK2) {
                int pb = perm[col];
                v = A1[(size_t)k*KK1 + pb] + (k == pb ? 1.0f : 0.0f);
            }
            Bc[(size_t)k*MP2 + col] = __float2bfloat16(v);
        }
    }
}

// sum S split-K partials -> XW fp32; if HILO also dis-scaled hi/lo bf16
template<int HILO, int S>
__global__ void k_xw_finish(const float* __restrict__ part, size_t zstride, int n,
                            const float* __restrict__ rs, float* __restrict__ XW,
                            __nv_bfloat16* __restrict__ hi, __nv_bfloat16* __restrict__ lo) {
    int r = blockIdx.x;
    int c = threadIdx.x;
    size_t base = (size_t)r * HID + c;
    if (r < n) {
        float a = part[base];
        #pragma unroll
        for (int zz = 1; zz < S; zz++) a += part[base + zz*zstride];
        XW[base] = a;
        if (HILO) {
            float d = rsqrtf(rs[r] + 2.0f);
            float v = a * d;
            __nv_bfloat16 h = __float2bfloat16(v);
            hi[base] = h;
            lo[base] = __float2bfloat16(v - __bfloat162float(h));
        }
    } else if (HILO) {
        hi[base] = __float2bfloat16(0.0f);
        lo[base] = __float2bfloat16(0.0f);
    }
}

// ---------------- sparse GCN on A0 (stride-64 lists), fused pool1 score ----------------
__global__ void k_gcn0(const float* __restrict__ XW, const float* __restrict__ b,
                       const int* __restrict__ cnt, const int* __restrict__ col_d,
                       float* __restrict__ out,
                       const float* __restrict__ p, float* __restrict__ score,
                       int* __restrict__ inv) {
    __shared__ int   snb[DMAX];
    __shared__ float sds[DMAX];
    __shared__ float sh[128];
    __shared__ float sp[128];
    int i = blockIdx.x, c = threadIdx.x;
    int deg = cnt[i];
    int nl = min(deg, DMAX);
    float di = rsqrtf((float)deg + 2.0f);
    if (c < nl) {
        int s = col_d[i * DMAX + c];
        snb[c] = s;
        sds[c] = rsqrtf((float)cnt[s] + 2.0f);
    }
    __syncthreads();
    float acc = 2.0f * di * XW[(size_t)i*HID + c];
    for (int t = 0; t < nl; t++)
        acc += sds[t] * XW[(size_t)snb[t]*HID + c];
    float val = tanhf(di * acc + b[c]);
    out[(size_t)i*HID + c] = val;
    float pc = p[c];
    sh[c] = val * pc;
    sp[c] = pc * pc;
    __syncthreads();
    for (int st = 64; st > 0; st >>= 1) {
        if (c < st) { sh[c] += sh[c+st]; sp[c] += sp[c+st]; }
        __syncthreads();
    }
    if (c == 0) { score[i] = tanhf(sh[0] * rsqrtf(sp[0])); inv[i] = -1; }
}

__global__ void k_topk(const float* __restrict__ s, int n, int K,
                       int* __restrict__ perm, float* __restrict__ vals,
                       int* __restrict__ inv) {
    __shared__ float sh[256];
    int i = blockIdx.x * blockDim.x + threadIdx.x;
    float si = (i < n) ? s[i] : -1e30f;
    int rank = 0;
    for (int j0 = 0; j0 < n; j0 += 256) {
        int j = j0 + threadIdx.x;
        sh[threadIdx.x] = (j < n) ? s[j] : -1e30f;
        __syncthreads();
        const float4* sh4 = (const float4*)sh;
        #pragma unroll 4
        for (int t = 0; t < 64; t++) {
            float4 v = sh4[t];
            int jj = j0 + 4*t;
            rank += (v.x > si) || (v.x == si && jj   < i);
            rank += (v.y > si) || (v.y == si && jj+1 < i);
            rank += (v.z > si) || (v.z == si && jj+2 < i);
            rank += (v.w > si) || (v.w == si && jj+3 < i);
        }
        __syncthreads();
    }
    if (i < n && rank < K) { perm[rank] = i; vals[rank] = si; inv[i] = rank; }
}

// ---------------- augment(A0) -> A1 submatrix: pairs + edges, shared-staged ----------------
__global__ void k_aug(const int* __restrict__ cnt_s, const int* __restrict__ col_s,
                      const int* __restrict__ cnt_d, const int* __restrict__ col_d,
                      const int* __restrict__ inv, float* __restrict__ A1) {
    __shared__ int oi[DMAX], oinv[DMAX], ji[DMAX], jinv[DMAX];
    int k = blockIdx.x;
    int tid = threadIdx.x;
    int ns = min(cnt_s[k], DMAX);
    int nd = min(cnt_d[k], DMAX);
    if (tid < ns) {
        int i = col_s[k * DMAX + tid];
        oi[tid] = i; oinv[tid] = inv[i];
    }
    if (tid >= 64 && tid - 64 < nd) {
        int j = col_d[k * DMAX + (tid - 64)];
        ji[tid - 64] = j; jinv[tid - 64] = inv[j];
    }
    __syncthreads();
    int invk = inv[k];
    // 2-paths through k: edge k->i (A[i,k]) x edge j->k (A[k,j]) -> +1 at [inv_i, inv_j]
    int tot = ns * nd;
    for (int t = tid; t < tot; t += 128) {
        int ii = t / nd, jj = t - ii * nd;
        int i = oi[ii], j = ji[jj];
        int r = oinv[ii], c = jinv[jj];
        if (i != k && j != k && i != j && r >= 0 && c >= 0)
            atomicAdd(&A1[(size_t)r*KK1 + c], 1.0f);
    }
    // direct edges k->i: +2 at [inv_i, inv_k]
    if (invk >= 0) {
        for (int e = tid; e < ns; e += 128) {
            int i = oi[e], r = oinv[e];
            if (i != k && r >= 0)
                atomicAdd(&A1[(size_t)r*KK1 + invk], 2.0f);
        }
    }
}

// sum 4 partials of A2 product, zero diag, rowsum -> rs2, write hi/lo bf16 (padded)
__global__ void k_a2_finish(const float* __restrict__ part,
                            __nv_bfloat16* __restrict__ A2h, __nv_bfloat16* __restrict__ A2l,
                            float* __restrict__ rs2) {
    __shared__ float sh[256];
    int i = blockIdx.x;  // [0, MP2)
    float rsum = 0.0f;
    for (int j = threadIdx.x; j < MP2; j += 256) {
        float s = 0.0f;
        if (i < KK2 && j < KK2) {
            #pragma unroll
            for (int zz = 0; zz < 4; zz++)
                s += part[((size_t)zz*MP2 + i)*MP2 + j];
            if (j == i) s = 0.0f;
        }
        rsum += s;
        __nv_bfloat16 h = __float2bfloat16(s);
        A2h[(size_t)i*MP2 + j] = h;
        A2l[(size_t)i*MP2 + j] = __float2bfloat16(s - __bfloat162float(h));
    }
    sh[threadIdx.x] = rsum;
    __syncthreads();
    for (int st = 128; st > 0; st >>= 1) {
        if (threadIdx.x < st) sh[threadIdx.x] += sh[threadIdx.x + st];
        __syncthreads();
    }
    if (threadIdx.x == 0 && i < KK2) rs2[i] = sh[0];
}

// row-per-block epilogue + optional fused score
template<int SCORE>
__global__ void k_agg_epi(const float* __restrict__ part, int S, size_t zstride,
                          const float* __restrict__ XW, const float* __restrict__ bias,
                          const float* __restrict__ rs, float* __restrict__ out,
                          const float* __restrict__ p, float* __restrict__ score,
                          int* __restrict__ inv) {
    __shared__ float sh[128];
    __shared__ float sp[128];
    int i = blockIdx.x, c = threadIdx.x;
    size_t base = (size_t)i * HID + c;
    float a = part[base];
    #pragma unroll 4
    for (int zz = 1; zz < S; zz++) a += part[base + zz*zstride];
    float d = rsqrtf(rs[i] + 2.0f);
    float val = tanhf(d * a + 2.0f * d * d * XW[base] + bias[c]);
    out[base] = val;
    if (SCORE) {
        float pc = p[c];
        sh[c] = val * pc;
        sp[c] = pc * pc;
        __syncthreads();
        for (int st = 64; st > 0; st >>= 1) {
            if (c < st) { sh[c] += sh[c+st]; sp[c] += sp[c+st]; }
            __syncthreads();
        }
        if (c == 0) { score[i] = tanhf(sh[0] * rsqrtf(sp[0])); inv[i] = -1; }
    }
}

// XW3 = (h0 + scatter(u1b, inv1)) @ Wu1  (N=3), warp per row
__global__ void k_xw3(const float* __restrict__ h0, const float* __restrict__ u1b,
                      const int* __restrict__ inv1, const float* __restrict__ W,
                      float* __restrict__ XW3) {
    int w = (blockIdx.x * blockDim.x + threadIdx.x) >> 5;
    int lane = threadIdx.x & 31;
    if (w >= N0) return;
    int r = inv1[w];
    float a0 = 0.f, a1 = 0.f, a2 = 0.f;
    #pragma unroll
    for (int q = 0; q < 4; q++) {
        int k = lane + q * 32;
        float v = h0[(size_t)w*HID + k];
        if (r >= 0) v += u1b[(size_t)r*HID + k];
        a0 += v * W[k*3+0];
        a1 += v * W[k*3+1];
        a2 += v * W[k*3+2];
    }
    #pragma unroll
    for (int off = 16; off > 0; off >>= 1) {
        a0 += __shfl_down_sync(0xffffffffu, a0, off);
        a1 += __shfl_down_sync(0xffffffffu, a1, off);
        a2 += __shfl_down_sync(0xffffffffu, a2, off);
    }
    if (lane == 0) { XW3[w*3+0] = a0; XW3[w*3+1] = a1; XW3[w*3+2] = a2; }
}

// final sparse GCN (OUTC=3) + noise, stride-64 lists
__global__ void k_gcn_final(const float* __restrict__ XW3, const float* __restrict__ b,
                            const int* __restrict__ cnt, const int* __restrict__ col_d,
                            const float* __restrict__ z, float* __restrict__ out) {
    int i = blockIdx.x * blockDim.x + threadIdx.x;
    if (i >= N0) return;
    int deg = cnt[i];
    int nl = min(deg, DMAX);
    float di = rsqrtf((float)deg + 2.0f);
    float a0 = 2.0f * di * XW3[i*3+0];
    float a1 = 2.0f * di * XW3[i*3+1];
    float a2 = 2.0f * di * XW3[i*3+2];
    for (int e = 0; e < nl; e++) {
        int s = col_d[i * DMAX + e];
        float ds = rsqrtf((float)cnt[s] + 2.0f);
        a0 += ds * XW3[s*3+0];
        a1 += ds * XW3[s*3+1];
        a2 += ds * XW3[s*3+2];
    }
    out[i*3+0] = di*a0 + b[0] + 0.1f*z[i*3+0];
    out[i*3+1] = di*a1 + b[1] + 0.1f*z[i*3+1];
    out[i*3+2] = di*a2 + b[2] + 0.1f*z[i*3+2];
}

// ---------------- launch ----------------
extern "C" void kernel_launch(void* const* d_in, const int* in_sizes, int n_in,
                              void* d_out, int out_size) {
    const float* x   = (const float*)d_in[0];
    const float* z   = (const float*)d_in[1];
    const float* W0  = (const float*)d_in[2];
    const float* b0  = (const float*)d_in[3];
    const float* W1  = (const float*)d_in[4];
    const float* b1  = (const float*)d_in[5];
    const float* W2  = (const float*)d_in[6];
    const float* b2  = (const float*)d_in[7];
    const float* p1  = (const float*)d_in[8];
    const float* p2  = (const float*)d_in[9];
    const float* Wu0 = (const float*)d_in[10];
    const float* bu0 = (const float*)d_in[11];
    const float* Wu1 = (const float*)d_in[12];
    const float* bu1 = (const float*)d_in[13];
    const int*   ei  = (const int*)d_in[14];
    int E = in_sizes[14] / 2;
    if (E > EMAX) E = EMAX;

    float* F; cudaGetSymbolAddress((void**)&F, g_f);
    int*   I; cudaGetSymbolAddress((void**)&I, g_i);
    __nv_bfloat16* H; cudaGetSymbolAddress((void**)&H, g_h);
    float* out = (float*)d_out;

    float *A1 = F+O_A1, *rs1 = F+O_RS1, *rs2 = F+O_RS2, *part = F+O_PART;
    float *XW0 = F+O_XW0, *h0 = F+O_H0, *XW = F+O_XW;
    float *h1 = F+O_H1, *u1b = F+O_U1B, *h2 = F+O_H2, *XW3 = F+O_XW3;
    float *score = F+O_SC, *vals1 = F+O_VL1, *vals2 = F+O_VL2;
    __nv_bfloat16 *A1bf = H+HB_A1, *Ar = H+HB_AR, *Bc = H+HB_BC;
    __nv_bfloat16 *XWh = H+HB_XH, *XWl = H+HB_XL;
    __nv_bfloat16 *A2h = H+HB_A2H, *A2l = H+HB_A2L;
    int *perm1 = I+IO_P1, *perm2 = I+IO_P2, *inv1 = I+IO_INV1, *inv2 = I+IO_INV2;

    cudaMemsetAsync(A1, 0, ((size_t)KK1*KK1 + KK1 + 768)*sizeof(float));
    cudaMemsetAsync(I, 0, 6000*sizeof(int));
    cudaMemsetAsync(d_out, 0, (size_t)out_size*sizeof(float));

    // adjacency (single kernel, fixed stride DMAX)
    k_build<<<CDIV(E,256),256>>>(ei, E, I+IO_CNTS, I+IO_CNTD, I+IO_COLS, I+IO_COLD);

    // down0 (+ fused pool1 score)
    k_xw0<<<N0/8,256>>>(x, W0, XW0);
    k_gcn0<<<N0,128>>>(XW0, b0, I+IO_CNTD, I+IO_COLD, h0, p1, score, inv1);
    k_topk<<<CDIV(N0,256),256>>>(score, N0, KK1, perm1, vals1, inv1);

    // augment(A0) -> A1 (pairs + edges in one kernel) ; bf16 copy + rowsum
    k_aug<<<N0,128>>>(I+IO_CNTS, I+IO_COLS, I+IO_CNTD, I+IO_COLD, inv1, A1);
    k_conv_A1<<<KP1,256>>>(A1, A1bf, rs1);

    // down1: XW = gate(h0)@W1 (z=8) ; finish(+hilo) ; bf16 agg ; epi(+pool2 score)
    k_gemm128<1><<<dim3(1, CDIV(KK1,128), 8),256>>>(h0, HID, W1, HID, part, HID,
        KK1, HID, HID, 16, perm1, vals1, 0, 0);
    k_xw_finish<1,8><<<KP1,128>>>(part, (size_t)KK1*HID, KK1, rs1, XW, XWh, XWl);
    k_wgemm<1><<<dim3(1, 12, 12),256>>>(A1bf, KP1, XWh, XWl, HID, part, HID, 128, (size_t)KP1*HID);
    k_agg_epi<1><<<KK1,128>>>(part, 12, (size_t)KP1*HID, XW, b1, rs1, h1, p2, score, inv2);
    k_topk<<<CDIV(KK1,256),256>>>(score, KK1, KK2, perm2, vals2, inv2);

    // A2 = (A1+I)[perm2,:] @ (A1+I)[:,perm2] (exact bf16) -> hi/lo + rowsum
    k_conv_arbc<<<MP2+KP1,256>>>(A1, perm2, Ar, Bc);
    k_wgemm<0><<<dim3(6, 6, 4),256>>>(Ar, KP1, Bc, Bc, MP2, part, MP2, 384, (size_t)MP2*MP2);
    k_a2_finish<<<MP2,256>>>(part, A2h, A2l, rs2);

    // down2: XW = gate(h1)@W2 (z=8) ; finish(+hilo with rs2) ; A2 hi/lo wgemm ; epi
    k_gemm128<1><<<dim3(1, CDIV(KK2,128), 8),256>>>(h1, HID, W2, HID, part, HID,
        KK2, HID, HID, 16, perm2, vals2, 0, 0);
    k_xw_finish<1,8><<<MP2,128>>>(part, (size_t)KK2*HID, KK2, rs2, XW, XWh, XWl);
    k_wgemm2<<<dim3(1, 6, 8),256>>>(A2h, A2l, MP2, XWh, XWl, HID, part, HID, 96, (size_t)MP2*HID);
    k_agg_epi<0><<<KK2,128>>>(part, 8, (size_t)MP2*HID, XW, b2, rs2, h2, 0, 0, 0);

    // up0: XW = (h1 + scatter(h2,inv2))@Wu0 (z=8) ; finish(+hilo) ; bf16 agg ; epi
    k_gemm128<3><<<dim3(1, CDIV(KK1,128), 8),256>>>(h1, HID, Wu0, HID, part, HID,
        KK1, HID, HID, 16, 0, 0, h2, inv2);
    k_xw_finish<1,8><<<KP1,128>>>(part, (size_t)KK1*HID, KK1, rs1, XW, XWh, XWl);
    k_wgemm<1><<<dim3(1, 12, 12),256>>>(A1bf, KP1, XWh, XWl, HID, part, HID, 128, (size_t)KP1*HID);
    k_agg_epi<0><<<KK1,128>>>(part, 12, (size_t)KP1*HID, XW, bu0, rs1, u1b, 0, 0, 0);

    // up1: XW3 ; final sparse GCN + noise
    k_xw3<<<CDIV(N0*32,256),256>>>(h0, u1b, inv1, Wu1, XW3);
    k_gcn_final<<<CDIV(N0,128),128>>>(XW3, bu1, I+IO_CNTD, I+IO_COLD, z, out);
}

// round 17
// speedup vs baseline: 5.2529x; 1.2116x over previous
#include <cuda_runtime.h>
#include <cuda_bf16.h>
#include <mma.h>
#include <math.h>

using namespace nvcuda;

#define N0   3000
#define KK1  1500
#define KK2  750
#define HID  128
#define INC  32
#define OUTC 3
#define EMAX 48000
#define DMAX 64

#define KP1  1536
#define MP2  768

#define CDIV(a,b) (((a)+(b)-1)/(b))

// ---------------- float scratch ----------------
static const size_t O_A1   = 0;                                  // KK1*KK1
static const size_t O_RS1  = O_A1  + (size_t)KK1*KK1;            // KK1
static const size_t O_RS2  = O_RS1 + KK1;                        // 768
static const size_t O_PART = O_RS2 + 768;                        // 2,359,296
static const size_t O_XW0  = O_PART+ (size_t)2359296;
static const size_t O_H0   = O_XW0 + (size_t)N0*HID;
static const size_t O_XW   = O_H0  + (size_t)N0*HID;
static const size_t O_H1   = O_XW  + (size_t)KK1*HID;
static const size_t O_U1B  = O_H1  + (size_t)KK1*HID;
static const size_t O_H2   = O_U1B + (size_t)KK1*HID;
static const size_t O_XW3  = O_H2  + (size_t)KK2*HID;
static const size_t O_SC   = O_XW3 + (size_t)N0*4;
static const size_t O_VL1  = O_SC  + N0;
static const size_t O_VL2  = O_VL1 + 1536;
static const size_t FTOT   = O_VL2 + 768;

__device__ float g_f[FTOT];

// ---------------- bf16 scratch ----------------
static const size_t HB_A1  = 0;                                  // KP1*KP1
static const size_t HB_AR  = HB_A1 + (size_t)KP1*KP1;            // MP2*KP1
static const size_t HB_BC  = HB_AR + (size_t)MP2*KP1;            // KP1*MP2
static const size_t HB_XH  = HB_BC + (size_t)KP1*MP2;            // KP1*HID
static const size_t HB_XL  = HB_XH + (size_t)KP1*HID;            // KP1*HID
static const size_t HB_A2H = HB_XL + (size_t)KP1*HID;            // MP2*MP2
static const size_t HB_A2L = HB_A2H + (size_t)MP2*MP2;           // MP2*MP2
static const size_t HTOT   = HB_A2L + (size_t)MP2*MP2;

__device__ __nv_bfloat16 g_h[HTOT];

// ---------------- int scratch ----------------
static const size_t IO_CNTS = 0;                 // 3000
static const size_t IO_CNTD = 3000;              // 3000
static const size_t IO_COLS = 6000;              // 3000*64
static const size_t IO_COLD = IO_COLS + (size_t)N0*DMAX;
static const size_t IO_P1   = IO_COLD + (size_t)N0*DMAX;
static const size_t IO_P2   = IO_P1 + 1536;
static const size_t IO_INV1 = IO_P2 + 768;       // 3072
static const size_t IO_INV2 = IO_INV1 + 3072;    // 1536
static const size_t IO_RK1  = IO_INV2 + 1536;    // 3072
static const size_t IO_RK2  = IO_RK1 + 3072;     // 1536
static const size_t ITOT    = IO_RK2 + 1536;

__device__ int g_i[ITOT];

// ---------------- adjacency build ----------------
__global__ void k_build(const int* ei, int E, int* cnt_s, int* cnt_d,
                        int* col_s, int* col_d) {
    int e = blockIdx.x * blockDim.x + threadIdx.x;
    if (e < E) {
        int s = ei[e], t = ei[E + e];
        int p = atomicAdd(&cnt_s[s], 1);
        if (p < DMAX) col_s[s * DMAX + p] = t;
        int q = atomicAdd(&cnt_d[t], 1);
        if (q < DMAX) col_d[t * DMAX + q] = s;
    }
}

// ---------------- down0 GEMM ----------------
__global__ __launch_bounds__(256) void k_xw0(const float* __restrict__ x,
                                             const float* __restrict__ W0,
                                             float* __restrict__ XW0) {
    __shared__ float ws[INC * HID];
    __shared__ float xs[8][INC];
    int tid = threadIdx.x;
    int r0 = blockIdx.x * 8;
    #pragma unroll
    for (int l = 0; l < 16; l++) ws[tid + l * 256] = W0[tid + l * 256];
    if (tid < 8 * INC) xs[tid >> 5][tid & 31] = x[(size_t)r0 * INC + tid];
    __syncthreads();
    int c = tid & 127, g = tid >> 7;
    float acc[4] = {};
    #pragma unroll
    for (int k = 0; k < INC; k++) {
        float wv = ws[k * HID + c];
        #pragma unroll
        for (int j = 0; j < 4; j++)
            acc[j] += xs[g + j * 2][k] * wv;
    }
    #pragma unroll
    for (int j = 0; j < 4; j++)
        XW0[(size_t)(r0 + g + j * 2) * HID + c] = acc[j];
}

// ---------------- fp32 SGEMM 128x128 (gate/scatter XW) ----------------
template<int AM>
__global__ __launch_bounds__(256) void k_gemm128(
    const float* __restrict__ A, int lda,
    const float* __restrict__ B, int ldb,
    float* __restrict__ C, int ldc,
    int M, int N, int K, int Kc,
    const int* __restrict__ aperm, const float* __restrict__ avals,
    const float* __restrict__ adelta, const int* __restrict__ ainv)
{
    __shared__ float As[16][132];
    __shared__ float Bs[16][128];
    int bm = blockIdx.y * 128, bn = blockIdx.x * 128;
    int kstart = blockIdx.z * Kc;
    int kend = min(K, kstart + Kc);
    if (gridDim.z > 1) C += (size_t)blockIdx.z * M * ldc;
    int tid = threadIdx.x, tx = tid & 15, ty = tid >> 4;
    float acc[8][8] = {};
    for (int k0 = kstart; k0 < kend; k0 += 16) {
        #pragma unroll
        for (int l = 0; l < 2; l++) {
            int idx = tid + l * 256;
            int m = idx >> 2, k4 = idx & 3;
            int gm = bm + m, gk = k0 + k4 * 4;
            float4 v = make_float4(0.f, 0.f, 0.f, 0.f);
            if (gm < M) {
                const float* src;
                float scale = 1.0f;
                if (AM == 1) { scale = avals[gm]; src = A + (size_t)aperm[gm] * lda; }
                else          src = A + (size_t)gm * lda;
                v = *(const float4*)(src + gk);
                if (AM == 1) { v.x *= scale; v.y *= scale; v.z *= scale; v.w *= scale; }
                if (AM == 3) {
                    int r = ainv[gm];
                    if (r >= 0) {
                        float4 d4 = *(const float4*)(adelta + (size_t)r * lda + gk);
                        v.x += d4.x; v.y += d4.y; v.z += d4.z; v.w += d4.w;
                    }
                }
            }
            As[k4*4+0][m] = v.x; As[k4*4+1][m] = v.y;
            As[k4*4+2][m] = v.z; As[k4*4+3][m] = v.w;
        }
        #pragma unroll
        for (int l = 0; l < 2; l++) {
            int idx = tid + l * 256;
            int kk = idx >> 5, n4 = idx & 31;
            int gk = k0 + kk, gn = bn + n4 * 4;
            float4 v = make_float4(0.f, 0.f, 0.f, 0.f);
            if (gk < kend && gn < N)
                v = *(const float4*)(B + (size_t)gk * ldb + gn);
            *(float4*)&Bs[kk][n4*4] = v;
        }
        __syncthreads();
        #pragma unroll
        for (int kk = 0; kk < 16; kk++) {
            float a[8], b[8];
            *(float4*)&a[0] = *(const float4*)&As[kk][ty*8];
            *(float4*)&a[4] = *(const float4*)&As[kk][ty*8+4];
            *(float4*)&b[0] = *(const float4*)&Bs[kk][tx*8];
            *(float4*)&b[4] = *(const float4*)&Bs[kk][tx*8+4];
            #pragma unroll
            for (int r = 0; r < 8; r++)
                #pragma unroll
                for (int c = 0; c < 8; c++)
                    acc[r][c] += a[r] * b[c];
        }
        __syncthreads();
    }
    #pragma unroll
    for (int r = 0; r < 8; r++) {
        int gm = bm + ty*8 + r;
        if (gm >= M) continue;
        #pragma unroll
        for (int c = 0; c < 8; c++) {
            int gn = bn + tx*8 + c;
            if (gn < N) C[(size_t)gm * ldc + gn] = acc[r][c];
        }
    }
}

// ---------------- bf16 WMMA GEMM ----------------
template<int SPLIT>
__global__ __launch_bounds__(256) void k_wgemm(
    const __nv_bfloat16* __restrict__ A, int lda,
    const __nv_bfloat16* __restrict__ Bh, const __nv_bfloat16* __restrict__ Bl, int ldb,
    float* __restrict__ C, int ldc, int Kc, size_t zstride)
{
    __shared__ __nv_bfloat16 As[128][48];
    __shared__ __nv_bfloat16 Bsh[32][136];
    __shared__ __nv_bfloat16 Bsl[SPLIT ? 32 : 1][SPLIT ? 136 : 8];
    int bm = blockIdx.y * 128, bn = blockIdx.x * 128;
    int k0beg = blockIdx.z * Kc;
    C += (size_t)blockIdx.z * zstride;
    int tid = threadIdx.x;
    int wid = tid >> 5;
    int wm = wid >> 2, wn = wid & 3;

    wmma::fragment<wmma::accumulator,16,16,16,float> cf[4][2];
    #pragma unroll
    for (int i = 0; i < 4; i++)
        #pragma unroll
        for (int j = 0; j < 2; j++)
            wmma::fill_fragment(cf[i][j], 0.0f);

    for (int k0 = k0beg; k0 < k0beg + Kc; k0 += 32) {
        #pragma unroll
        for (int l = 0; l < 2; l++) {
            int idx = tid + l * 256;
            int m = idx >> 2, q = idx & 3;
            *(uint4*)&As[m][q*8] = *(const uint4*)(A + (size_t)(bm + m)*lda + k0 + q*8);
        }
        #pragma unroll
        for (int l = 0; l < 2; l++) {
            int idx = tid + l * 256;
            int kk = idx >> 4, q = idx & 15;
            *(uint4*)&Bsh[kk][q*8] = *(const uint4*)(Bh + (size_t)(k0 + kk)*ldb + bn + q*8);
        }
        if (SPLIT) {
            #pragma unroll
            for (int l = 0; l < 2; l++) {
                int idx = tid + l * 256;
                int kk = idx >> 4, q = idx & 15;
                *(uint4*)&Bsl[kk][q*8] = *(const uint4*)(Bl + (size_t)(k0 + kk)*ldb + bn + q*8);
            }
        }
        __syncthreads();
        #pragma unroll
        for (int ks = 0; ks < 2; ks++) {
            wmma::fragment<wmma::matrix_a,16,16,16,__nv_bfloat16,wmma::row_major> af[4];
            #pragma unroll
            for (int i = 0; i < 4; i++)
                wmma::load_matrix_sync(af[i], &As[wm*64 + i*16][ks*16], 48);
            wmma::fragment<wmma::matrix_b,16,16,16,__nv_bfloat16,wmma::row_major> bf[2];
            #pragma unroll
            for (int j = 0; j < 2; j++)
                wmma::load_matrix_sync(bf[j], &Bsh[ks*16][wn*32 + j*16], 136);
            #pragma unroll
            for (int i = 0; i < 4; i++)
                #pragma unroll
                for (int j = 0; j < 2; j++)
                    wmma::mma_sync(cf[i][j], af[i], bf[j], cf[i][j]);
            if (SPLIT) {
                #pragma unroll
                for (int j = 0; j < 2; j++)
                    wmma::load_matrix_sync(bf[j], &Bsl[ks*16][wn*32 + j*16], 136);
                #pragma unroll
                for (int i = 0; i < 4; i++)
                    #pragma unroll
                    for (int j = 0; j < 2; j++)
                        wmma::mma_sync(cf[i][j], af[i], bf[j], cf[i][j]);
            }
        }
        __syncthreads();
    }
    #pragma unroll
    for (int i = 0; i < 4; i++)
        #pragma unroll
        for (int j = 0; j < 2; j++)
            wmma::store_matrix_sync(C + (size_t)(bm + wm*64 + i*16)*ldc + bn + wn*32 + j*16,
                                    cf[i][j], ldc, wmma::mem_row_major);
}

// (Ah+Al) @ (Bh+Bl) via 3 products — A2 aggregation
__global__ __launch_bounds__(256) void k_wgemm2(
    const __nv_bfloat16* __restrict__ Ah, const __nv_bfloat16* __restrict__ Al, int lda,
    const __nv_bfloat16* __restrict__ Bh, const __nv_bfloat16* __restrict__ Bl, int ldb,
    float* __restrict__ C, int ldc, int Kc, size_t zstride)
{
    __shared__ __nv_bfloat16 Ash[128][48];
    __shared__ __nv_bfloat16 Asl[128][48];
    __shared__ __nv_bfloat16 Bsh[32][136];
    __shared__ __nv_bfloat16 Bsl[32][136];
    int bm = blockIdx.y * 128, bn = blockIdx.x * 128;
    int k0beg = blockIdx.z * Kc;
    C += (size_t)blockIdx.z * zstride;
    int tid = threadIdx.x;
    int wid = tid >> 5;
    int wm = wid >> 2, wn = wid & 3;

    wmma::fragment<wmma::accumulator,16,16,16,float> cf[4][2];
    #pragma unroll
    for (int i = 0; i < 4; i++)
        #pragma unroll
        for (int j = 0; j < 2; j++)
            wmma::fill_fragment(cf[i][j], 0.0f);

    for (int k0 = k0beg; k0 < k0beg + Kc; k0 += 32) {
        #pragma unroll
        for (int l = 0; l < 2; l++) {
            int idx = tid + l * 256;
            int m = idx >> 2, q = idx & 3;
            *(uint4*)&Ash[m][q*8] = *(const uint4*)(Ah + (size_t)(bm + m)*lda + k0 + q*8);
            *(uint4*)&Asl[m][q*8] = *(const uint4*)(Al + (size_t)(bm + m)*lda + k0 + q*8);
        }
        #pragma unroll
        for (int l = 0; l < 2; l++) {
            int idx = tid + l * 256;
            int kk = idx >> 4, q = idx & 15;
            *(uint4*)&Bsh[kk][q*8] = *(const uint4*)(Bh + (size_t)(k0 + kk)*ldb + bn + q*8);
            *(uint4*)&Bsl[kk][q*8] = *(const uint4*)(Bl + (size_t)(k0 + kk)*ldb + bn + q*8);
        }
        __syncthreads();
        #pragma unroll
        for (int ks = 0; ks < 2; ks++) {
            wmma::fragment<wmma::matrix_a,16,16,16,__nv_bfloat16,wmma::row_major> afh[4], afl[4];
            #pragma unroll
            for (int i = 0; i < 4; i++) {
                wmma::load_matrix_sync(afh[i], &Ash[wm*64 + i*16][ks*16], 48);
                wmma::load_matrix_sync(afl[i], &Asl[wm*64 + i*16][ks*16], 48);
            }
            wmma::fragment<wmma::matrix_b,16,16,16,__nv_bfloat16,wmma::row_major> bfh[2], bfl[2];
            #pragma unroll
            for (int j = 0; j < 2; j++) {
                wmma::load_matrix_sync(bfh[j], &Bsh[ks*16][wn*32 + j*16], 136);
                wmma::load_matrix_sync(bfl[j], &Bsl[ks*16][wn*32 + j*16], 136);
            }
            #pragma unroll
            for (int i = 0; i < 4; i++)
                #pragma unroll
                for (int j = 0; j < 2; j++) {
                    wmma::mma_sync(cf[i][j], afh[i], bfh[j], cf[i][j]);
                    wmma::mma_sync(cf[i][j], afh[i], bfl[j], cf[i][j]);
                    wmma::mma_sync(cf[i][j], afl[i], bfh[j], cf[i][j]);
                }
        }
        __syncthreads();
    }
    #pragma unroll
    for (int i = 0; i < 4; i++)
        #pragma unroll
        for (int j = 0; j < 2; j++)
            wmma::store_matrix_sync(C + (size_t)(bm + wm*64 + i*16)*ldc + bn + wn*32 + j*16,
                                    cf[i][j], ldc, wmma::mem_row_major);
}

// ---------------- bf16 conversions ----------------
__global__ void k_conv_A1(const float* __restrict__ A1, __nv_bfloat16* __restrict__ dst,
                          float* __restrict__ rs1) {
    __shared__ float sh[256];
    int r = blockIdx.x;
    float rsum = 0.0f;
    for (int c = threadIdx.x; c < KP1; c += 256) {
        float v = (r < KK1 && c < KK1) ? A1[(size_t)r*KK1 + c] : 0.0f;
        rsum += v;
        dst[(size_t)r*KP1 + c] = __float2bfloat16(v);
    }
    sh[threadIdx.x] = rsum;
    __syncthreads();
    for (int st = 128; st > 0; st >>= 1) {
        if (threadIdx.x < st) sh[threadIdx.x] += sh[threadIdx.x + st];
        __syncthreads();
    }
    if (threadIdx.x == 0 && r < KK1) rs1[r] = sh[0];
}

__global__ void k_conv_arbc(const float* __restrict__ A1, const int* __restrict__ perm,
                            __nv_bfloat16* __restrict__ Ar, __nv_bfloat16* __restrict__ Bc) {
    int b = blockIdx.x;
    if (b < MP2) {
        int r = b;
        int pr = (r < KK2) ? perm[r] : -1;
        for (int c = threadIdx.x; c < KP1; c += 256) {
            float v = 0.0f;
            if (pr >= 0 && c < KK1) v = A1[(size_t)pr*KK1 + c] + (c == pr ? 1.0f : 0.0f);
            Ar[(size_t)r*KP1 + c] = __float2bfloat16(v);
        }
    } else {
        int k = b - MP2;
        for (int col = threadIdx.x; col < MP2; col += 256) {
            float v = 0.0f;
            if (k < KK1 && col < KK2) {
                int pb = perm[col];
                v = A1[(size_t)k*KK1 + pb] + (k == pb ? 1.0f : 0.0f);
            }
            Bc[(size_t)k*MP2 + col] = __float2bfloat16(v);
        }
    }
}

// sum S split-K partials -> XW fp32; if HILO also dis-scaled hi/lo bf16
template<int HILO, int S>
__global__ void k_xw_finish(const float* __restrict__ part, size_t zstride, int n,
                            const float* __restrict__ rs, float* __restrict__ XW,
                            __nv_bfloat16* __restrict__ hi, __nv_bfloat16* __restrict__ lo) {
    int r = blockIdx.x;
    int c = threadIdx.x;
    size_t base = (size_t)r * HID + c;
    if (r < n) {
        float a = part[base];
        #pragma unroll
        for (int zz = 1; zz < S; zz++) a += part[base + zz*zstride];
        XW[base] = a;
        if (HILO) {
            float d = rsqrtf(rs[r] + 2.0f);
            float v = a * d;
            __nv_bfloat16 h = __float2bfloat16(v);
            hi[base] = h;
            lo[base] = __float2bfloat16(v - __bfloat162float(h));
        }
    } else if (HILO) {
        hi[base] = __float2bfloat16(0.0f);
        lo[base] = __float2bfloat16(0.0f);
    }
}

// ---------------- sparse GCN on A0, fused pool1 score (+rank zero) ----------------
__global__ void k_gcn0(const float* __restrict__ XW, const float* __restrict__ b,
                       const int* __restrict__ cnt, const int* __restrict__ col_d,
                       float* __restrict__ out,
                       const float* __restrict__ p, float* __restrict__ score,
                       int* __restrict__ inv, int* __restrict__ rank) {
    __shared__ int   snb[DMAX];
    __shared__ float sds[DMAX];
    __shared__ float sh[128];
    __shared__ float sp[128];
    int i = blockIdx.x, c = threadIdx.x;
    int deg = cnt[i];
    int nl = min(deg, DMAX);
    float di = rsqrtf((float)deg + 2.0f);
    if (c < nl) {
        int s = col_d[i * DMAX + c];
        snb[c] = s;
        sds[c] = rsqrtf((float)cnt[s] + 2.0f);
    }
    __syncthreads();
    float acc = 2.0f * di * XW[(size_t)i*HID + c];
    for (int t = 0; t < nl; t++)
        acc += sds[t] * XW[(size_t)snb[t]*HID + c];
    float val = tanhf(di * acc + b[c]);
    out[(size_t)i*HID + c] = val;
    float pc = p[c];
    sh[c] = val * pc;
    sp[c] = pc * pc;
    __syncthreads();
    for (int st = 64; st > 0; st >>= 1) {
        if (c < st) { sh[c] += sh[c+st]; sp[c] += sp[c+st]; }
        __syncthreads();
    }
    if (c == 0) { score[i] = tanhf(sh[0] * rsqrtf(sp[0])); inv[i] = -1; rank[i] = 0; }
}

// ---------------- 2D-parallel top-K rank counting ----------------
// grid (CDIV(n,256), CDIV(n,256)); block (bx,by) ranks i-chunk bx against j-chunk by.
__global__ void k_topk_rank(const float* __restrict__ s, int n, int* __restrict__ rank) {
    __shared__ float sh[256];
    int i = blockIdx.x * 256 + threadIdx.x;
    int j0 = blockIdx.y * 256;
    int j = j0 + threadIdx.x;
    sh[threadIdx.x] = (j < n) ? s[j] : -1e30f;
    __syncthreads();
    float si = (i < n) ? s[i] : -1e30f;
    int r = 0;
    const float4* sh4 = (const float4*)sh;
    #pragma unroll 4
    for (int t = 0; t < 64; t++) {
        float4 v = sh4[t];
        int jj = j0 + 4*t;
        r += (v.x > si) || (v.x == si && jj   < i);
        r += (v.y > si) || (v.y == si && jj+1 < i);
        r += (v.z > si) || (v.z == si && jj+2 < i);
        r += (v.w > si) || (v.w == si && jj+3 < i);
    }
    if (i < n && r) atomicAdd(&rank[i], r);
}

__global__ void k_topk_sel(const float* __restrict__ s, const int* __restrict__ rank,
                           int n, int K, int* __restrict__ perm, float* __restrict__ vals,
                           int* __restrict__ inv) {
    int i = blockIdx.x * blockDim.x + threadIdx.x;
    if (i < n) {
        int r = rank[i];
        if (r < K) { perm[r] = i; vals[r] = s[i]; inv[i] = r; }
    }
}

// ---------------- augment(A0) -> A1 submatrix ----------------
__global__ void k_aug(const int* __restrict__ cnt_s, const int* __restrict__ col_s,
                      const int* __restrict__ cnt_d, const int* __restrict__ col_d,
                      const int* __restrict__ inv, float* __restrict__ A1) {
    __shared__ int oi[DMAX], oinv[DMAX], ji[DMAX], jinv[DMAX];
    int k = blockIdx.x;
    int tid = threadIdx.x;
    int ns = min(cnt_s[k], DMAX);
    int nd = min(cnt_d[k], DMAX);
    if (tid < ns) {
        int i = col_s[k * DMAX + tid];
        oi[tid] = i; oinv[tid] = inv[i];
    }
    if (tid >= 64 && tid - 64 < nd) {
        int j = col_d[k * DMAX + (tid - 64)];
        ji[tid - 64] = j; jinv[tid - 64] = inv[j];
    }
    __syncthreads();
    int invk = inv[k];
    int tot = ns * nd;
    for (int t = tid; t < tot; t += 128) {
        int ii = t / nd, jj = t - ii * nd;
        int i = oi[ii], j = ji[jj];
        int r = oinv[ii], c = jinv[jj];
        if (i != k && j != k && i != j && r >= 0 && c >= 0)
            atomicAdd(&A1[(size_t)r*KK1 + c], 1.0f);
    }
    if (invk >= 0) {
        for (int e = tid; e < ns; e += 128) {
            int i = oi[e], r = oinv[e];
            if (i != k && r >= 0)
                atomicAdd(&A1[(size_t)r*KK1 + invk], 2.0f);
        }
    }
}

// sum 4 partials of A2 product, zero diag, rowsum -> rs2, hi/lo bf16
__global__ void k_a2_finish(const float* __restrict__ part,
                            __nv_bfloat16* __restrict__ A2h, __nv_bfloat16* __restrict__ A2l,
                            float* __restrict__ rs2) {
    __shared__ float sh[256];
    int i = blockIdx.x;
    float rsum = 0.0f;
    for (int j = threadIdx.x; j < MP2; j += 256) {
        float s = 0.0f;
        if (i < KK2 && j < KK2) {
            #pragma unroll
            for (int zz = 0; zz < 4; zz++)
                s += part[((size_t)zz*MP2 + i)*MP2 + j];
            if (j == i) s = 0.0f;
        }
        rsum += s;
        __nv_bfloat16 h = __float2bfloat16(s);
        A2h[(size_t)i*MP2 + j] = h;
        A2l[(size_t)i*MP2 + j] = __float2bfloat16(s - __bfloat162float(h));
    }
    sh[threadIdx.x] = rsum;
    __syncthreads();
    for (int st = 128; st > 0; st >>= 1) {
        if (threadIdx.x < st) sh[threadIdx.x] += sh[threadIdx.x + st];
        __syncthreads();
    }
    if (threadIdx.x == 0 && i < KK2) rs2[i] = sh[0];
}

// row-per-block epilogue + optional fused score (+rank zero)
template<int SCORE>
__global__ void k_agg_epi(const float* __restrict__ part, int S, size_t zstride,
                          const float* __restrict__ XW, const float* __restrict__ bias,
                          const float* __restrict__ rs, float* __restrict__ out,
                          const float* __restrict__ p, float* __restrict__ score,
                          int* __restrict__ inv, int* __restrict__ rank) {
    __shared__ float sh[128];
    __shared__ float sp[128];
    int i = blockIdx.x, c = threadIdx.x;
    size_t base = (size_t)i * HID + c;
    float a = part[base];
    #pragma unroll 4
    for (int zz = 1; zz < S; zz++) a += part[base + zz*zstride];
    float d = rsqrtf(rs[i] + 2.0f);
    float val = tanhf(d * a + 2.0f * d * d * XW[base] + bias[c]);
    out[base] = val;
    if (SCORE) {
        float pc = p[c];
        sh[c] = val * pc;
        sp[c] = pc * pc;
        __syncthreads();
        for (int st = 64; st > 0; st >>= 1) {
            if (c < st) { sh[c] += sh[c+st]; sp[c] += sp[c+st]; }
            __syncthreads();
        }
        if (c == 0) { score[i] = tanhf(sh[0] * rsqrtf(sp[0])); inv[i] = -1; rank[i] = 0; }
    }
}

// XW3 = (h0 + scatter(u1b, inv1)) @ Wu1  (N=3), warp per row
__global__ void k_xw3(const float* __restrict__ h0, const float* __restrict__ u1b,
                      const int* __restrict__ inv1, const float* __restrict__ W,
                      float* __restrict__ XW3) {
    int w = (blockIdx.x * blockDim.x + threadIdx.x) >> 5;
    int lane = threadIdx.x & 31;
    if (w >= N0) return;
    int r = inv1[w];
    float a0 = 0.f, a1 = 0.f, a2 = 0.f;
    #pragma unroll
    for (int q = 0; q < 4; q++) {
        int k = lane + q * 32;
        float v = h0[(size_t)w*HID + k];
        if (r >= 0) v += u1b[(size_t)r*HID + k];
        a0 += v * W[k*3+0];
        a1 += v * W[k*3+1];
        a2 += v * W[k*3+2];
    }
    #pragma unroll
    for (int off = 16; off > 0; off >>= 1) {
        a0 += __shfl_down_sync(0xffffffffu, a0, off);
        a1 += __shfl_down_sync(0xffffffffu, a1, off);
        a2 += __shfl_down_sync(0xffffffffu, a2, off);
    }
    if (lane == 0) { XW3[w*3+0] = a0; XW3[w*3+1] = a1; XW3[w*3+2] = a2; }
}

// final sparse GCN (OUTC=3) + noise
__global__ void k_gcn_final(const float* __restrict__ XW3, const float* __restrict__ b,
                            const int* __restrict__ cnt, const int* __restrict__ col_d,
                            const float* __restrict__ z, float* __restrict__ out) {
    int i = blockIdx.x * blockDim.x + threadIdx.x;
    if (i >= N0) return;
    int deg = cnt[i];
    int nl = min(deg, DMAX);
    float di = rsqrtf((float)deg + 2.0f);
    float a0 = 2.0f * di * XW3[i*3+0];
    float a1 = 2.0f * di * XW3[i*3+1];
    float a2 = 2.0f * di * XW3[i*3+2];
    for (int e = 0; e < nl; e++) {
        int s = col_d[i * DMAX + e];
        float ds = rsqrtf((float)cnt[s] + 2.0f);
        a0 += ds * XW3[s*3+0];
        a1 += ds * XW3[s*3+1];
        a2 += ds * XW3[s*3+2];
    }
    out[i*3+0] = di*a0 + b[0] + 0.1f*z[i*3+0];
    out[i*3+1] = di*a1 + b[1] + 0.1f*z[i*3+1];
    out[i*3+2] = di*a2 + b[2] + 0.1f*z[i*3+2];
}

// ---------------- launch ----------------
extern "C" void kernel_launch(void* const* d_in, const int* in_sizes, int n_in,
                              void* d_out, int out_size) {
    const float* x   = (const float*)d_in[0];
    const float* z   = (const float*)d_in[1];
    const float* W0  = (const float*)d_in[2];
    const float* b0  = (const float*)d_in[3];
    const float* W1  = (const float*)d_in[4];
    const float* b1  = (const float*)d_in[5];
    const float* W2  = (const float*)d_in[6];
    const float* b2  = (const float*)d_in[7];
    const float* p1  = (const float*)d_in[8];
    const float* p2  = (const float*)d_in[9];
    const float* Wu0 = (const float*)d_in[10];
    const float* bu0 = (const float*)d_in[11];
    const float* Wu1 = (const float*)d_in[12];
    const float* bu1 = (const float*)d_in[13];
    const int*   ei  = (const int*)d_in[14];
    int E = in_sizes[14] / 2;
    if (E > EMAX) E = EMAX;

    float* F; cudaGetSymbolAddress((void**)&F, g_f);
    int*   I; cudaGetSymbolAddress((void**)&I, g_i);
    __nv_bfloat16* H; cudaGetSymbolAddress((void**)&H, g_h);
    float* out = (float*)d_out;

    float *A1 = F+O_A1, *rs1 = F+O_RS1, *rs2 = F+O_RS2, *part = F+O_PART;
    float *XW0 = F+O_XW0, *h0 = F+O_H0, *XW = F+O_XW;
    float *h1 = F+O_H1, *u1b = F+O_U1B, *h2 = F+O_H2, *XW3 = F+O_XW3;
    float *score = F+O_SC, *vals1 = F+O_VL1, *vals2 = F+O_VL2;
    __nv_bfloat16 *A1bf = H+HB_A1, *Ar = H+HB_AR, *Bc = H+HB_BC;
    __nv_bfloat16 *XWh = H+HB_XH, *XWl = H+HB_XL;
    __nv_bfloat16 *A2h = H+HB_A2H, *A2l = H+HB_A2L;
    int *perm1 = I+IO_P1, *perm2 = I+IO_P2, *inv1 = I+IO_INV1, *inv2 = I+IO_INV2;
    int *rank1 = I+IO_RK1, *rank2 = I+IO_RK2;

    cudaMemsetAsync(A1, 0, ((size_t)KK1*KK1 + KK1 + 768)*sizeof(float));
    cudaMemsetAsync(I, 0, 6000*sizeof(int));
    cudaMemsetAsync(d_out, 0, (size_t)out_size*sizeof(float));

    // adjacency
    k_build<<<CDIV(E,256),256>>>(ei, E, I+IO_CNTS, I+IO_CNTD, I+IO_COLS, I+IO_COLD);

    // down0 (+ fused pool1 score + rank zero)
    k_xw0<<<N0/8,256>>>(x, W0, XW0);
    k_gcn0<<<N0,128>>>(XW0, b0, I+IO_CNTD, I+IO_COLD, h0, p1, score, inv1, rank1);
    k_topk_rank<<<dim3(CDIV(N0,256), CDIV(N0,256)),256>>>(score, N0, rank1);
    k_topk_sel<<<CDIV(N0,256),256>>>(score, rank1, N0, KK1, perm1, vals1, inv1);

    // augment(A0) -> A1 ; bf16 copy + rowsum
    k_aug<<<N0,128>>>(I+IO_CNTS, I+IO_COLS, I+IO_CNTD, I+IO_COLD, inv1, A1);
    k_conv_A1<<<KP1,256>>>(A1, A1bf, rs1);

    // down1: XW = gate(h0)@W1 (z=8) ; finish(+hilo) ; bf16 agg ; epi(+pool2 score)
    k_gemm128<1><<<dim3(1, CDIV(KK1,128), 8),256>>>(h0, HID, W1, HID, part, HID,
        KK1, HID, HID, 16, perm1, vals1, 0, 0);
    k_xw_finish<1,8><<<KP1,128>>>(part, (size_t)KK1*HID, KK1, rs1, XW, XWh, XWl);
    k_wgemm<1><<<dim3(1, 12, 12),256>>>(A1bf, KP1, XWh, XWl, HID, part, HID, 128, (size_t)KP1*HID);
    k_agg_epi<1><<<KK1,128>>>(part, 12, (size_t)KP1*HID, XW, b1, rs1, h1, p2, score, inv2, rank2);
    k_topk_rank<<<dim3(CDIV(KK1,256), CDIV(KK1,256)),256>>>(score, KK1, rank2);
    k_topk_sel<<<CDIV(KK1,256),256>>>(score, rank2, KK1, KK2, perm2, vals2, inv2);

    // A2 = (A1+I)[perm2,:] @ (A1+I)[:,perm2] (exact bf16) -> hi/lo + rowsum
    k_conv_arbc<<<MP2+KP1,256>>>(A1, perm2, Ar, Bc);
    k_wgemm<0><<<dim3(6, 6, 4),256>>>(Ar, KP1, Bc, Bc, MP2, part, MP2, 384, (size_t)MP2*MP2);
    k_a2_finish<<<MP2,256>>>(part, A2h, A2l, rs2);

    // down2
    k_gemm128<1><<<dim3(1, CDIV(KK2,128), 8),256>>>(h1, HID, W2, HID, part, HID,
        KK2, HID, HID, 16, perm2, vals2, 0, 0);
    k_xw_finish<1,8><<<MP2,128>>>(part, (size_t)KK2*HID, KK2, rs2, XW, XWh, XWl);
    k_wgemm2<<<dim3(1, 6, 8),256>>>(A2h, A2l, MP2, XWh, XWl, HID, part, HID, 96, (size_t)MP2*HID);
    k_agg_epi<0><<<KK2,128>>>(part, 8, (size_t)MP2*HID, XW, b2, rs2, h2, 0, 0, 0, 0);

    // up0
    k_gemm128<3><<<dim3(1, CDIV(KK1,128), 8),256>>>(h1, HID, Wu0, HID, part, HID,
        KK1, HID, HID, 16, 0, 0, h2, inv2);
    k_xw_finish<1,8><<<KP1,128>>>(part, (size_t)KK1*HID, KK1, rs1, XW, XWh, XWl);
    k_wgemm<1><<<dim3(1, 12, 12),256>>>(A1bf, KP1, XWh, XWl, HID, part, HID, 128, (size_t)KP1*HID);
    k_agg_epi<0><<<KK1,128>>>(part, 12, (size_t)KP1*HID, XW, bu0, rs1, u1b, 0, 0, 0, 0);

    // up1
    k_xw3<<<CDIV(N0*32,256),256>>>(h0, u1b, inv1, Wu1, XW3);
    k_gcn_final<<<CDIV(N0,128),128>>>(XW3, bu1, I+IO_CNTD, I+IO_COLD, z, out);
}